// round 1
// baseline (speedup 1.0000x reference)
#include <cuda_runtime.h>

#define B_DIM  2
#define N_SEQ  1024
#define DIMX   1024
#define HEADS  16
#define DH     64
#define INNER  1024
#define MAXPOS 512

// Scratch (allocation-free: __device__ globals)
__device__ float g_q[(size_t)B_DIM*HEADS*N_SEQ*DH];   // [b][h][i][d]
__device__ float g_k[(size_t)B_DIM*HEADS*N_SEQ*DH];
__device__ float g_v[(size_t)B_DIM*HEADS*N_SEQ*DH];
__device__ float g_o[(size_t)B_DIM*N_SEQ*INNER];      // [b][i][h*64+d]

// ---------------------------------------------------------------------------
// Tiled fp32 GEMM: C = A[M,K] @ B[K,N], BM=BN=128, BK=8, 256 threads, 8x8 frag
// mode 0: scatter into g_q (head-major)
// mode 1: scatter into g_k / g_v (Wkv split)
// mode 2: plain row-major + bias into outp (A==nullptr means A = g_o)
// ---------------------------------------------------------------------------
__global__ __launch_bounds__(256) void sgemm_kernel(
    const float* __restrict__ A, const float* __restrict__ Bw,
    int K, int N, int mode, const float* __restrict__ bias,
    float* __restrict__ outp)
{
    __shared__ float As[8][128];
    __shared__ float Bs[8][128];

    const float* Ap = A ? A : g_o;

    const int tid = threadIdx.x;
    const int tx = tid & 15, ty = tid >> 4;
    const int m0 = blockIdx.y * 128, n0 = blockIdx.x * 128;

    float acc[8][8];
#pragma unroll
    for (int i = 0; i < 8; i++)
#pragma unroll
        for (int j = 0; j < 8; j++) acc[i][j] = 0.f;

    const int am = tid >> 1, ak = (tid & 1) * 4;     // A loader: 4 floats/thread
    const int bk = tid >> 5, bn = (tid & 31) * 4;    // B loader: 4 floats/thread

    for (int k0 = 0; k0 < K; k0 += 8) {
        float4 av = *(const float4*)(Ap + (size_t)(m0 + am) * K + k0 + ak);
        As[ak + 0][am] = av.x; As[ak + 1][am] = av.y;
        As[ak + 2][am] = av.z; As[ak + 3][am] = av.w;
        float4 bv = *(const float4*)(Bw + (size_t)(k0 + bk) * N + n0 + bn);
        *(float4*)&Bs[bk][bn] = bv;
        __syncthreads();

#pragma unroll
        for (int kk = 0; kk < 8; kk++) {
            float a[8], b[8];
            float4 t;
            t = *(float4*)&As[kk][ty * 4];      a[0]=t.x; a[1]=t.y; a[2]=t.z; a[3]=t.w;
            t = *(float4*)&As[kk][ty * 4 + 64]; a[4]=t.x; a[5]=t.y; a[6]=t.z; a[7]=t.w;
            t = *(float4*)&Bs[kk][tx * 4];      b[0]=t.x; b[1]=t.y; b[2]=t.z; b[3]=t.w;
            t = *(float4*)&Bs[kk][tx * 4 + 64]; b[4]=t.x; b[5]=t.y; b[6]=t.z; b[7]=t.w;
#pragma unroll
            for (int i = 0; i < 8; i++)
#pragma unroll
                for (int j = 0; j < 8; j++)
                    acc[i][j] = fmaf(a[i], b[j], acc[i][j]);
        }
        __syncthreads();
    }

#pragma unroll
    for (int i = 0; i < 8; i++) {
        int m = m0 + ty * 4 + (i < 4 ? i : 60 + i);
#pragma unroll
        for (int j = 0; j < 8; j++) {
            int c = n0 + tx * 4 + (j < 4 ? j : 60 + j);
            float v = acc[i][j];
            if (mode == 2) {
                outp[(size_t)m * 1024 + c] = v + bias[c];
            } else {
                int bb = m >> 10, ii = m & 1023;
                if (mode == 0) {
                    int h = c >> 6, d = c & 63;
                    g_q[(((size_t)bb * HEADS + h) * N_SEQ + ii) * DH + d] = v;
                } else {
                    if (c < INNER) {
                        int h = c >> 6, d = c & 63;
                        g_k[(((size_t)bb * HEADS + h) * N_SEQ + ii) * DH + d] = v;
                    } else {
                        int h = (c - INNER) >> 6, d = c & 63;
                        g_v[(((size_t)bb * HEADS + h) * N_SEQ + ii) * DH + d] = v;
                    }
                }
            }
        }
    }
}

// ---------------------------------------------------------------------------
// Fused flash attention with relative position bias.
// Grid: (16 row blocks, 16 heads, 2 batch). Block 256 thr = (tx 0..15, ty 0..15)
// Each thread owns a 4x4 (row x col) tile of the 64x64 score block, and a
// 4x4 (row x d) tile of the output.
// SMEM: q[64x64] | kT/p[64x68] | v[64x64] | rel[127x65]  ~= 83 KB
// ---------------------------------------------------------------------------
__global__ __launch_bounds__(256) void attn_kernel(const float* __restrict__ rel_emb)
{
    extern __shared__ float sm[];
    float* q_s   = sm;                        // 4096
    float* kp_s  = sm + 4096;                 // 64*68 = 4352 (K^T, then P)
    float* v_s   = sm + 4096 + 4352;          // 4096
    float* rel_s = sm + 4096 + 4352 + 4096;   // 127*65 = 8255

    const int tid = threadIdx.x;
    const int tx = tid & 15, ty = tid >> 4;
    const int i0 = blockIdx.x * 64;
    const int h  = blockIdx.y;
    const int b  = blockIdx.z;
    const size_t headbase = ((size_t)b * HEADS + h) * N_SEQ * DH;

    // load q tile (row-major [r][d])
    for (int idx = tid * 4; idx < 64 * 64; idx += 256 * 4)
        *(float4*)&q_s[idx] = *(const float4*)&g_q[headbase + (size_t)i0 * DH + idx];

    float m_i[4], l_i[4], o[4][4];
#pragma unroll
    for (int i = 0; i < 4; i++) {
        m_i[i] = -1e30f; l_i[i] = 0.f;
#pragma unroll
        for (int j = 0; j < 4; j++) o[i][j] = 0.f;
    }

    const float scale = 0.125f;  // 64^-0.5
    const int base2 = ty * 4 - tx * 4 + 63;   // rel row for ii-jj == 0

    for (int jt = 0; jt < 16; jt++) {
        const int j0 = jt * 64;
        __syncthreads();  // previous iter's P/V/rel reads complete

        // K^T tile: kp_s[d][j], stride 68
        for (int idx = tid; idx < 4096; idx += 256) {
            int j = idx >> 6, d = idx & 63;
            kp_s[d * 68 + j] = g_k[headbase + (size_t)(j0 + j) * DH + d];
        }
        // V tile row-major [j][d]
        for (int idx = tid * 4; idx < 4096; idx += 1024)
            *(float4*)&v_s[idx] = *(const float4*)&g_v[headbase + (size_t)j0 * DH + idx];
        // rel rows: dist = i-j for i in [i0,i0+63], j in [j0,j0+63] -> 127 rows
        for (int idx = tid; idx < 127 * 64; idx += 256) {
            int r = idx >> 6, col = idx & 63;
            int dist = i0 - j0 - 63 + r;
            dist = min(max(dist, -MAXPOS), MAXPOS) + MAXPOS;
            rel_s[r * 65 + col] = rel_emb[(size_t)dist * DH + col];
        }
        __syncthreads();

        // scores: s[i][j] = sum_d q[i][d] * (k[j][d] + rel[i-j][d])
        float acc[4][4];
#pragma unroll
        for (int i = 0; i < 4; i++)
#pragma unroll
            for (int j = 0; j < 4; j++) acc[i][j] = 0.f;

#pragma unroll 4
        for (int d = 0; d < 64; d++) {
            float4 k4 = *(float4*)&kp_s[d * 68 + tx * 4];
            float kb[4] = {k4.x, k4.y, k4.z, k4.w};
            float rl[7];
#pragma unroll
            for (int t = 0; t < 7; t++) rl[t] = rel_s[(base2 - 3 + t) * 65 + d];
#pragma unroll
            for (int i = 0; i < 4; i++) {
                float qv = q_s[(ty * 4 + i) * 64 + d];
#pragma unroll
                for (int j = 0; j < 4; j++)
                    acc[i][j] = fmaf(qv, kb[j] + rl[i - j + 3], acc[i][j]);
            }
        }

        // online softmax (16 lanes per row group, within half-warp)
        float p[4][4];
#pragma unroll
        for (int i = 0; i < 4; i++) {
            float rmax = -1e30f;
#pragma unroll
            for (int j = 0; j < 4; j++) {
                acc[i][j] *= scale;
                rmax = fmaxf(rmax, acc[i][j]);
            }
#pragma unroll
            for (int msk = 8; msk >= 1; msk >>= 1)
                rmax = fmaxf(rmax, __shfl_xor_sync(0xffffffffu, rmax, msk));
            float mnew = fmaxf(m_i[i], rmax);
            float alpha = __expf(m_i[i] - mnew);
            m_i[i] = mnew;
            float rsum = 0.f;
#pragma unroll
            for (int j = 0; j < 4; j++) {
                p[i][j] = __expf(acc[i][j] - mnew);
                rsum += p[i][j];
            }
#pragma unroll
            for (int msk = 8; msk >= 1; msk >>= 1)
                rsum += __shfl_xor_sync(0xffffffffu, rsum, msk);
            l_i[i] = l_i[i] * alpha + rsum;
#pragma unroll
            for (int j = 0; j < 4; j++) o[i][j] *= alpha;
        }

        __syncthreads();  // K^T reads done; safe to overwrite with P
#pragma unroll
        for (int i = 0; i < 4; i++)
#pragma unroll
            for (int j = 0; j < 4; j++)
                kp_s[(ty * 4 + i) * 68 + tx * 4 + j] = p[i][j];
        __syncthreads();  // P visible

        // O += P @ V
        for (int j = 0; j < 64; j++) {
            float4 v4 = *(float4*)&v_s[j * 64 + tx * 4];
            float vb[4] = {v4.x, v4.y, v4.z, v4.w};
#pragma unroll
            for (int i = 0; i < 4; i++) {
                float pv = kp_s[(ty * 4 + i) * 68 + j];
#pragma unroll
                for (int jj = 0; jj < 4; jj++)
                    o[i][jj] = fmaf(pv, vb[jj], o[i][jj]);
            }
        }
    }

    // epilogue: normalize and store to g_o[b][i][h*64+d]
#pragma unroll
    for (int i = 0; i < 4; i++) {
        float inv = 1.f / l_i[i];
        int row = i0 + ty * 4 + i;
        float4 ov;
        ov.x = o[i][0] * inv; ov.y = o[i][1] * inv;
        ov.z = o[i][2] * inv; ov.w = o[i][3] * inv;
        *(float4*)&g_o[((size_t)b * N_SEQ + row) * INNER + h * DH + tx * 4] = ov;
    }
}

// ---------------------------------------------------------------------------
extern "C" void kernel_launch(void* const* d_in, const int* in_sizes, int n_in,
                              void* d_out, int out_size)
{
    (void)in_sizes; (void)n_in; (void)out_size;
    const float* x   = (const float*)d_in[0];   // [2,1024,1024]
    const float* Wq  = (const float*)d_in[1];   // [1024,1024]
    const float* Wkv = (const float*)d_in[2];   // [1024,2048]
    const float* Wo  = (const float*)d_in[3];   // [1024,1024]
    const float* bo  = (const float*)d_in[4];   // [1024]
    const float* rel = (const float*)d_in[5];   // [1025,64]
    float* out = (float*)d_out;                 // [2,1024,1024]

    // q = x @ Wq  -> g_q (head-major)
    sgemm_kernel<<<dim3(INNER / 128, (B_DIM * N_SEQ) / 128), 256>>>(
        x, Wq, DIMX, INNER, 0, nullptr, nullptr);
    // kv = x @ Wkv -> g_k, g_v
    sgemm_kernel<<<dim3((2 * INNER) / 128, (B_DIM * N_SEQ) / 128), 256>>>(
        x, Wkv, DIMX, 2 * INNER, 1, nullptr, nullptr);

    // fused attention
    cudaFuncSetAttribute(attn_kernel, cudaFuncAttributeMaxDynamicSharedMemorySize, 83200);
    attn_kernel<<<dim3(16, HEADS, B_DIM), 256, 83196>>>(rel);

    // out = g_o @ Wo + bo
    sgemm_kernel<<<dim3(DIMX / 128, (B_DIM * N_SEQ) / 128), 256>>>(
        nullptr, Wo, INNER, DIMX, 2, bo, out);
}

// round 3
// speedup vs baseline: 1.4238x; 1.4238x over previous
#include <cuda_runtime.h>
#include <cuda_bf16.h>
#include <cstdint>

#define B_DIM  2
#define N_SEQ  1024
#define DIMX   1024
#define HEADS  16
#define DH     64
#define INNER  1024
#define MAXPOS 512

// ------------------------- device scratch (no allocs) -----------------------
__device__ __align__(16) float g_q[(size_t)B_DIM*HEADS*N_SEQ*DH];
__device__ __align__(16) float g_k[(size_t)B_DIM*HEADS*N_SEQ*DH];
__device__ __align__(16) float g_v[(size_t)B_DIM*HEADS*N_SEQ*DH];

__device__ __align__(16) __nv_bfloat16 g_xh[(size_t)B_DIM*N_SEQ*DIMX];
__device__ __align__(16) __nv_bfloat16 g_xl[(size_t)B_DIM*N_SEQ*DIMX];
__device__ __align__(16) __nv_bfloat16 g_wqh[(size_t)DIMX*INNER];
__device__ __align__(16) __nv_bfloat16 g_wql[(size_t)DIMX*INNER];
__device__ __align__(16) __nv_bfloat16 g_wkvh[(size_t)2*DIMX*INNER];
__device__ __align__(16) __nv_bfloat16 g_wkvl[(size_t)2*DIMX*INNER];
__device__ __align__(16) __nv_bfloat16 g_woh[(size_t)INNER*DIMX];
__device__ __align__(16) __nv_bfloat16 g_wol[(size_t)INNER*DIMX];
__device__ __align__(16) __nv_bfloat16 g_oh[(size_t)B_DIM*N_SEQ*INNER];
__device__ __align__(16) __nv_bfloat16 g_ol[(size_t)B_DIM*N_SEQ*INNER];

// ------------------------------- helpers ------------------------------------
__device__ __forceinline__ uint32_t smem_u32(const void* p) {
    uint32_t a;
    asm("{ .reg .u64 t; cvta.to.shared.u64 t, %1; cvt.u32.u64 %0, t; }"
        : "=r"(a) : "l"(p));
    return a;
}
__device__ __forceinline__ void cp16(uint32_t saddr, const void* gaddr) {
    asm volatile("cp.async.cg.shared.global [%0], [%1], 16;"
                 :: "r"(saddr), "l"(gaddr) : "memory");
}
__device__ __forceinline__ void ldm_x4(uint32_t a, uint32_t& r0, uint32_t& r1,
                                       uint32_t& r2, uint32_t& r3) {
    asm volatile("ldmatrix.sync.aligned.m8n8.x4.shared.b16 {%0,%1,%2,%3}, [%4];"
                 : "=r"(r0), "=r"(r1), "=r"(r2), "=r"(r3) : "r"(a));
}
__device__ __forceinline__ void mma16816(float* c, const uint32_t* a,
                                         uint32_t b0, uint32_t b1) {
    asm volatile(
        "mma.sync.aligned.m16n8k16.row.col.f32.bf16.bf16.f32 "
        "{%0,%1,%2,%3}, {%4,%5,%6,%7}, {%8,%9}, {%0,%1,%2,%3};"
        : "+f"(c[0]), "+f"(c[1]), "+f"(c[2]), "+f"(c[3])
        : "r"(a[0]), "r"(a[1]), "r"(a[2]), "r"(a[3]), "r"(b0), "r"(b1));
}

// ------------------------- conversion kernels -------------------------------
__global__ __launch_bounds__(256) void split_kernel(const float* __restrict__ in, int n4)
{
    int i = blockIdx.x * blockDim.x + threadIdx.x;
    if (i >= n4) return;
    float4 v = ((const float4*)in)[i];
    __nv_bfloat16 h0 = __float2bfloat16(v.x), h1 = __float2bfloat16(v.y);
    __nv_bfloat16 h2 = __float2bfloat16(v.z), h3 = __float2bfloat16(v.w);
    __nv_bfloat16 l0 = __float2bfloat16(v.x - __bfloat162float(h0));
    __nv_bfloat16 l1 = __float2bfloat16(v.y - __bfloat162float(h1));
    __nv_bfloat16 l2 = __float2bfloat16(v.z - __bfloat162float(h2));
    __nv_bfloat16 l3 = __float2bfloat16(v.w - __bfloat162float(h3));
    ((__nv_bfloat162*)g_xh)[2*i]   = {h0, h1};
    ((__nv_bfloat162*)g_xh)[2*i+1] = {h2, h3};
    ((__nv_bfloat162*)g_xl)[2*i]   = {l0, l1};
    ((__nv_bfloat162*)g_xl)[2*i+1] = {l2, l3};
}

// transpose + split: W[K][N] fp32 -> Wt_h/Wt_l [N][K] bf16
__global__ __launch_bounds__(256) void tsplit_kernel(const float* __restrict__ W,
                                                     int K, int N, int mode)
{
    __shared__ float t[32][33];
    __nv_bfloat16 *th, *tl;
    if (mode == 0)      { th = g_wqh;  tl = g_wql; }
    else if (mode == 1) { th = g_wkvh; tl = g_wkvl; }
    else                { th = g_woh;  tl = g_wol; }

    const int n0 = blockIdx.x * 32, k0 = blockIdx.y * 32;
    const int tx = threadIdx.x & 31, ty = threadIdx.x >> 5;
#pragma unroll
    for (int r = 0; r < 4; r++)
        t[ty + 8*r][tx] = W[(size_t)(k0 + ty + 8*r) * N + n0 + tx];
    __syncthreads();
#pragma unroll
    for (int r = 0; r < 4; r++) {
        float v = t[tx][ty + 8*r];
        __nv_bfloat16 h = __float2bfloat16(v);
        __nv_bfloat16 l = __float2bfloat16(v - __bfloat162float(h));
        size_t o = (size_t)(n0 + ty + 8*r) * K + k0 + tx;
        th[o] = h; tl[o] = l;
    }
}

// ------------------------- mma.sync bf16-split GEMM -------------------------
// C[M,N] = (Ah+Al)[M,K] @ (Bh+Bl)[N,K]^T, fp32 accum, 3 passes (hh, hl, lh).
// Tile 128x128, BK=32, 8 warps (2x4), warp tile 64x32, cp.async double buffer.
// mode 0 -> g_q scatter ; mode 1 -> g_k/g_v ; mode 2 -> outp + bias.
#define BK 32
#define RS 40                    // padded row stride in bf16 (80 bytes)
#define TILE_B (128 * RS * 2)    // 10240 bytes per operand tile
#define STAGE_B (4 * TILE_B)     // Ah, Al, Bh, Bl

__global__ __launch_bounds__(256, 1) void gemm_mma(int mode,
                                                   const float* __restrict__ bias,
                                                   float* __restrict__ outp)
{
    extern __shared__ __align__(128) char smem[];
    const uint32_t sb = smem_u32(smem);
    const int tid = threadIdx.x;
    const int wid = tid >> 5, lane = tid & 31;
    const int warp_m = wid & 1, warp_n = wid >> 1;
    const int m0 = blockIdx.y * 128, n0 = blockIdx.x * 128;

    const __nv_bfloat16 *Ah, *Al, *Bh, *Bl;
    if (mode == 0)      { Ah = g_xh; Al = g_xl; Bh = g_wqh;  Bl = g_wql;  }
    else if (mode == 1) { Ah = g_xh; Al = g_xl; Bh = g_wkvh; Bl = g_wkvl; }
    else                { Ah = g_oh; Al = g_ol; Bh = g_woh;  Bl = g_wol;  }

    float acc[4][4][4];
#pragma unroll
    for (int i = 0; i < 4; i++)
#pragma unroll
        for (int j = 0; j < 4; j++)
#pragma unroll
            for (int t = 0; t < 4; t++) acc[i][j][t] = 0.f;

    // loader geometry: 2048 16B-chunks per stage, 8 per thread
    // id = tid + i*256 ; tile = id>>9 (Ah,Al,Bh,Bl) ; rem = id&511
    // row = rem>>2 ; cc = rem&3  (cc*8 bf16 within BK=32)
    const int nkt = DIMX / BK;

    auto issue_stage = [&](int kt) {
        const int k0 = kt * BK;
        const uint32_t st = sb + (kt & 1) * STAGE_B;
#pragma unroll
        for (int i = 0; i < 8; i++) {
            int id = tid + i * 256;
            int tile = id >> 9, rem = id & 511;
            int r = rem >> 2, cc = rem & 3;
            uint32_t sa = st + tile * TILE_B + r * (RS * 2) + cc * 16;
            const __nv_bfloat16* src;
            size_t goff;
            if (tile == 0)      { src = Ah; goff = (size_t)(m0 + r) * DIMX; }
            else if (tile == 1) { src = Al; goff = (size_t)(m0 + r) * DIMX; }
            else if (tile == 2) { src = Bh; goff = (size_t)(n0 + r) * DIMX; }
            else                { src = Bl; goff = (size_t)(n0 + r) * DIMX; }
            cp16(sa, src + goff + k0 + cc * 8);
        }
        asm volatile("cp.async.commit_group;" ::: "memory");
    };

    issue_stage(0);

    const int lr = lane & 15;
    const int lc = (lane >> 4) * 8;

    for (int kt = 0; kt < nkt; kt++) {
        if (kt + 1 < nkt) {
            issue_stage(kt + 1);
            asm volatile("cp.async.wait_group 1;" ::: "memory");
        } else {
            asm volatile("cp.async.wait_group 0;" ::: "memory");
        }
        __syncthreads();

        const uint32_t st = sb + (kt & 1) * STAGE_B;
        const uint32_t aBaseH = st + 0 * TILE_B + (warp_m * 64 + lr) * (RS * 2);
        const uint32_t aBaseL = st + 1 * TILE_B + (warp_m * 64 + lr) * (RS * 2);
        const uint32_t bBaseH = st + 2 * TILE_B + (warp_n * 32 + lr) * (RS * 2);
        const uint32_t bBaseL = st + 3 * TILE_B + (warp_n * 32 + lr) * (RS * 2);

#pragma unroll
        for (int ks = 0; ks < BK; ks += 16) {
            uint32_t ah[4][4], al[4][4], bh[2][4], bl[2][4];
            const uint32_t koff = (ks + lc) * 2;
#pragma unroll
            for (int mt = 0; mt < 4; mt++) {
                ldm_x4(aBaseH + mt * 16 * (RS * 2) + koff,
                       ah[mt][0], ah[mt][1], ah[mt][2], ah[mt][3]);
                ldm_x4(aBaseL + mt * 16 * (RS * 2) + koff,
                       al[mt][0], al[mt][1], al[mt][2], al[mt][3]);
            }
#pragma unroll
            for (int p = 0; p < 2; p++) {
                ldm_x4(bBaseH + p * 16 * (RS * 2) + koff,
                       bh[p][0], bh[p][1], bh[p][2], bh[p][3]);
                ldm_x4(bBaseL + p * 16 * (RS * 2) + koff,
                       bl[p][0], bl[p][1], bl[p][2], bl[p][3]);
            }
#pragma unroll
            for (int mt = 0; mt < 4; mt++)
#pragma unroll
                for (int nt = 0; nt < 4; nt++) {
                    const int p = nt >> 1, s = nt & 1;
                    mma16816(acc[mt][nt], ah[mt], bh[p][s], bh[p][s + 2]);
                    mma16816(acc[mt][nt], ah[mt], bl[p][s], bl[p][s + 2]);
                    mma16816(acc[mt][nt], al[mt], bh[p][s], bh[p][s + 2]);
                }
        }
        __syncthreads();
    }

    // epilogue: c-frag (mt,nt): rows m0+warp_m*64+mt*16+lane/4 (+8),
    //                           cols n0+warp_n*32+nt*8+2*(lane&3) (+1)
#pragma unroll
    for (int mt = 0; mt < 4; mt++) {
#pragma unroll
        for (int half = 0; half < 2; half++) {
            const int m = m0 + warp_m * 64 + mt * 16 + (lane >> 2) + half * 8;
#pragma unroll
            for (int nt = 0; nt < 4; nt++) {
                const int c = n0 + warp_n * 32 + nt * 8 + 2 * (lane & 3);
                float v0 = acc[mt][nt][half * 2 + 0];
                float v1 = acc[mt][nt][half * 2 + 1];
                if (mode == 2) {
                    float2 o = {v0 + bias[c], v1 + bias[c + 1]};
                    *(float2*)&outp[(size_t)m * DIMX + c] = o;
                } else {
                    const int bb = m >> 10, ii = m & 1023;
                    int col0 = c;
                    float* dst;
                    if (mode == 0) dst = g_q;
                    else if (col0 < INNER) dst = g_k;
                    else { dst = g_v; col0 -= INNER; }
                    const int hh = col0 >> 6, dd = col0 & 63;
                    float2 o = {v0, v1};
                    *(float2*)&dst[(((size_t)bb * HEADS + hh) * N_SEQ + ii) * DH + dd] = o;
                }
            }
        }
    }
}

// ---------------------------------------------------------------------------
// Fused flash attention with relative position bias (fp32 CUDA cores).
// Epilogue emits bf16 hi/lo into g_oh/g_ol for the Wo GEMM.
// ---------------------------------------------------------------------------
__global__ __launch_bounds__(256) void attn_kernel(const float* __restrict__ rel_emb)
{
    extern __shared__ float sm[];
    float* q_s   = sm;                        // 4096
    float* kp_s  = sm + 4096;                 // 64*68 (K^T, then P)
    float* v_s   = sm + 4096 + 4352;          // 4096
    float* rel_s = sm + 4096 + 4352 + 4096;   // 127*65

    const int tid = threadIdx.x;
    const int tx = tid & 15, ty = tid >> 4;
    const int i0 = blockIdx.x * 64;
    const int h  = blockIdx.y;
    const int b  = blockIdx.z;
    const size_t headbase = ((size_t)b * HEADS + h) * N_SEQ * DH;

    for (int idx = tid * 4; idx < 64 * 64; idx += 256 * 4)
        *(float4*)&q_s[idx] = *(const float4*)&g_q[headbase + (size_t)i0 * DH + idx];

    float m_i[4], l_i[4], o[4][4];
#pragma unroll
    for (int i = 0; i < 4; i++) {
        m_i[i] = -1e30f; l_i[i] = 0.f;
#pragma unroll
        for (int j = 0; j < 4; j++) o[i][j] = 0.f;
    }

    const float scale = 0.125f;
    const int base2 = ty * 4 - tx * 4 + 63;

    for (int jt = 0; jt < 16; jt++) {
        const int j0 = jt * 64;
        __syncthreads();

        for (int idx = tid; idx < 4096; idx += 256) {
            int j = idx >> 6, d = idx & 63;
            kp_s[d * 68 + j] = g_k[headbase + (size_t)(j0 + j) * DH + d];
        }
        for (int idx = tid * 4; idx < 4096; idx += 1024)
            *(float4*)&v_s[idx] = *(const float4*)&g_v[headbase + (size_t)j0 * DH + idx];
        for (int idx = tid; idx < 127 * 64; idx += 256) {
            int r = idx >> 6, col = idx & 63;
            int dist = i0 - j0 - 63 + r;
            dist = min(max(dist, -MAXPOS), MAXPOS) + MAXPOS;
            rel_s[r * 65 + col] = rel_emb[(size_t)dist * DH + col];
        }
        __syncthreads();

        float acc[4][4];
#pragma unroll
        for (int i = 0; i < 4; i++)
#pragma unroll
            for (int j = 0; j < 4; j++) acc[i][j] = 0.f;

#pragma unroll 4
        for (int d = 0; d < 64; d++) {
            float4 k4 = *(float4*)&kp_s[d * 68 + tx * 4];
            float kb[4] = {k4.x, k4.y, k4.z, k4.w};
            float rl[7];
#pragma unroll
            for (int t = 0; t < 7; t++) rl[t] = rel_s[(base2 - 3 + t) * 65 + d];
#pragma unroll
            for (int i = 0; i < 4; i++) {
                float qv = q_s[(ty * 4 + i) * 64 + d];
#pragma unroll
                for (int j = 0; j < 4; j++)
                    acc[i][j] = fmaf(qv, kb[j] + rl[i - j + 3], acc[i][j]);
            }
        }

        float p[4][4];
#pragma unroll
        for (int i = 0; i < 4; i++) {
            float rmax = -1e30f;
#pragma unroll
            for (int j = 0; j < 4; j++) {
                acc[i][j] *= scale;
                rmax = fmaxf(rmax, acc[i][j]);
            }
#pragma unroll
            for (int msk = 8; msk >= 1; msk >>= 1)
                rmax = fmaxf(rmax, __shfl_xor_sync(0xffffffffu, rmax, msk));
            float mnew = fmaxf(m_i[i], rmax);
            float alpha = __expf(m_i[i] - mnew);
            m_i[i] = mnew;
            float rsum = 0.f;
#pragma unroll
            for (int j = 0; j < 4; j++) {
                p[i][j] = __expf(acc[i][j] - mnew);
                rsum += p[i][j];
            }
#pragma unroll
            for (int msk = 8; msk >= 1; msk >>= 1)
                rsum += __shfl_xor_sync(0xffffffffu, rsum, msk);
            l_i[i] = l_i[i] * alpha + rsum;
#pragma unroll
            for (int j = 0; j < 4; j++) o[i][j] *= alpha;
        }

        __syncthreads();
#pragma unroll
        for (int i = 0; i < 4; i++)
#pragma unroll
            for (int j = 0; j < 4; j++)
                kp_s[(ty * 4 + i) * 68 + tx * 4 + j] = p[i][j];
        __syncthreads();

        for (int j = 0; j < 64; j++) {
            float4 v4 = *(float4*)&v_s[j * 64 + tx * 4];
            float vb[4] = {v4.x, v4.y, v4.z, v4.w};
#pragma unroll
            for (int i = 0; i < 4; i++) {
                float pv = kp_s[(ty * 4 + i) * 68 + j];
#pragma unroll
                for (int jj = 0; jj < 4; jj++)
                    o[i][jj] = fmaf(pv, vb[jj], o[i][jj]);
            }
        }
    }

#pragma unroll
    for (int i = 0; i < 4; i++) {
        float inv = 1.f / l_i[i];
        int row = i0 + ty * 4 + i;
        float f0 = o[i][0] * inv, f1 = o[i][1] * inv;
        float f2 = o[i][2] * inv, f3 = o[i][3] * inv;
        __nv_bfloat16 h0 = __float2bfloat16(f0), h1 = __float2bfloat16(f1);
        __nv_bfloat16 h2 = __float2bfloat16(f2), h3 = __float2bfloat16(f3);
        __nv_bfloat16 l0 = __float2bfloat16(f0 - __bfloat162float(h0));
        __nv_bfloat16 l1 = __float2bfloat16(f1 - __bfloat162float(h1));
        __nv_bfloat16 l2 = __float2bfloat16(f2 - __bfloat162float(h2));
        __nv_bfloat16 l3 = __float2bfloat16(f3 - __bfloat162float(h3));
        size_t base = ((size_t)b * N_SEQ + row) * INNER + h * DH + tx * 4;
        *(__nv_bfloat162*)&g_oh[base]     = {h0, h1};
        *(__nv_bfloat162*)&g_oh[base + 2] = {h2, h3};
        *(__nv_bfloat162*)&g_ol[base]     = {l0, l1};
        *(__nv_bfloat162*)&g_ol[base + 2] = {l2, l3};
    }
}

// ---------------------------------------------------------------------------
extern "C" void kernel_launch(void* const* d_in, const int* in_sizes, int n_in,
                              void* d_out, int out_size)
{
    (void)in_sizes; (void)n_in; (void)out_size;
    const float* x   = (const float*)d_in[0];
    const float* Wq  = (const float*)d_in[1];   // [1024,1024]
    const float* Wkv = (const float*)d_in[2];   // [1024,2048]
    const float* Wo  = (const float*)d_in[3];   // [1024,1024]
    const float* bo  = (const float*)d_in[4];
    const float* rel = (const float*)d_in[5];
    float* out = (float*)d_out;

    const int GEMM_SMEM = 2 * STAGE_B;          // 81920
    cudaFuncSetAttribute(gemm_mma, cudaFuncAttributeMaxDynamicSharedMemorySize, GEMM_SMEM);
    cudaFuncSetAttribute(attn_kernel, cudaFuncAttributeMaxDynamicSharedMemorySize, 83200);

    // fp32 -> bf16 hi/lo conversions
    split_kernel<<<2048, 256>>>(x, (B_DIM * N_SEQ * DIMX) / 4);
    tsplit_kernel<<<dim3(INNER / 32, DIMX / 32), 256>>>(Wq, DIMX, INNER, 0);
    tsplit_kernel<<<dim3(2 * INNER / 32, DIMX / 32), 256>>>(Wkv, DIMX, 2 * INNER, 1);
    tsplit_kernel<<<dim3(DIMX / 32, INNER / 32), 256>>>(Wo, INNER, DIMX, 2);

    // q = x @ Wq   (tensor cores via mma.sync, bf16-split)
    gemm_mma<<<dim3(INNER / 128, (B_DIM * N_SEQ) / 128), 256, GEMM_SMEM>>>(0, nullptr, nullptr);
    // kv = x @ Wkv
    gemm_mma<<<dim3(2 * INNER / 128, (B_DIM * N_SEQ) / 128), 256, GEMM_SMEM>>>(1, nullptr, nullptr);

    // fused attention (fp32) -> g_oh/g_ol
    attn_kernel<<<dim3(16, HEADS, B_DIM), 256, 83196>>>(rel);

    // out = o @ Wo + bo
    gemm_mma<<<dim3(DIMX / 128, (B_DIM * N_SEQ) / 128), 256, GEMM_SMEM>>>(2, bo, out);
}

// round 4
// speedup vs baseline: 2.5878x; 1.8176x over previous
#include <cuda_runtime.h>
#include <cuda_bf16.h>
#include <cstdint>

#define B_DIM  2
#define N_SEQ  1024
#define DIMX   1024
#define HEADS  16
#define DH     64
#define INNER  1024
#define MAXPOS 512

// ------------------------- device scratch (no allocs) -----------------------
__device__ __align__(16) __nv_bfloat16 g_xh[(size_t)B_DIM*N_SEQ*DIMX];
__device__ __align__(16) __nv_bfloat16 g_xl[(size_t)B_DIM*N_SEQ*DIMX];
__device__ __align__(16) __nv_bfloat16 g_wqh[(size_t)DIMX*INNER];
__device__ __align__(16) __nv_bfloat16 g_wql[(size_t)DIMX*INNER];
__device__ __align__(16) __nv_bfloat16 g_wkvh[(size_t)2*DIMX*INNER];
__device__ __align__(16) __nv_bfloat16 g_wkvl[(size_t)2*DIMX*INNER];
__device__ __align__(16) __nv_bfloat16 g_woh[(size_t)INNER*DIMX];
__device__ __align__(16) __nv_bfloat16 g_wol[(size_t)INNER*DIMX];
__device__ __align__(16) __nv_bfloat16 g_oh[(size_t)B_DIM*N_SEQ*INNER];
__device__ __align__(16) __nv_bfloat16 g_ol[(size_t)B_DIM*N_SEQ*INNER];
// q,k,v as bf16 hi/lo, head-major [b][h][i][d]; q pre-scaled by dh^-0.5
__device__ __align__(16) __nv_bfloat16 g_qh[(size_t)B_DIM*HEADS*N_SEQ*DH];
__device__ __align__(16) __nv_bfloat16 g_ql[(size_t)B_DIM*HEADS*N_SEQ*DH];
__device__ __align__(16) __nv_bfloat16 g_kh[(size_t)B_DIM*HEADS*N_SEQ*DH];
__device__ __align__(16) __nv_bfloat16 g_kl[(size_t)B_DIM*HEADS*N_SEQ*DH];
__device__ __align__(16) __nv_bfloat16 g_vh[(size_t)B_DIM*HEADS*N_SEQ*DH];
__device__ __align__(16) __nv_bfloat16 g_vl[(size_t)B_DIM*HEADS*N_SEQ*DH];
// rel_emb bf16 hi/lo [1025][64]
__device__ __align__(16) __nv_bfloat16 g_relh[(size_t)(2*MAXPOS+1)*DH];
__device__ __align__(16) __nv_bfloat16 g_rell[(size_t)(2*MAXPOS+1)*DH];

// ------------------------------- helpers ------------------------------------
__device__ __forceinline__ uint32_t smem_u32(const void* p) {
    uint32_t a;
    asm("{ .reg .u64 t; cvta.to.shared.u64 t, %1; cvt.u32.u64 %0, t; }"
        : "=r"(a) : "l"(p));
    return a;
}
__device__ __forceinline__ void cp16(uint32_t saddr, const void* gaddr) {
    asm volatile("cp.async.cg.shared.global [%0], [%1], 16;"
                 :: "r"(saddr), "l"(gaddr) : "memory");
}
__device__ __forceinline__ void ldm_x4(uint32_t a, uint32_t& r0, uint32_t& r1,
                                       uint32_t& r2, uint32_t& r3) {
    asm volatile("ldmatrix.sync.aligned.m8n8.x4.shared.b16 {%0,%1,%2,%3}, [%4];"
                 : "=r"(r0), "=r"(r1), "=r"(r2), "=r"(r3) : "r"(a));
}
__device__ __forceinline__ void ldm_x4t(uint32_t a, uint32_t& r0, uint32_t& r1,
                                        uint32_t& r2, uint32_t& r3) {
    asm volatile("ldmatrix.sync.aligned.m8n8.x4.trans.shared.b16 {%0,%1,%2,%3}, [%4];"
                 : "=r"(r0), "=r"(r1), "=r"(r2), "=r"(r3) : "r"(a));
}
__device__ __forceinline__ void mma16816(float* c, const uint32_t* a,
                                         uint32_t b0, uint32_t b1) {
    asm volatile(
        "mma.sync.aligned.m16n8k16.row.col.f32.bf16.bf16.f32 "
        "{%0,%1,%2,%3}, {%4,%5,%6,%7}, {%8,%9}, {%0,%1,%2,%3};"
        : "+f"(c[0]), "+f"(c[1]), "+f"(c[2]), "+f"(c[3])
        : "r"(a[0]), "r"(a[1]), "r"(a[2]), "r"(a[3]), "r"(b0), "r"(b1));
}
__device__ __forceinline__ uint32_t sw128(uint32_t off) {
    return off ^ ((off >> 3) & 0x70);
}
__device__ __forceinline__ void split2(float a, float b, uint32_t& hi, uint32_t& lo) {
    __nv_bfloat162 h, l;
    h.x = __float2bfloat16(a); h.y = __float2bfloat16(b);
    l.x = __float2bfloat16(a - __bfloat162float(h.x));
    l.y = __float2bfloat16(b - __bfloat162float(h.y));
    hi = *(uint32_t*)&h; lo = *(uint32_t*)&l;
}

// ------------------------- conversion kernels -------------------------------
__global__ __launch_bounds__(256) void split_kernel(const float* __restrict__ in, int n4)
{
    int i = blockIdx.x * blockDim.x + threadIdx.x;
    if (i >= n4) return;
    float4 v = ((const float4*)in)[i];
    uint32_t h0, l0, h1, l1;
    split2(v.x, v.y, h0, l0);
    split2(v.z, v.w, h1, l1);
    ((uint32_t*)g_xh)[2*i] = h0; ((uint32_t*)g_xh)[2*i+1] = h1;
    ((uint32_t*)g_xl)[2*i] = l0; ((uint32_t*)g_xl)[2*i+1] = l1;
}

__global__ __launch_bounds__(256) void relsplit_kernel(const float* __restrict__ rel, int n4)
{
    int i = blockIdx.x * blockDim.x + threadIdx.x;
    if (i >= n4) return;
    float4 v = ((const float4*)rel)[i];
    uint32_t h0, l0, h1, l1;
    split2(v.x, v.y, h0, l0);
    split2(v.z, v.w, h1, l1);
    ((uint32_t*)g_relh)[2*i] = h0; ((uint32_t*)g_relh)[2*i+1] = h1;
    ((uint32_t*)g_rell)[2*i] = l0; ((uint32_t*)g_rell)[2*i+1] = l1;
}

// transpose + split: W[K][N] fp32 -> Wt_h/Wt_l [N][K] bf16
__global__ __launch_bounds__(256) void tsplit_kernel(const float* __restrict__ W,
                                                     int K, int N, int mode)
{
    __shared__ float t[32][33];
    __nv_bfloat16 *th, *tl;
    if (mode == 0)      { th = g_wqh;  tl = g_wql; }
    else if (mode == 1) { th = g_wkvh; tl = g_wkvl; }
    else                { th = g_woh;  tl = g_wol; }

    const int n0 = blockIdx.x * 32, k0 = blockIdx.y * 32;
    const int tx = threadIdx.x & 31, ty = threadIdx.x >> 5;
#pragma unroll
    for (int r = 0; r < 4; r++)
        t[ty + 8*r][tx] = W[(size_t)(k0 + ty + 8*r) * N + n0 + tx];
    __syncthreads();
#pragma unroll
    for (int r = 0; r < 4; r++) {
        float v = t[tx][ty + 8*r];
        __nv_bfloat16 h = __float2bfloat16(v);
        __nv_bfloat16 l = __float2bfloat16(v - __bfloat162float(h));
        size_t o = (size_t)(n0 + ty + 8*r) * K + k0 + tx;
        th[o] = h; tl[o] = l;
    }
}

// ------------------------- mma.sync bf16-split GEMM -------------------------
#define BK 32
#define RS 40
#define TILE_B (128 * RS * 2)
#define STAGE_B (4 * TILE_B)

__global__ __launch_bounds__(256, 1) void gemm_mma(int mode,
                                                   const float* __restrict__ bias,
                                                   float* __restrict__ outp)
{
    extern __shared__ __align__(128) char smem[];
    const uint32_t sb = smem_u32(smem);
    const int tid = threadIdx.x;
    const int wid = tid >> 5, lane = tid & 31;
    const int warp_m = wid & 1, warp_n = wid >> 1;
    const int m0 = blockIdx.y * 128, n0 = blockIdx.x * 128;

    const __nv_bfloat16 *Ah, *Al, *Bh, *Bl;
    if (mode == 0)      { Ah = g_xh; Al = g_xl; Bh = g_wqh;  Bl = g_wql;  }
    else if (mode == 1) { Ah = g_xh; Al = g_xl; Bh = g_wkvh; Bl = g_wkvl; }
    else                { Ah = g_oh; Al = g_ol; Bh = g_woh;  Bl = g_wol;  }

    float acc[4][4][4];
#pragma unroll
    for (int i = 0; i < 4; i++)
#pragma unroll
        for (int j = 0; j < 4; j++)
#pragma unroll
            for (int t = 0; t < 4; t++) acc[i][j][t] = 0.f;

    const int nkt = DIMX / BK;

    auto issue_stage = [&](int kt) {
        const int k0 = kt * BK;
        const uint32_t st = sb + (kt & 1) * STAGE_B;
#pragma unroll
        for (int i = 0; i < 8; i++) {
            int id = tid + i * 256;
            int tile = id >> 9, rem = id & 511;
            int r = rem >> 2, cc = rem & 3;
            uint32_t sa = st + tile * TILE_B + r * (RS * 2) + cc * 16;
            const __nv_bfloat16* src;
            size_t goff;
            if (tile == 0)      { src = Ah; goff = (size_t)(m0 + r) * DIMX; }
            else if (tile == 1) { src = Al; goff = (size_t)(m0 + r) * DIMX; }
            else if (tile == 2) { src = Bh; goff = (size_t)(n0 + r) * DIMX; }
            else                { src = Bl; goff = (size_t)(n0 + r) * DIMX; }
            cp16(sa, src + goff + k0 + cc * 8);
        }
        asm volatile("cp.async.commit_group;" ::: "memory");
    };

    issue_stage(0);

    const int lr = lane & 15;
    const int lc = (lane >> 4) * 8;

    for (int kt = 0; kt < nkt; kt++) {
        if (kt + 1 < nkt) {
            issue_stage(kt + 1);
            asm volatile("cp.async.wait_group 1;" ::: "memory");
        } else {
            asm volatile("cp.async.wait_group 0;" ::: "memory");
        }
        __syncthreads();

        const uint32_t st = sb + (kt & 1) * STAGE_B;
        const uint32_t aBaseH = st + 0 * TILE_B + (warp_m * 64 + lr) * (RS * 2);
        const uint32_t aBaseL = st + 1 * TILE_B + (warp_m * 64 + lr) * (RS * 2);
        const uint32_t bBaseH = st + 2 * TILE_B + (warp_n * 32 + lr) * (RS * 2);
        const uint32_t bBaseL = st + 3 * TILE_B + (warp_n * 32 + lr) * (RS * 2);

#pragma unroll
        for (int ks = 0; ks < BK; ks += 16) {
            uint32_t ah[4][4], al[4][4], bh[2][4], bl[2][4];
            const uint32_t koff = (ks + lc) * 2;
#pragma unroll
            for (int mt = 0; mt < 4; mt++) {
                ldm_x4(aBaseH + mt * 16 * (RS * 2) + koff,
                       ah[mt][0], ah[mt][1], ah[mt][2], ah[mt][3]);
                ldm_x4(aBaseL + mt * 16 * (RS * 2) + koff,
                       al[mt][0], al[mt][1], al[mt][2], al[mt][3]);
            }
#pragma unroll
            for (int p = 0; p < 2; p++) {
                ldm_x4(bBaseH + p * 16 * (RS * 2) + koff,
                       bh[p][0], bh[p][1], bh[p][2], bh[p][3]);
                ldm_x4(bBaseL + p * 16 * (RS * 2) + koff,
                       bl[p][0], bl[p][1], bl[p][2], bl[p][3]);
            }
#pragma unroll
            for (int mt = 0; mt < 4; mt++)
#pragma unroll
                for (int nt = 0; nt < 4; nt++) {
                    const int p = nt >> 1, s = nt & 1;
                    mma16816(acc[mt][nt], ah[mt], bh[p][s], bh[p][s + 2]);
                    mma16816(acc[mt][nt], ah[mt], bl[p][s], bl[p][s + 2]);
                    mma16816(acc[mt][nt], al[mt], bh[p][s], bh[p][s + 2]);
                }
        }
        __syncthreads();
    }

    const float qscale = 0.125f;  // dh^-0.5, folded into q
#pragma unroll
    for (int mt = 0; mt < 4; mt++) {
#pragma unroll
        for (int half = 0; half < 2; half++) {
            const int m = m0 + warp_m * 64 + mt * 16 + (lane >> 2) + half * 8;
#pragma unroll
            for (int nt = 0; nt < 4; nt++) {
                const int c = n0 + warp_n * 32 + nt * 8 + 2 * (lane & 3);
                float v0 = acc[mt][nt][half * 2 + 0];
                float v1 = acc[mt][nt][half * 2 + 1];
                if (mode == 2) {
                    float2 o = {v0 + bias[c], v1 + bias[c + 1]};
                    *(float2*)&outp[(size_t)m * DIMX + c] = o;
                } else {
                    const int bb = m >> 10, ii = m & 1023;
                    int col0 = c;
                    __nv_bfloat16 *dh, *dl;
                    if (mode == 0) {
                        dh = g_qh; dl = g_ql;
                        v0 *= qscale; v1 *= qscale;
                    } else if (col0 < INNER) { dh = g_kh; dl = g_kl; }
                    else { dh = g_vh; dl = g_vl; col0 -= INNER; }
                    const int hh = col0 >> 6, dd = col0 & 63;
                    uint32_t hi, lo;
                    split2(v0, v1, hi, lo);
                    size_t o = (((size_t)bb * HEADS + hh) * N_SEQ + ii) * DH + dd;
                    *(uint32_t*)&dh[o] = hi;
                    *(uint32_t*)&dl[o] = lo;
                }
            }
        }
    }
}

// ---------------------------------------------------------------------------
// Tensor-core flash attention with relative position bias, bf16-split 3-pass.
// CTA: 128 threads (4 warps), i-block 64 (warp w owns rows w*16..w*16+15),
// j-tiles of 64.  SW128-swizzled SMEM tiles (128B rows), V via ldmatrix.trans.
// ---------------------------------------------------------------------------
#define A_QH 0
#define A_QL 8192
#define A_KH 16384
#define A_KL 24576
#define A_VH 32768
#define A_VL 40960
#define A_RH 49152
#define A_RL 65536
#define A_S2 81920
#define S2S  132                       // f32 stride
#define ATT_SMEM (A_S2 + 64 * S2S * 4) // 115712

__global__ __launch_bounds__(128) void attn_mma(void)
{
    extern __shared__ __align__(128) char smem[];
    const uint32_t sb = smem_u32(smem);
    float* s2p = (float*)(smem + A_S2);

    const int tid  = threadIdx.x;
    const int lane = tid & 31, warp = tid >> 5;
    const int wbase = warp * 16;
    const int i0 = blockIdx.x * 64;
    const int h  = blockIdx.y;
    const int b  = blockIdx.z;
    const size_t hb = ((size_t)b * HEADS + h) * N_SEQ * DH;

    // ---- load Q (hi/lo) into SMEM ----
#pragma unroll
    for (int i = 0; i < 4; i++) {
        int id = tid + i * 128;
        int r = id >> 3, c = id & 7;
        uint32_t d = sw128(r * 128 + c * 16);
        cp16(sb + A_QH + d, g_qh + hb + (size_t)(i0 + r) * DH + c * 8);
        cp16(sb + A_QL + d, g_ql + hb + (size_t)(i0 + r) * DH + c * 8);
    }
    asm volatile("cp.async.commit_group;" ::: "memory");
    asm volatile("cp.async.wait_group 0;" ::: "memory");
    __syncthreads();

    // ---- Q a-frags in registers (reused for all 16 j-tiles) ----
    uint32_t qa[2][4][4];
#pragma unroll
    for (int ks = 0; ks < 4; ks++) {
        uint32_t off = sw128((wbase + (lane & 15)) * 128 + ks * 32 + (lane >> 4) * 16);
        ldm_x4(sb + A_QH + off, qa[0][ks][0], qa[0][ks][1], qa[0][ks][2], qa[0][ks][3]);
        ldm_x4(sb + A_QL + off, qa[1][ks][0], qa[1][ks][1], qa[1][ks][2], qa[1][ks][3]);
    }

    float o[8][4];
#pragma unroll
    for (int nt = 0; nt < 8; nt++)
#pragma unroll
        for (int e = 0; e < 4; e++) o[nt][e] = 0.f;
    float m2[2] = {-1e30f, -1e30f}, l2[2] = {0.f, 0.f};

    for (int jt = 0; jt < 16; jt++) {
        const int j0 = jt * 64;
        __syncthreads();   // prior tile's SMEM reads complete

        // group A: K hi/lo + rel hi/lo
#pragma unroll
        for (int i = 0; i < 4; i++) {
            int id = tid + i * 128;
            int r = id >> 3, c = id & 7;
            uint32_t d = sw128(r * 128 + c * 16);
            size_t g = hb + (size_t)(j0 + r) * DH + c * 8;
            cp16(sb + A_KH + d, g_kh + g);
            cp16(sb + A_KL + d, g_kl + g);
        }
#pragma unroll
        for (int i = 0; i < 8; i++) {
            int id = tid + i * 128;
            int r = id >> 3, c = id & 7;
            int dist = i0 - j0 - 63 + r;
            dist = min(max(dist, -MAXPOS), MAXPOS) + MAXPOS;
            uint32_t d = sw128(r * 128 + c * 16);
            size_t g = (size_t)dist * DH + c * 8;
            cp16(sb + A_RH + d, g_relh + g);
            cp16(sb + A_RL + d, g_rell + g);
        }
        asm volatile("cp.async.commit_group;" ::: "memory");
        // group B: V hi/lo
#pragma unroll
        for (int i = 0; i < 4; i++) {
            int id = tid + i * 128;
            int r = id >> 3, c = id & 7;
            uint32_t d = sw128(r * 128 + c * 16);
            size_t g = hb + (size_t)(j0 + r) * DH + c * 8;
            cp16(sb + A_VH + d, g_vh + g);
            cp16(sb + A_VL + d, g_vl + g);
        }
        asm volatile("cp.async.commit_group;" ::: "memory");

        asm volatile("cp.async.wait_group 1;" ::: "memory");  // K + rel ready
        __syncthreads();

        // ---- S2 = Q @ rel_windowT (64x128), two 64-col halves ----
#pragma unroll
        for (int hf = 0; hf < 2; hf++) {
            float s2[8][4];
#pragma unroll
            for (int nt = 0; nt < 8; nt++)
#pragma unroll
                for (int e = 0; e < 4; e++) s2[nt][e] = 0.f;
#pragma unroll
            for (int ks = 0; ks < 4; ks++) {
                uint32_t rbh[4][4], rbl[4][4];
#pragma unroll
                for (int g = 0; g < 4; g++) {
                    uint32_t off = sw128((hf * 64 + g * 16 + (lane & 15)) * 128
                                         + ks * 32 + (lane >> 4) * 16);
                    ldm_x4(sb + A_RH + off, rbh[g][0], rbh[g][1], rbh[g][2], rbh[g][3]);
                    ldm_x4(sb + A_RL + off, rbl[g][0], rbl[g][1], rbl[g][2], rbl[g][3]);
                }
#pragma unroll
                for (int nt = 0; nt < 8; nt++) {
                    const int p = nt >> 1, s_ = nt & 1;
                    mma16816(s2[nt], qa[0][ks], rbh[p][s_], rbh[p][s_ + 2]);
                    mma16816(s2[nt], qa[0][ks], rbl[p][s_], rbl[p][s_ + 2]);
                    mma16816(s2[nt], qa[1][ks], rbh[p][s_], rbh[p][s_ + 2]);
                }
            }
            const int rl0 = wbase + (lane >> 2);
#pragma unroll
            for (int nt = 0; nt < 8; nt++) {
                const int col = hf * 64 + nt * 8 + 2 * (lane & 3);
                *(float2*)&s2p[rl0 * S2S + col]       = {s2[nt][0], s2[nt][1]};
                *(float2*)&s2p[(rl0 + 8) * S2S + col] = {s2[nt][2], s2[nt][3]};
            }
        }
        __syncwarp();

        // ---- S1 = Q @ K^T (64x64) ----
        float s[8][4];
#pragma unroll
        for (int nt = 0; nt < 8; nt++)
#pragma unroll
            for (int e = 0; e < 4; e++) s[nt][e] = 0.f;
#pragma unroll
        for (int ks = 0; ks < 4; ks++) {
            uint32_t kbh[4][4], kbl[4][4];
#pragma unroll
            for (int g = 0; g < 4; g++) {
                uint32_t off = sw128((g * 16 + (lane & 15)) * 128
                                     + ks * 32 + (lane >> 4) * 16);
                ldm_x4(sb + A_KH + off, kbh[g][0], kbh[g][1], kbh[g][2], kbh[g][3]);
                ldm_x4(sb + A_KL + off, kbl[g][0], kbl[g][1], kbl[g][2], kbl[g][3]);
            }
#pragma unroll
            for (int nt = 0; nt < 8; nt++) {
                const int p = nt >> 1, s_ = nt & 1;
                mma16816(s[nt], qa[0][ks], kbh[p][s_], kbh[p][s_ + 2]);
                mma16816(s[nt], qa[0][ks], kbl[p][s_], kbl[p][s_ + 2]);
                mma16816(s[nt], qa[1][ks], kbh[p][s_], kbh[p][s_ + 2]);
            }
        }

        // ---- gather rel term, online softmax ----
        const int rl0 = wbase + (lane >> 2);
#pragma unroll
        for (int nt = 0; nt < 8; nt++)
#pragma unroll
            for (int e = 0; e < 4; e++) {
                const int rr = rl0 + 8 * (e >> 1);
                const int jj = nt * 8 + 2 * (lane & 3) + (e & 1);
                s[nt][e] += s2p[rr * S2S + rr - jj + 63];
            }

        float mx[2] = {-1e30f, -1e30f};
#pragma unroll
        for (int nt = 0; nt < 8; nt++)
#pragma unroll
            for (int e = 0; e < 4; e++)
                mx[e >> 1] = fmaxf(mx[e >> 1], s[nt][e]);
#pragma unroll
        for (int h2 = 0; h2 < 2; h2++) {
            mx[h2] = fmaxf(mx[h2], __shfl_xor_sync(0xffffffffu, mx[h2], 1));
            mx[h2] = fmaxf(mx[h2], __shfl_xor_sync(0xffffffffu, mx[h2], 2));
        }
        float al2[2];
#pragma unroll
        for (int h2 = 0; h2 < 2; h2++) {
            float mnew = fmaxf(m2[h2], mx[h2]);
            al2[h2] = __expf(m2[h2] - mnew);
            m2[h2] = mnew;
        }
        float sum[2] = {0.f, 0.f};
#pragma unroll
        for (int nt = 0; nt < 8; nt++)
#pragma unroll
            for (int e = 0; e < 4; e++) {
                float p = __expf(s[nt][e] - m2[e >> 1]);
                s[nt][e] = p;
                sum[e >> 1] += p;
            }
#pragma unroll
        for (int h2 = 0; h2 < 2; h2++) {
            sum[h2] += __shfl_xor_sync(0xffffffffu, sum[h2], 1);
            sum[h2] += __shfl_xor_sync(0xffffffffu, sum[h2], 2);
            l2[h2] = l2[h2] * al2[h2] + sum[h2];
        }
#pragma unroll
        for (int nt = 0; nt < 8; nt++) {
            o[nt][0] *= al2[0]; o[nt][1] *= al2[0];
            o[nt][2] *= al2[1]; o[nt][3] *= al2[1];
        }

        // ---- P c-frag -> a-frag (bf16 hi/lo) ----
        uint32_t pah[4][4], pal[4][4];
#pragma unroll
        for (int ks = 0; ks < 4; ks++) {
            split2(s[2*ks][0],   s[2*ks][1],   pah[ks][0], pal[ks][0]);
            split2(s[2*ks][2],   s[2*ks][3],   pah[ks][1], pal[ks][1]);
            split2(s[2*ks+1][0], s[2*ks+1][1], pah[ks][2], pal[ks][2]);
            split2(s[2*ks+1][2], s[2*ks+1][3], pah[ks][3], pal[ks][3]);
        }

        asm volatile("cp.async.wait_group 0;" ::: "memory");  // V ready
        __syncthreads();

        // ---- O += P @ V ----
#pragma unroll
        for (int ks = 0; ks < 4; ks++) {
            uint32_t vbh[4][4], vbl[4][4];
            const int jr = ks * 16 + (lane & 7) + ((lane >> 3) & 1) * 8;
#pragma unroll
            for (int dp = 0; dp < 4; dp++) {
                uint32_t off = sw128(jr * 128 + dp * 32 + (lane >> 4) * 16);
                ldm_x4t(sb + A_VH + off, vbh[dp][0], vbh[dp][1], vbh[dp][2], vbh[dp][3]);
                ldm_x4t(sb + A_VL + off, vbl[dp][0], vbl[dp][1], vbl[dp][2], vbl[dp][3]);
            }
#pragma unroll
            for (int nt = 0; nt < 8; nt++) {
                const int dp = nt >> 1, s_ = (nt & 1) * 2;
                mma16816(o[nt], pah[ks], vbh[dp][s_], vbh[dp][s_ + 1]);
                mma16816(o[nt], pah[ks], vbl[dp][s_], vbl[dp][s_ + 1]);
                mma16816(o[nt], pal[ks], vbh[dp][s_], vbh[dp][s_ + 1]);
            }
        }
    }

    // ---- epilogue: normalize, split bf16 hi/lo -> g_oh/g_ol ----
    const float inv0 = 1.f / l2[0], inv1 = 1.f / l2[1];
    const int row0 = i0 + wbase + (lane >> 2);
#pragma unroll
    for (int nt = 0; nt < 8; nt++) {
        const int d = nt * 8 + 2 * (lane & 3);
        uint32_t hi, lo;
        size_t base0 = ((size_t)b * N_SEQ + row0) * INNER + h * DH + d;
        split2(o[nt][0] * inv0, o[nt][1] * inv0, hi, lo);
        *(uint32_t*)&g_oh[base0] = hi;
        *(uint32_t*)&g_ol[base0] = lo;
        size_t base1 = ((size_t)b * N_SEQ + row0 + 8) * INNER + h * DH + d;
        split2(o[nt][2] * inv1, o[nt][3] * inv1, hi, lo);
        *(uint32_t*)&g_oh[base1] = hi;
        *(uint32_t*)&g_ol[base1] = lo;
    }
}

// ---------------------------------------------------------------------------
extern "C" void kernel_launch(void* const* d_in, const int* in_sizes, int n_in,
                              void* d_out, int out_size)
{
    (void)in_sizes; (void)n_in; (void)out_size;
    const float* x   = (const float*)d_in[0];
    const float* Wq  = (const float*)d_in[1];
    const float* Wkv = (const float*)d_in[2];
    const float* Wo  = (const float*)d_in[3];
    const float* bo  = (const float*)d_in[4];
    const float* rel = (const float*)d_in[5];
    float* out = (float*)d_out;

    const int GEMM_SMEM = 2 * STAGE_B;
    cudaFuncSetAttribute(gemm_mma, cudaFuncAttributeMaxDynamicSharedMemorySize, GEMM_SMEM);
    cudaFuncSetAttribute(attn_mma, cudaFuncAttributeMaxDynamicSharedMemorySize, ATT_SMEM);

    // fp32 -> bf16 hi/lo conversions
    split_kernel<<<2048, 256>>>(x, (B_DIM * N_SEQ * DIMX) / 4);
    relsplit_kernel<<<65, 256>>>(rel, (2 * MAXPOS + 1) * DH / 4);
    tsplit_kernel<<<dim3(INNER / 32, DIMX / 32), 256>>>(Wq, DIMX, INNER, 0);
    tsplit_kernel<<<dim3(2 * INNER / 32, DIMX / 32), 256>>>(Wkv, DIMX, 2 * INNER, 1);
    tsplit_kernel<<<dim3(DIMX / 32, INNER / 32), 256>>>(Wo, INNER, DIMX, 2);

    // projections (tensor cores)
    gemm_mma<<<dim3(INNER / 128, (B_DIM * N_SEQ) / 128), 256, GEMM_SMEM>>>(0, nullptr, nullptr);
    gemm_mma<<<dim3(2 * INNER / 128, (B_DIM * N_SEQ) / 128), 256, GEMM_SMEM>>>(1, nullptr, nullptr);

    // fused attention (tensor cores) -> g_oh/g_ol
    attn_mma<<<dim3(16, HEADS, B_DIM), 128, ATT_SMEM>>>();

    // out = o @ Wo + bo
    gemm_mma<<<dim3(DIMX / 128, (B_DIM * N_SEQ) / 128), 256, GEMM_SMEM>>>(2, bo, out);
}

// round 5
// speedup vs baseline: 2.9184x; 1.1277x over previous
#include <cuda_runtime.h>
#include <cuda_bf16.h>
#include <cstdint>

#define B_DIM  2
#define N_SEQ  1024
#define DIMX   1024
#define HEADS  16
#define DH     64
#define INNER  1024
#define MAXPOS 512

// ------------------------- device scratch (no allocs) -----------------------
__device__ __align__(16) __nv_bfloat16 g_xh[(size_t)B_DIM*N_SEQ*DIMX];
__device__ __align__(16) __nv_bfloat16 g_xl[(size_t)B_DIM*N_SEQ*DIMX];
// fused projection weights [Wq|Wkv] transposed: [3072][1024]
__device__ __align__(16) __nv_bfloat16 g_wph[(size_t)3*DIMX*INNER];
__device__ __align__(16) __nv_bfloat16 g_wpl[(size_t)3*DIMX*INNER];
__device__ __align__(16) __nv_bfloat16 g_woh[(size_t)INNER*DIMX];
__device__ __align__(16) __nv_bfloat16 g_wol[(size_t)INNER*DIMX];
__device__ __align__(16) __nv_bfloat16 g_oh[(size_t)B_DIM*N_SEQ*INNER];
__device__ __align__(16) __nv_bfloat16 g_ol[(size_t)B_DIM*N_SEQ*INNER];
__device__ __align__(16) __nv_bfloat16 g_qh[(size_t)B_DIM*HEADS*N_SEQ*DH];
__device__ __align__(16) __nv_bfloat16 g_ql[(size_t)B_DIM*HEADS*N_SEQ*DH];
__device__ __align__(16) __nv_bfloat16 g_kh[(size_t)B_DIM*HEADS*N_SEQ*DH];
__device__ __align__(16) __nv_bfloat16 g_kl[(size_t)B_DIM*HEADS*N_SEQ*DH];
__device__ __align__(16) __nv_bfloat16 g_vh[(size_t)B_DIM*HEADS*N_SEQ*DH];
__device__ __align__(16) __nv_bfloat16 g_vl[(size_t)B_DIM*HEADS*N_SEQ*DH];
__device__ __align__(16) __nv_bfloat16 g_relh[(size_t)(2*MAXPOS+1)*DH];
__device__ __align__(16) __nv_bfloat16 g_rell[(size_t)(2*MAXPOS+1)*DH];

// ------------------------------- helpers ------------------------------------
__device__ __forceinline__ uint32_t smem_u32(const void* p) {
    uint32_t a;
    asm("{ .reg .u64 t; cvta.to.shared.u64 t, %1; cvt.u32.u64 %0, t; }"
        : "=r"(a) : "l"(p));
    return a;
}
__device__ __forceinline__ void cp16(uint32_t saddr, const void* gaddr) {
    asm volatile("cp.async.cg.shared.global [%0], [%1], 16;"
                 :: "r"(saddr), "l"(gaddr) : "memory");
}
__device__ __forceinline__ void ldm_x4(uint32_t a, uint32_t& r0, uint32_t& r1,
                                       uint32_t& r2, uint32_t& r3) {
    asm volatile("ldmatrix.sync.aligned.m8n8.x4.shared.b16 {%0,%1,%2,%3}, [%4];"
                 : "=r"(r0), "=r"(r1), "=r"(r2), "=r"(r3) : "r"(a));
}
__device__ __forceinline__ void ldm_x4t(uint32_t a, uint32_t& r0, uint32_t& r1,
                                        uint32_t& r2, uint32_t& r3) {
    asm volatile("ldmatrix.sync.aligned.m8n8.x4.trans.shared.b16 {%0,%1,%2,%3}, [%4];"
                 : "=r"(r0), "=r"(r1), "=r"(r2), "=r"(r3) : "r"(a));
}
__device__ __forceinline__ void mma16816(float* c, const uint32_t* a,
                                         uint32_t b0, uint32_t b1) {
    asm volatile(
        "mma.sync.aligned.m16n8k16.row.col.f32.bf16.bf16.f32 "
        "{%0,%1,%2,%3}, {%4,%5,%6,%7}, {%8,%9}, {%0,%1,%2,%3};"
        : "+f"(c[0]), "+f"(c[1]), "+f"(c[2]), "+f"(c[3])
        : "r"(a[0]), "r"(a[1]), "r"(a[2]), "r"(a[3]), "r"(b0), "r"(b1));
}
__device__ __forceinline__ uint32_t sw128(uint32_t off) {
    return off ^ ((off >> 3) & 0x70);
}
__device__ __forceinline__ void split2(float a, float b, uint32_t& hi, uint32_t& lo) {
    __nv_bfloat162 h, l;
    h.x = __float2bfloat16(a); h.y = __float2bfloat16(b);
    l.x = __float2bfloat16(a - __bfloat162float(h.x));
    l.y = __float2bfloat16(b - __bfloat162float(h.y));
    hi = *(uint32_t*)&h; lo = *(uint32_t*)&l;
}

// ------------------------- conversion kernels -------------------------------
#define NX4 (B_DIM * N_SEQ * DIMX / 4)          // 524288
#define NR4 ((2 * MAXPOS + 1) * DH / 4)         // 16400

__global__ __launch_bounds__(256) void split_xrel(const float* __restrict__ x,
                                                  const float* __restrict__ rel)
{
    int i = blockIdx.x * blockDim.x + threadIdx.x;
    if (i >= NX4 + NR4) return;
    if (i < NX4) {
        float4 v = ((const float4*)x)[i];
        uint32_t h0, l0, h1, l1;
        split2(v.x, v.y, h0, l0);
        split2(v.z, v.w, h1, l1);
        ((uint32_t*)g_xh)[2*i] = h0; ((uint32_t*)g_xh)[2*i+1] = h1;
        ((uint32_t*)g_xl)[2*i] = l0; ((uint32_t*)g_xl)[2*i+1] = l1;
    } else {
        int j = i - NX4;
        float4 v = ((const float4*)rel)[j];
        uint32_t h0, l0, h1, l1;
        split2(v.x, v.y, h0, l0);
        split2(v.z, v.w, h1, l1);
        ((uint32_t*)g_relh)[2*j] = h0; ((uint32_t*)g_relh)[2*j+1] = h1;
        ((uint32_t*)g_rell)[2*j] = l0; ((uint32_t*)g_rell)[2*j+1] = l1;
    }
}

// transpose + split all weights in one launch.
// blocks 0..1023: Wq[1024][1024]  -> g_wp rows 0..1023
// blocks 1024..3071: Wkv[1024][2048] -> g_wp rows 1024..3071
// blocks 3072..4095: Wo[1024][1024] -> g_wo rows 0..1023
__global__ __launch_bounds__(256) void tsplit_all(const float* __restrict__ Wq,
                                                  const float* __restrict__ Wkv,
                                                  const float* __restrict__ Wo)
{
    __shared__ float t[32][33];
    const int bid = blockIdx.x;
    const float* W; __nv_bfloat16 *th, *tl;
    int N, kt, ntile, rowoff;
    if (bid < 1024)      { W = Wq;  N = 1024; kt = bid >> 5; ntile = bid & 31;
                           th = g_wph; tl = g_wpl; rowoff = 0; }
    else if (bid < 3072) { int l = bid - 1024; W = Wkv; N = 2048;
                           kt = l >> 6; ntile = l & 63;
                           th = g_wph; tl = g_wpl; rowoff = 1024; }
    else                 { int l = bid - 3072; W = Wo; N = 1024;
                           kt = l >> 5; ntile = l & 31;
                           th = g_woh; tl = g_wol; rowoff = 0; }
    const int n0 = ntile * 32, k0 = kt * 32;
    const int tx = threadIdx.x & 31, ty = threadIdx.x >> 5;
#pragma unroll
    for (int r = 0; r < 4; r++)
        t[ty + 8*r][tx] = W[(size_t)(k0 + ty + 8*r) * N + n0 + tx];
    __syncthreads();
#pragma unroll
    for (int r = 0; r < 4; r++) {
        float v = t[tx][ty + 8*r];
        __nv_bfloat16 h = __float2bfloat16(v);
        __nv_bfloat16 l = __float2bfloat16(v - __bfloat162float(h));
        size_t o = (size_t)(rowoff + n0 + ty + 8*r) * 1024 + k0 + tx;
        th[o] = h; tl[o] = l;
    }
}

// ------------------------- mma.sync bf16-split GEMM -------------------------
// mode 0: C = x @ [Wq|Wkv] (N=3072) -> scatter q(scaled)/k/v bf16 hi/lo
// mode 2: C = o @ Wo + bias -> outp fp32
#define BK 32
#define RS 40
#define TILE_B (128 * RS * 2)
#define STAGE_B (4 * TILE_B)

__global__ __launch_bounds__(256, 1) void gemm_mma(int mode,
                                                   const float* __restrict__ bias,
                                                   float* __restrict__ outp)
{
    extern __shared__ __align__(128) char smem[];
    const uint32_t sb = smem_u32(smem);
    const int tid = threadIdx.x;
    const int wid = tid >> 5, lane = tid & 31;
    const int warp_m = wid & 1, warp_n = wid >> 1;
    const int m0 = blockIdx.y * 128, n0 = blockIdx.x * 128;

    const __nv_bfloat16 *Ah, *Al, *Bh, *Bl;
    if (mode == 0) { Ah = g_xh; Al = g_xl; Bh = g_wph; Bl = g_wpl; }
    else           { Ah = g_oh; Al = g_ol; Bh = g_woh; Bl = g_wol; }

    float acc[4][4][4];
#pragma unroll
    for (int i = 0; i < 4; i++)
#pragma unroll
        for (int j = 0; j < 4; j++)
#pragma unroll
            for (int t = 0; t < 4; t++) acc[i][j][t] = 0.f;

    const int nkt = DIMX / BK;

    auto issue_stage = [&](int kt) {
        const int k0 = kt * BK;
        const uint32_t st = sb + (kt & 1) * STAGE_B;
#pragma unroll
        for (int i = 0; i < 8; i++) {
            int id = tid + i * 256;
            int tile = id >> 9, rem = id & 511;
            int r = rem >> 2, cc = rem & 3;
            uint32_t sa = st + tile * TILE_B + r * (RS * 2) + cc * 16;
            const __nv_bfloat16* src;
            size_t goff;
            if (tile == 0)      { src = Ah; goff = (size_t)(m0 + r) * DIMX; }
            else if (tile == 1) { src = Al; goff = (size_t)(m0 + r) * DIMX; }
            else if (tile == 2) { src = Bh; goff = (size_t)(n0 + r) * DIMX; }
            else                { src = Bl; goff = (size_t)(n0 + r) * DIMX; }
            cp16(sa, src + goff + k0 + cc * 8);
        }
        asm volatile("cp.async.commit_group;" ::: "memory");
    };

    issue_stage(0);

    const int lr = lane & 15;
    const int lc = (lane >> 4) * 8;

    for (int kt = 0; kt < nkt; kt++) {
        if (kt + 1 < nkt) {
            issue_stage(kt + 1);
            asm volatile("cp.async.wait_group 1;" ::: "memory");
        } else {
            asm volatile("cp.async.wait_group 0;" ::: "memory");
        }
        __syncthreads();

        const uint32_t st = sb + (kt & 1) * STAGE_B;
        const uint32_t aBaseH = st + 0 * TILE_B + (warp_m * 64 + lr) * (RS * 2);
        const uint32_t aBaseL = st + 1 * TILE_B + (warp_m * 64 + lr) * (RS * 2);
        const uint32_t bBaseH = st + 2 * TILE_B + (warp_n * 32 + lr) * (RS * 2);
        const uint32_t bBaseL = st + 3 * TILE_B + (warp_n * 32 + lr) * (RS * 2);

#pragma unroll
        for (int ks = 0; ks < BK; ks += 16) {
            uint32_t ah[4][4], al[4][4], bh[2][4], bl[2][4];
            const uint32_t koff = (ks + lc) * 2;
#pragma unroll
            for (int mt = 0; mt < 4; mt++) {
                ldm_x4(aBaseH + mt * 16 * (RS * 2) + koff,
                       ah[mt][0], ah[mt][1], ah[mt][2], ah[mt][3]);
                ldm_x4(aBaseL + mt * 16 * (RS * 2) + koff,
                       al[mt][0], al[mt][1], al[mt][2], al[mt][3]);
            }
#pragma unroll
            for (int p = 0; p < 2; p++) {
                ldm_x4(bBaseH + p * 16 * (RS * 2) + koff,
                       bh[p][0], bh[p][1], bh[p][2], bh[p][3]);
                ldm_x4(bBaseL + p * 16 * (RS * 2) + koff,
                       bl[p][0], bl[p][1], bl[p][2], bl[p][3]);
            }
#pragma unroll
            for (int mt = 0; mt < 4; mt++)
#pragma unroll
                for (int nt = 0; nt < 4; nt++) {
                    const int p = nt >> 1, s = nt & 1;
                    mma16816(acc[mt][nt], ah[mt], bh[p][s], bh[p][s + 2]);
                    mma16816(acc[mt][nt], ah[mt], bl[p][s], bl[p][s + 2]);
                    mma16816(acc[mt][nt], al[mt], bh[p][s], bh[p][s + 2]);
                }
        }
        __syncthreads();
    }

    const float qscale = 0.125f;
#pragma unroll
    for (int mt = 0; mt < 4; mt++) {
#pragma unroll
        for (int half = 0; half < 2; half++) {
            const int m = m0 + warp_m * 64 + mt * 16 + (lane >> 2) + half * 8;
#pragma unroll
            for (int nt = 0; nt < 4; nt++) {
                const int c = n0 + warp_n * 32 + nt * 8 + 2 * (lane & 3);
                float v0 = acc[mt][nt][half * 2 + 0];
                float v1 = acc[mt][nt][half * 2 + 1];
                if (mode != 0) {
                    float2 o = {v0 + bias[c], v1 + bias[c + 1]};
                    *(float2*)&outp[(size_t)m * DIMX + c] = o;
                } else {
                    const int bb = m >> 10, ii = m & 1023;
                    int col0 = c;
                    __nv_bfloat16 *dh, *dl;
                    if (c < INNER) {
                        dh = g_qh; dl = g_ql;
                        v0 *= qscale; v1 *= qscale;
                    } else if (c < 2 * INNER) {
                        dh = g_kh; dl = g_kl; col0 = c - INNER;
                    } else {
                        dh = g_vh; dl = g_vl; col0 = c - 2 * INNER;
                    }
                    const int hh = col0 >> 6, dd = col0 & 63;
                    uint32_t hi, lo;
                    split2(v0, v1, hi, lo);
                    size_t o = (((size_t)bb * HEADS + hh) * N_SEQ + ii) * DH + dd;
                    *(uint32_t*)&dh[o] = hi;
                    *(uint32_t*)&dl[o] = lo;
                }
            }
        }
    }
}

// ---------------------------------------------------------------------------
// Tensor-core flash attention, bf16-split, S2 ring buffer.
// Ring: slot(dist) = (dist - i0 + 63) & 127 ; each j-tile computes only the
// 64 NEW columns (windows slide by 64). Warp-private rows -> __syncwarp only.
// ---------------------------------------------------------------------------
#define A_QH 0
#define A_QL 8192
#define A_KH 16384
#define A_KL 24576
#define A_VH 32768
#define A_VL 40960
#define A_RH 49152                    // 64 rows x 128B = 8192
#define A_RL 57344
#define A_S2 65536
#define S2S  132
#define ATT_SMEM (A_S2 + 64 * S2S * 4)   // 99328

__global__ __launch_bounds__(128, 2) void attn_mma(void)
{
    extern __shared__ __align__(128) char smem[];
    const uint32_t sb = smem_u32(smem);
    float* s2p = (float*)(smem + A_S2);

    const int tid  = threadIdx.x;
    const int lane = tid & 31, warp = tid >> 5;
    const int wbase = warp * 16;
    const int i0 = blockIdx.x * 64;
    const int h  = blockIdx.y;
    const int b  = blockIdx.z;
    const size_t hb = ((size_t)b * HEADS + h) * N_SEQ * DH;

    // ---- load Q (hi/lo) ----
#pragma unroll
    for (int i = 0; i < 4; i++) {
        int id = tid + i * 128;
        int r = id >> 3, c = id & 7;
        uint32_t d = sw128(r * 128 + c * 16);
        cp16(sb + A_QH + d, g_qh + hb + (size_t)(i0 + r) * DH + c * 8);
        cp16(sb + A_QL + d, g_ql + hb + (size_t)(i0 + r) * DH + c * 8);
    }
    asm volatile("cp.async.commit_group;" ::: "memory");
    asm volatile("cp.async.wait_group 0;" ::: "memory");
    __syncthreads();

    uint32_t qa[2][4][4];
#pragma unroll
    for (int ks = 0; ks < 4; ks++) {
        uint32_t off = sw128((wbase + (lane & 15)) * 128 + ks * 32 + (lane >> 4) * 16);
        ldm_x4(sb + A_QH + off, qa[0][ks][0], qa[0][ks][1], qa[0][ks][2], qa[0][ks][3]);
        ldm_x4(sb + A_QL + off, qa[1][ks][0], qa[1][ks][1], qa[1][ks][2], qa[1][ks][3]);
    }

    auto stage_rel = [&](int Dbase) {
#pragma unroll
        for (int i = 0; i < 4; i++) {
            int id = tid + i * 128;
            int r = id >> 3, c = id & 7;
            int dist = min(max(Dbase + r, -MAXPOS), MAXPOS) + MAXPOS;
            uint32_t d = sw128(r * 128 + c * 16);
            cp16(sb + A_RH + d, g_relh + (size_t)dist * DH + c * 8);
            cp16(sb + A_RL + d, g_rell + (size_t)dist * DH + c * 8);
        }
    };

    auto s2_group = [&](int baseSlot) {
        float s2[8][4];
#pragma unroll
        for (int nt = 0; nt < 8; nt++)
#pragma unroll
            for (int e = 0; e < 4; e++) s2[nt][e] = 0.f;
#pragma unroll
        for (int ks = 0; ks < 4; ks++) {
            uint32_t rbh[4][4], rbl[4][4];
#pragma unroll
            for (int g = 0; g < 4; g++) {
                uint32_t off = sw128((g * 16 + (lane & 15)) * 128
                                     + ks * 32 + (lane >> 4) * 16);
                ldm_x4(sb + A_RH + off, rbh[g][0], rbh[g][1], rbh[g][2], rbh[g][3]);
                ldm_x4(sb + A_RL + off, rbl[g][0], rbl[g][1], rbl[g][2], rbl[g][3]);
            }
#pragma unroll
            for (int nt = 0; nt < 8; nt++) {
                const int p = nt >> 1, s_ = nt & 1;
                mma16816(s2[nt], qa[0][ks], rbh[p][s_], rbh[p][s_ + 2]);
                mma16816(s2[nt], qa[0][ks], rbl[p][s_], rbl[p][s_ + 2]);
                mma16816(s2[nt], qa[1][ks], rbh[p][s_], rbh[p][s_ + 2]);
            }
        }
        const int rl0 = wbase + (lane >> 2);
#pragma unroll
        for (int nt = 0; nt < 8; nt++) {
            const int col = baseSlot + nt * 8 + 2 * (lane & 3);
            *(float2*)&s2p[rl0 * S2S + col]       = {s2[nt][0], s2[nt][1]};
            *(float2*)&s2p[(rl0 + 8) * S2S + col] = {s2[nt][2], s2[nt][3]};
        }
    };

    // pre-group: slots 64..127 = dists [i0+1, i0+64]
    stage_rel(i0 + 1);
    asm volatile("cp.async.commit_group;" ::: "memory");
    asm volatile("cp.async.wait_group 0;" ::: "memory");
    __syncthreads();
    s2_group(64);

    float o[8][4];
#pragma unroll
    for (int nt = 0; nt < 8; nt++)
#pragma unroll
        for (int e = 0; e < 4; e++) o[nt][e] = 0.f;
    float m2[2] = {-1e30f, -1e30f}, l2[2] = {0.f, 0.f};
    bool clipgrp[2] = {false, false};

    for (int jt = 0; jt < 16; jt++) {
        const int j0 = jt * 64;
        __syncthreads();   // prior tile's SMEM reads complete

        // group A: K hi/lo + (maybe) new rel rows
#pragma unroll
        for (int i = 0; i < 4; i++) {
            int id = tid + i * 128;
            int r = id >> 3, c = id & 7;
            uint32_t d = sw128(r * 128 + c * 16);
            size_t g = hb + (size_t)(j0 + r) * DH + c * 8;
            cp16(sb + A_KH + d, g_kh + g);
            cp16(sb + A_KL + d, g_kl + g);
        }
        const int Dbase = i0 - j0 - 63;
        const bool fullclip = (Dbase + 63 <= -MAXPOS);
        const bool skip = fullclip && clipgrp[jt & 1];
        if (!skip) stage_rel(Dbase);
        asm volatile("cp.async.commit_group;" ::: "memory");
        // group B: V hi/lo
#pragma unroll
        for (int i = 0; i < 4; i++) {
            int id = tid + i * 128;
            int r = id >> 3, c = id & 7;
            uint32_t d = sw128(r * 128 + c * 16);
            size_t g = hb + (size_t)(j0 + r) * DH + c * 8;
            cp16(sb + A_VH + d, g_vh + g);
            cp16(sb + A_VL + d, g_vl + g);
        }
        asm volatile("cp.async.commit_group;" ::: "memory");

        asm volatile("cp.async.wait_group 1;" ::: "memory");
        __syncthreads();

        // ---- new S2 columns (64) ----
        if (!skip) s2_group((jt & 1) ? 64 : 0);
        clipgrp[jt & 1] = fullclip;
        __syncwarp();

        // ---- S1 = Q @ K^T (64x64) ----
        float s[8][4];
#pragma unroll
        for (int nt = 0; nt < 8; nt++)
#pragma unroll
            for (int e = 0; e < 4; e++) s[nt][e] = 0.f;
#pragma unroll
        for (int ks = 0; ks < 4; ks++) {
            uint32_t kbh[4][4], kbl[4][4];
#pragma unroll
            for (int g = 0; g < 4; g++) {
                uint32_t off = sw128((g * 16 + (lane & 15)) * 128
                                     + ks * 32 + (lane >> 4) * 16);
                ldm_x4(sb + A_KH + off, kbh[g][0], kbh[g][1], kbh[g][2], kbh[g][3]);
                ldm_x4(sb + A_KL + off, kbl[g][0], kbl[g][1], kbl[g][2], kbl[g][3]);
            }
#pragma unroll
            for (int nt = 0; nt < 8; nt++) {
                const int p = nt >> 1, s_ = nt & 1;
                mma16816(s[nt], qa[0][ks], kbh[p][s_], kbh[p][s_ + 2]);
                mma16816(s[nt], qa[0][ks], kbl[p][s_], kbl[p][s_ + 2]);
                mma16816(s[nt], qa[1][ks], kbh[p][s_], kbh[p][s_ + 2]);
            }
        }

        // ---- gather rel bias from ring, online softmax ----
        const int rl0 = wbase + (lane >> 2);
#pragma unroll
        for (int nt = 0; nt < 8; nt++)
#pragma unroll
            for (int e = 0; e < 4; e++) {
                const int rr = rl0 + 8 * (e >> 1);
                const int jj = nt * 8 + 2 * (lane & 3) + (e & 1);
                const int slot = (rr - jj + 63 - j0) & 127;
                s[nt][e] += s2p[rr * S2S + slot];
            }

        float mx[2] = {-1e30f, -1e30f};
#pragma unroll
        for (int nt = 0; nt < 8; nt++)
#pragma unroll
            for (int e = 0; e < 4; e++)
                mx[e >> 1] = fmaxf(mx[e >> 1], s[nt][e]);
#pragma unroll
        for (int h2 = 0; h2 < 2; h2++) {
            mx[h2] = fmaxf(mx[h2], __shfl_xor_sync(0xffffffffu, mx[h2], 1));
            mx[h2] = fmaxf(mx[h2], __shfl_xor_sync(0xffffffffu, mx[h2], 2));
        }
        float al2[2];
#pragma unroll
        for (int h2 = 0; h2 < 2; h2++) {
            float mnew = fmaxf(m2[h2], mx[h2]);
            al2[h2] = __expf(m2[h2] - mnew);
            m2[h2] = mnew;
        }
        float sum[2] = {0.f, 0.f};
#pragma unroll
        for (int nt = 0; nt < 8; nt++)
#pragma unroll
            for (int e = 0; e < 4; e++) {
                float p = __expf(s[nt][e] - m2[e >> 1]);
                s[nt][e] = p;
                sum[e >> 1] += p;
            }
#pragma unroll
        for (int h2 = 0; h2 < 2; h2++) {
            sum[h2] += __shfl_xor_sync(0xffffffffu, sum[h2], 1);
            sum[h2] += __shfl_xor_sync(0xffffffffu, sum[h2], 2);
            l2[h2] = l2[h2] * al2[h2] + sum[h2];
        }
#pragma unroll
        for (int nt = 0; nt < 8; nt++) {
            o[nt][0] *= al2[0]; o[nt][1] *= al2[0];
            o[nt][2] *= al2[1]; o[nt][3] *= al2[1];
        }

        // ---- P c-frag -> a-frag (bf16 hi/lo) ----
        uint32_t pah[4][4], pal[4][4];
#pragma unroll
        for (int ks = 0; ks < 4; ks++) {
            split2(s[2*ks][0],   s[2*ks][1],   pah[ks][0], pal[ks][0]);
            split2(s[2*ks][2],   s[2*ks][3],   pah[ks][1], pal[ks][1]);
            split2(s[2*ks+1][0], s[2*ks+1][1], pah[ks][2], pal[ks][2]);
            split2(s[2*ks+1][2], s[2*ks+1][3], pah[ks][3], pal[ks][3]);
        }

        asm volatile("cp.async.wait_group 0;" ::: "memory");
        __syncthreads();

        // ---- O += P @ V ----
#pragma unroll
        for (int ks = 0; ks < 4; ks++) {
            uint32_t vbh[4][4], vbl[4][4];
            const int jr = ks * 16 + (lane & 7) + ((lane >> 3) & 1) * 8;
#pragma unroll
            for (int dp = 0; dp < 4; dp++) {
                uint32_t off = sw128(jr * 128 + dp * 32 + (lane >> 4) * 16);
                ldm_x4t(sb + A_VH + off, vbh[dp][0], vbh[dp][1], vbh[dp][2], vbh[dp][3]);
                ldm_x4t(sb + A_VL + off, vbl[dp][0], vbl[dp][1], vbl[dp][2], vbl[dp][3]);
            }
#pragma unroll
            for (int nt = 0; nt < 8; nt++) {
                const int dp = nt >> 1, s_ = (nt & 1) * 2;
                mma16816(o[nt], pah[ks], vbh[dp][s_], vbh[dp][s_ + 1]);
                mma16816(o[nt], pah[ks], vbl[dp][s_], vbl[dp][s_ + 1]);
                mma16816(o[nt], pal[ks], vbh[dp][s_], vbh[dp][s_ + 1]);
            }
        }
    }

    // ---- epilogue ----
    const float inv0 = 1.f / l2[0], inv1 = 1.f / l2[1];
    const int row0 = i0 + wbase + (lane >> 2);
#pragma unroll
    for (int nt = 0; nt < 8; nt++) {
        const int d = nt * 8 + 2 * (lane & 3);
        uint32_t hi, lo;
        size_t base0 = ((size_t)b * N_SEQ + row0) * INNER + h * DH + d;
        split2(o[nt][0] * inv0, o[nt][1] * inv0, hi, lo);
        *(uint32_t*)&g_oh[base0] = hi;
        *(uint32_t*)&g_ol[base0] = lo;
        size_t base1 = ((size_t)b * N_SEQ + row0 + 8) * INNER + h * DH + d;
        split2(o[nt][2] * inv1, o[nt][3] * inv1, hi, lo);
        *(uint32_t*)&g_oh[base1] = hi;
        *(uint32_t*)&g_ol[base1] = lo;
    }
}

// ---------------------------------------------------------------------------
extern "C" void kernel_launch(void* const* d_in, const int* in_sizes, int n_in,
                              void* d_out, int out_size)
{
    (void)in_sizes; (void)n_in; (void)out_size;
    const float* x   = (const float*)d_in[0];
    const float* Wq  = (const float*)d_in[1];
    const float* Wkv = (const float*)d_in[2];
    const float* Wo  = (const float*)d_in[3];
    const float* bo  = (const float*)d_in[4];
    const float* rel = (const float*)d_in[5];
    float* out = (float*)d_out;

    const int GEMM_SMEM = 2 * STAGE_B;
    cudaFuncSetAttribute(gemm_mma, cudaFuncAttributeMaxDynamicSharedMemorySize, GEMM_SMEM);
    cudaFuncSetAttribute(attn_mma, cudaFuncAttributeMaxDynamicSharedMemorySize, ATT_SMEM);

    split_xrel<<<(NX4 + NR4 + 255) / 256, 256>>>(x, rel);
    tsplit_all<<<4096, 256>>>(Wq, Wkv, Wo);

    // fused q/k/v projection: x @ [Wq|Wkv]
    gemm_mma<<<dim3(3 * INNER / 128, (B_DIM * N_SEQ) / 128), 256, GEMM_SMEM>>>(0, nullptr, nullptr);

    // fused attention (tensor cores, S2 ring)
    attn_mma<<<dim3(16, HEADS, B_DIM), 128, ATT_SMEM>>>();

    // out = o @ Wo + bo
    gemm_mma<<<dim3(DIMX / 128, (B_DIM * N_SEQ) / 128), 256, GEMM_SMEM>>>(2, bo, out);
}

// round 6
// speedup vs baseline: 3.1226x; 1.0700x over previous
#include <cuda_runtime.h>
#include <cuda_bf16.h>
#include <cuda_fp16.h>
#include <cstdint>

#define B_DIM  2
#define N_SEQ  1024
#define DIMX   1024
#define HEADS  16
#define DH     64
#define INNER  1024
#define MAXPOS 512

// ------------------------- device scratch (no allocs) -----------------------
__device__ __align__(16) __nv_bfloat16 g_xh[(size_t)B_DIM*N_SEQ*DIMX];
__device__ __align__(16) __nv_bfloat16 g_xl[(size_t)B_DIM*N_SEQ*DIMX];
__device__ __align__(16) __nv_bfloat16 g_wph[(size_t)3*DIMX*INNER];
__device__ __align__(16) __nv_bfloat16 g_wpl[(size_t)3*DIMX*INNER];
__device__ __align__(16) __nv_bfloat16 g_woh[(size_t)INNER*DIMX];
__device__ __align__(16) __nv_bfloat16 g_wol[(size_t)INNER*DIMX];
__device__ __align__(16) __nv_bfloat16 g_oh[(size_t)B_DIM*N_SEQ*INNER];
__device__ __align__(16) __nv_bfloat16 g_ol[(size_t)B_DIM*N_SEQ*INNER];
// attention operands in fp16: q single (scaled), k/v/rel split hi+lo
__device__ __align__(16) __half g_qh[(size_t)B_DIM*HEADS*N_SEQ*DH];
__device__ __align__(16) __half g_kh[(size_t)B_DIM*HEADS*N_SEQ*DH];
__device__ __align__(16) __half g_kl[(size_t)B_DIM*HEADS*N_SEQ*DH];
__device__ __align__(16) __half g_vh[(size_t)B_DIM*HEADS*N_SEQ*DH];
__device__ __align__(16) __half g_vl[(size_t)B_DIM*HEADS*N_SEQ*DH];
__device__ __align__(16) __half g_relh[(size_t)(2*MAXPOS+1)*DH];
__device__ __align__(16) __half g_rell[(size_t)(2*MAXPOS+1)*DH];

// ------------------------------- helpers ------------------------------------
__device__ __forceinline__ uint32_t smem_u32(const void* p) {
    uint32_t a;
    asm("{ .reg .u64 t; cvta.to.shared.u64 t, %1; cvt.u32.u64 %0, t; }"
        : "=r"(a) : "l"(p));
    return a;
}
__device__ __forceinline__ void cp16(uint32_t saddr, const void* gaddr) {
    asm volatile("cp.async.cg.shared.global [%0], [%1], 16;"
                 :: "r"(saddr), "l"(gaddr) : "memory");
}
__device__ __forceinline__ void ldm_x4(uint32_t a, uint32_t& r0, uint32_t& r1,
                                       uint32_t& r2, uint32_t& r3) {
    asm volatile("ldmatrix.sync.aligned.m8n8.x4.shared.b16 {%0,%1,%2,%3}, [%4];"
                 : "=r"(r0), "=r"(r1), "=r"(r2), "=r"(r3) : "r"(a));
}
__device__ __forceinline__ void ldm_x4t(uint32_t a, uint32_t& r0, uint32_t& r1,
                                        uint32_t& r2, uint32_t& r3) {
    asm volatile("ldmatrix.sync.aligned.m8n8.x4.trans.shared.b16 {%0,%1,%2,%3}, [%4];"
                 : "=r"(r0), "=r"(r1), "=r"(r2), "=r"(r3) : "r"(a));
}
// bf16 mma (GEMMs)
__device__ __forceinline__ void mma16816(float* c, const uint32_t* a,
                                         uint32_t b0, uint32_t b1) {
    asm volatile(
        "mma.sync.aligned.m16n8k16.row.col.f32.bf16.bf16.f32 "
        "{%0,%1,%2,%3}, {%4,%5,%6,%7}, {%8,%9}, {%0,%1,%2,%3};"
        : "+f"(c[0]), "+f"(c[1]), "+f"(c[2]), "+f"(c[3])
        : "r"(a[0]), "r"(a[1]), "r"(a[2]), "r"(a[3]), "r"(b0), "r"(b1));
}
// fp16 mma (attention)
__device__ __forceinline__ void mma16816h(float* c, const uint32_t* a,
                                          uint32_t b0, uint32_t b1) {
    asm volatile(
        "mma.sync.aligned.m16n8k16.row.col.f32.f16.f16.f32 "
        "{%0,%1,%2,%3}, {%4,%5,%6,%7}, {%8,%9}, {%0,%1,%2,%3};"
        : "+f"(c[0]), "+f"(c[1]), "+f"(c[2]), "+f"(c[3])
        : "r"(a[0]), "r"(a[1]), "r"(a[2]), "r"(a[3]), "r"(b0), "r"(b1));
}
__device__ __forceinline__ uint32_t sw128(uint32_t off) {
    return off ^ ((off >> 3) & 0x70);
}
__device__ __forceinline__ void split2(float a, float b, uint32_t& hi, uint32_t& lo) {
    __nv_bfloat162 h, l;
    h.x = __float2bfloat16(a); h.y = __float2bfloat16(b);
    l.x = __float2bfloat16(a - __bfloat162float(h.x));
    l.y = __float2bfloat16(b - __bfloat162float(h.y));
    hi = *(uint32_t*)&h; lo = *(uint32_t*)&l;
}
__device__ __forceinline__ uint32_t pack_h2(float a, float b) {
    __half2 h = __floats2half2_rn(a, b);
    return *(uint32_t*)&h;
}
__device__ __forceinline__ void split2h(float a, float b, uint32_t& hi, uint32_t& lo) {
    __half2 h = __floats2half2_rn(a, b);
    float ra = a - __half2float(__low2half(h));
    float rb = b - __half2float(__high2half(h));
    __half2 l = __floats2half2_rn(ra, rb);
    hi = *(uint32_t*)&h; lo = *(uint32_t*)&l;
}

// ------------------------- conversion kernels -------------------------------
#define NX4 (B_DIM * N_SEQ * DIMX / 4)          // 524288
#define NR4 ((2 * MAXPOS + 1) * DH / 4)         // 16400

__global__ __launch_bounds__(256) void split_xrel(const float* __restrict__ x,
                                                  const float* __restrict__ rel)
{
    int i = blockIdx.x * blockDim.x + threadIdx.x;
    if (i >= NX4 + NR4) return;
    if (i < NX4) {
        float4 v = ((const float4*)x)[i];
        uint32_t h0, l0, h1, l1;
        split2(v.x, v.y, h0, l0);
        split2(v.z, v.w, h1, l1);
        ((uint32_t*)g_xh)[2*i] = h0; ((uint32_t*)g_xh)[2*i+1] = h1;
        ((uint32_t*)g_xl)[2*i] = l0; ((uint32_t*)g_xl)[2*i+1] = l1;
    } else {
        int j = i - NX4;
        float4 v = ((const float4*)rel)[j];
        uint32_t h0, l0, h1, l1;
        split2h(v.x, v.y, h0, l0);
        split2h(v.z, v.w, h1, l1);
        ((uint32_t*)g_relh)[2*j] = h0; ((uint32_t*)g_relh)[2*j+1] = h1;
        ((uint32_t*)g_rell)[2*j] = l0; ((uint32_t*)g_rell)[2*j+1] = l1;
    }
}

// transpose + split all weights in one launch.
__global__ __launch_bounds__(256) void tsplit_all(const float* __restrict__ Wq,
                                                  const float* __restrict__ Wkv,
                                                  const float* __restrict__ Wo)
{
    __shared__ float t[32][33];
    const int bid = blockIdx.x;
    const float* W; __nv_bfloat16 *th, *tl;
    int N, kt, ntile, rowoff;
    if (bid < 1024)      { W = Wq;  N = 1024; kt = bid >> 5; ntile = bid & 31;
                           th = g_wph; tl = g_wpl; rowoff = 0; }
    else if (bid < 3072) { int l = bid - 1024; W = Wkv; N = 2048;
                           kt = l >> 6; ntile = l & 63;
                           th = g_wph; tl = g_wpl; rowoff = 1024; }
    else                 { int l = bid - 3072; W = Wo; N = 1024;
                           kt = l >> 5; ntile = l & 31;
                           th = g_woh; tl = g_wol; rowoff = 0; }
    const int n0 = ntile * 32, k0 = kt * 32;
    const int tx = threadIdx.x & 31, ty = threadIdx.x >> 5;
#pragma unroll
    for (int r = 0; r < 4; r++)
        t[ty + 8*r][tx] = W[(size_t)(k0 + ty + 8*r) * N + n0 + tx];
    __syncthreads();
#pragma unroll
    for (int r = 0; r < 4; r++) {
        float v = t[tx][ty + 8*r];
        __nv_bfloat16 h = __float2bfloat16(v);
        __nv_bfloat16 l = __float2bfloat16(v - __bfloat162float(h));
        size_t o = (size_t)(rowoff + n0 + ty + 8*r) * 1024 + k0 + tx;
        th[o] = h; tl[o] = l;
    }
}

// ------------------------- mma.sync bf16-split GEMM -------------------------
#define BK 32
#define RS 40
#define TILE_B (128 * RS * 2)
#define STAGE_B (4 * TILE_B)

__global__ __launch_bounds__(256, 1) void gemm_mma(int mode,
                                                   const float* __restrict__ bias,
                                                   float* __restrict__ outp)
{
    extern __shared__ __align__(128) char smem[];
    const uint32_t sb = smem_u32(smem);
    const int tid = threadIdx.x;
    const int wid = tid >> 5, lane = tid & 31;
    const int warp_m = wid & 1, warp_n = wid >> 1;
    const int m0 = blockIdx.y * 128, n0 = blockIdx.x * 128;

    const __nv_bfloat16 *Ah, *Al, *Bh, *Bl;
    if (mode == 0) { Ah = g_xh; Al = g_xl; Bh = g_wph; Bl = g_wpl; }
    else           { Ah = g_oh; Al = g_ol; Bh = g_woh; Bl = g_wol; }

    float acc[4][4][4];
#pragma unroll
    for (int i = 0; i < 4; i++)
#pragma unroll
        for (int j = 0; j < 4; j++)
#pragma unroll
            for (int t = 0; t < 4; t++) acc[i][j][t] = 0.f;

    const int nkt = DIMX / BK;

    auto issue_stage = [&](int kt) {
        const int k0 = kt * BK;
        const uint32_t st = sb + (kt & 1) * STAGE_B;
#pragma unroll
        for (int i = 0; i < 8; i++) {
            int id = tid + i * 256;
            int tile = id >> 9, rem = id & 511;
            int r = rem >> 2, cc = rem & 3;
            uint32_t sa = st + tile * TILE_B + r * (RS * 2) + cc * 16;
            const __nv_bfloat16* src;
            size_t goff;
            if (tile == 0)      { src = Ah; goff = (size_t)(m0 + r) * DIMX; }
            else if (tile == 1) { src = Al; goff = (size_t)(m0 + r) * DIMX; }
            else if (tile == 2) { src = Bh; goff = (size_t)(n0 + r) * DIMX; }
            else                { src = Bl; goff = (size_t)(n0 + r) * DIMX; }
            cp16(sa, src + goff + k0 + cc * 8);
        }
        asm volatile("cp.async.commit_group;" ::: "memory");
    };

    issue_stage(0);

    const int lr = lane & 15;
    const int lc = (lane >> 4) * 8;

    for (int kt = 0; kt < nkt; kt++) {
        if (kt + 1 < nkt) {
            issue_stage(kt + 1);
            asm volatile("cp.async.wait_group 1;" ::: "memory");
        } else {
            asm volatile("cp.async.wait_group 0;" ::: "memory");
        }
        __syncthreads();

        const uint32_t st = sb + (kt & 1) * STAGE_B;
        const uint32_t aBaseH = st + 0 * TILE_B + (warp_m * 64 + lr) * (RS * 2);
        const uint32_t aBaseL = st + 1 * TILE_B + (warp_m * 64 + lr) * (RS * 2);
        const uint32_t bBaseH = st + 2 * TILE_B + (warp_n * 32 + lr) * (RS * 2);
        const uint32_t bBaseL = st + 3 * TILE_B + (warp_n * 32 + lr) * (RS * 2);

#pragma unroll
        for (int ks = 0; ks < BK; ks += 16) {
            uint32_t ah[4][4], al[4][4], bh[2][4], bl[2][4];
            const uint32_t koff = (ks + lc) * 2;
#pragma unroll
            for (int mt = 0; mt < 4; mt++) {
                ldm_x4(aBaseH + mt * 16 * (RS * 2) + koff,
                       ah[mt][0], ah[mt][1], ah[mt][2], ah[mt][3]);
                ldm_x4(aBaseL + mt * 16 * (RS * 2) + koff,
                       al[mt][0], al[mt][1], al[mt][2], al[mt][3]);
            }
#pragma unroll
            for (int p = 0; p < 2; p++) {
                ldm_x4(bBaseH + p * 16 * (RS * 2) + koff,
                       bh[p][0], bh[p][1], bh[p][2], bh[p][3]);
                ldm_x4(bBaseL + p * 16 * (RS * 2) + koff,
                       bl[p][0], bl[p][1], bl[p][2], bl[p][3]);
            }
#pragma unroll
            for (int mt = 0; mt < 4; mt++)
#pragma unroll
                for (int nt = 0; nt < 4; nt++) {
                    const int p = nt >> 1, s = nt & 1;
                    mma16816(acc[mt][nt], ah[mt], bh[p][s], bh[p][s + 2]);
                    mma16816(acc[mt][nt], ah[mt], bl[p][s], bl[p][s + 2]);
                    mma16816(acc[mt][nt], al[mt], bh[p][s], bh[p][s + 2]);
                }
        }
        __syncthreads();
    }

    const float qscale = 0.125f;
#pragma unroll
    for (int mt = 0; mt < 4; mt++) {
#pragma unroll
        for (int half = 0; half < 2; half++) {
            const int m = m0 + warp_m * 64 + mt * 16 + (lane >> 2) + half * 8;
#pragma unroll
            for (int nt = 0; nt < 4; nt++) {
                const int c = n0 + warp_n * 32 + nt * 8 + 2 * (lane & 3);
                float v0 = acc[mt][nt][half * 2 + 0];
                float v1 = acc[mt][nt][half * 2 + 1];
                if (mode != 0) {
                    float2 o = {v0 + bias[c], v1 + bias[c + 1]};
                    *(float2*)&outp[(size_t)m * DIMX + c] = o;
                } else {
                    const int bb = m >> 10, ii = m & 1023;
                    if (c < INNER) {               // q: single fp16, scaled
                        const int hh = c >> 6, dd = c & 63;
                        size_t o = (((size_t)bb * HEADS + hh) * N_SEQ + ii) * DH + dd;
                        *(uint32_t*)&g_qh[o] = pack_h2(v0 * qscale, v1 * qscale);
                    } else {                       // k/v: fp16 hi+lo
                        int col0 = c - INNER;
                        __half *dh, *dl;
                        if (col0 < INNER) { dh = g_kh; dl = g_kl; }
                        else { dh = g_vh; dl = g_vl; col0 -= INNER; }
                        const int hh = col0 >> 6, dd = col0 & 63;
                        uint32_t hi, lo;
                        split2h(v0, v1, hi, lo);
                        size_t o = (((size_t)bb * HEADS + hh) * N_SEQ + ii) * DH + dd;
                        *(uint32_t*)&dh[o] = hi;
                        *(uint32_t*)&dl[o] = lo;
                    }
                }
            }
        }
    }
}

// ---------------------------------------------------------------------------
// Tensor-core flash attention, fp16 2-pass (a single, b hi+lo), S2 ring.
// ---------------------------------------------------------------------------
#define A_QH 0
#define A_KH 8192
#define A_KL 16384
#define A_VH 24576
#define A_VL 32768
#define A_RH 40960
#define A_RL 49152
#define A_S2 57344
#define S2S  132
#define ATT_SMEM (A_S2 + 64 * S2S * 4)   // 91136

__global__ __launch_bounds__(128, 2) void attn_mma(void)
{
    extern __shared__ __align__(128) char smem[];
    const uint32_t sb = smem_u32(smem);
    float* s2p = (float*)(smem + A_S2);

    const int tid  = threadIdx.x;
    const int lane = tid & 31, warp = tid >> 5;
    const int wbase = warp * 16;
    const int i0 = blockIdx.x * 64;
    const int h  = blockIdx.y;
    const int b  = blockIdx.z;
    const size_t hb = ((size_t)b * HEADS + h) * N_SEQ * DH;

    // ---- load Q (single fp16 plane) ----
#pragma unroll
    for (int i = 0; i < 4; i++) {
        int id = tid + i * 128;
        int r = id >> 3, c = id & 7;
        uint32_t d = sw128(r * 128 + c * 16);
        cp16(sb + A_QH + d, g_qh + hb + (size_t)(i0 + r) * DH + c * 8);
    }
    asm volatile("cp.async.commit_group;" ::: "memory");
    asm volatile("cp.async.wait_group 0;" ::: "memory");
    __syncthreads();

    uint32_t qa[4][4];
#pragma unroll
    for (int ks = 0; ks < 4; ks++) {
        uint32_t off = sw128((wbase + (lane & 15)) * 128 + ks * 32 + (lane >> 4) * 16);
        ldm_x4(sb + A_QH + off, qa[ks][0], qa[ks][1], qa[ks][2], qa[ks][3]);
    }

    auto stage_rel = [&](int Dbase) {
#pragma unroll
        for (int i = 0; i < 4; i++) {
            int id = tid + i * 128;
            int r = id >> 3, c = id & 7;
            int dist = min(max(Dbase + r, -MAXPOS), MAXPOS) + MAXPOS;
            uint32_t d = sw128(r * 128 + c * 16);
            cp16(sb + A_RH + d, g_relh + (size_t)dist * DH + c * 8);
            cp16(sb + A_RL + d, g_rell + (size_t)dist * DH + c * 8);
        }
    };

    auto s2_group = [&](int baseSlot) {
        float s2[8][4];
#pragma unroll
        for (int nt = 0; nt < 8; nt++)
#pragma unroll
            for (int e = 0; e < 4; e++) s2[nt][e] = 0.f;
#pragma unroll
        for (int ks = 0; ks < 4; ks++) {
            uint32_t rbh[4][4], rbl[4][4];
#pragma unroll
            for (int g = 0; g < 4; g++) {
                uint32_t off = sw128((g * 16 + (lane & 15)) * 128
                                     + ks * 32 + (lane >> 4) * 16);
                ldm_x4(sb + A_RH + off, rbh[g][0], rbh[g][1], rbh[g][2], rbh[g][3]);
                ldm_x4(sb + A_RL + off, rbl[g][0], rbl[g][1], rbl[g][2], rbl[g][3]);
            }
#pragma unroll
            for (int nt = 0; nt < 8; nt++) {
                const int p = nt >> 1, s_ = nt & 1;
                mma16816h(s2[nt], qa[ks], rbh[p][s_], rbh[p][s_ + 2]);
                mma16816h(s2[nt], qa[ks], rbl[p][s_], rbl[p][s_ + 2]);
            }
        }
        const int rl0 = wbase + (lane >> 2);
#pragma unroll
        for (int nt = 0; nt < 8; nt++) {
            const int col = baseSlot + nt * 8 + 2 * (lane & 3);
            *(float2*)&s2p[rl0 * S2S + col]       = {s2[nt][0], s2[nt][1]};
            *(float2*)&s2p[(rl0 + 8) * S2S + col] = {s2[nt][2], s2[nt][3]};
        }
    };

    // pre-group: slots 64..127 = dists [i0+1, i0+64]
    stage_rel(i0 + 1);
    asm volatile("cp.async.commit_group;" ::: "memory");
    asm volatile("cp.async.wait_group 0;" ::: "memory");
    __syncthreads();
    s2_group(64);

    float o[8][4];
#pragma unroll
    for (int nt = 0; nt < 8; nt++)
#pragma unroll
        for (int e = 0; e < 4; e++) o[nt][e] = 0.f;
    float m2[2] = {-1e30f, -1e30f}, l2[2] = {0.f, 0.f};
    bool clipgrp[2] = {false, false};

    for (int jt = 0; jt < 16; jt++) {
        const int j0 = jt * 64;
        __syncthreads();

        // group A: K hi/lo + (maybe) new rel rows
#pragma unroll
        for (int i = 0; i < 4; i++) {
            int id = tid + i * 128;
            int r = id >> 3, c = id & 7;
            uint32_t d = sw128(r * 128 + c * 16);
            size_t g = hb + (size_t)(j0 + r) * DH + c * 8;
            cp16(sb + A_KH + d, g_kh + g);
            cp16(sb + A_KL + d, g_kl + g);
        }
        const int Dbase = i0 - j0 - 63;
        const bool fullclip = (Dbase + 63 <= -MAXPOS);
        const bool skip = fullclip && clipgrp[jt & 1];
        if (!skip) stage_rel(Dbase);
        asm volatile("cp.async.commit_group;" ::: "memory");
        // group B: V hi/lo
#pragma unroll
        for (int i = 0; i < 4; i++) {
            int id = tid + i * 128;
            int r = id >> 3, c = id & 7;
            uint32_t d = sw128(r * 128 + c * 16);
            size_t g = hb + (size_t)(j0 + r) * DH + c * 8;
            cp16(sb + A_VH + d, g_vh + g);
            cp16(sb + A_VL + d, g_vl + g);
        }
        asm volatile("cp.async.commit_group;" ::: "memory");

        asm volatile("cp.async.wait_group 1;" ::: "memory");
        __syncthreads();

        // ---- new S2 columns (64) ----
        if (!skip) s2_group((jt & 1) ? 64 : 0);
        clipgrp[jt & 1] = fullclip;
        __syncwarp();

        // ---- S1 = Q @ K^T (64x64) ----
        float s[8][4];
#pragma unroll
        for (int nt = 0; nt < 8; nt++)
#pragma unroll
            for (int e = 0; e < 4; e++) s[nt][e] = 0.f;
#pragma unroll
        for (int ks = 0; ks < 4; ks++) {
            uint32_t kbh[4][4], kbl[4][4];
#pragma unroll
            for (int g = 0; g < 4; g++) {
                uint32_t off = sw128((g * 16 + (lane & 15)) * 128
                                     + ks * 32 + (lane >> 4) * 16);
                ldm_x4(sb + A_KH + off, kbh[g][0], kbh[g][1], kbh[g][2], kbh[g][3]);
                ldm_x4(sb + A_KL + off, kbl[g][0], kbl[g][1], kbl[g][2], kbl[g][3]);
            }
#pragma unroll
            for (int nt = 0; nt < 8; nt++) {
                const int p = nt >> 1, s_ = nt & 1;
                mma16816h(s[nt], qa[ks], kbh[p][s_], kbh[p][s_ + 2]);
                mma16816h(s[nt], qa[ks], kbl[p][s_], kbl[p][s_ + 2]);
            }
        }

        // ---- gather rel bias from ring, online softmax ----
        const int rl0 = wbase + (lane >> 2);
#pragma unroll
        for (int nt = 0; nt < 8; nt++)
#pragma unroll
            for (int e = 0; e < 4; e++) {
                const int rr = rl0 + 8 * (e >> 1);
                const int jj = nt * 8 + 2 * (lane & 3) + (e & 1);
                const int slot = (rr - jj + 63 - j0) & 127;
                s[nt][e] += s2p[rr * S2S + slot];
            }

        float mx[2] = {-1e30f, -1e30f};
#pragma unroll
        for (int nt = 0; nt < 8; nt++)
#pragma unroll
            for (int e = 0; e < 4; e++)
                mx[e >> 1] = fmaxf(mx[e >> 1], s[nt][e]);
#pragma unroll
        for (int h2 = 0; h2 < 2; h2++) {
            mx[h2] = fmaxf(mx[h2], __shfl_xor_sync(0xffffffffu, mx[h2], 1));
            mx[h2] = fmaxf(mx[h2], __shfl_xor_sync(0xffffffffu, mx[h2], 2));
        }
        float al2[2];
#pragma unroll
        for (int h2 = 0; h2 < 2; h2++) {
            float mnew = fmaxf(m2[h2], mx[h2]);
            al2[h2] = __expf(m2[h2] - mnew);
            m2[h2] = mnew;
        }
        float sum[2] = {0.f, 0.f};
#pragma unroll
        for (int nt = 0; nt < 8; nt++)
#pragma unroll
            for (int e = 0; e < 4; e++) {
                float p = __expf(s[nt][e] - m2[e >> 1]);
                s[nt][e] = p;
                sum[e >> 1] += p;
            }
#pragma unroll
        for (int h2 = 0; h2 < 2; h2++) {
            sum[h2] += __shfl_xor_sync(0xffffffffu, sum[h2], 1);
            sum[h2] += __shfl_xor_sync(0xffffffffu, sum[h2], 2);
            l2[h2] = l2[h2] * al2[h2] + sum[h2];
        }
#pragma unroll
        for (int nt = 0; nt < 8; nt++) {
            o[nt][0] *= al2[0]; o[nt][1] *= al2[0];
            o[nt][2] *= al2[1]; o[nt][3] *= al2[1];
        }

        // ---- P c-frag -> a-frag (single fp16) ----
        uint32_t pa[4][4];
#pragma unroll
        for (int ks = 0; ks < 4; ks++) {
            pa[ks][0] = pack_h2(s[2*ks][0],   s[2*ks][1]);
            pa[ks][1] = pack_h2(s[2*ks][2],   s[2*ks][3]);
            pa[ks][2] = pack_h2(s[2*ks+1][0], s[2*ks+1][1]);
            pa[ks][3] = pack_h2(s[2*ks+1][2], s[2*ks+1][3]);
        }

        asm volatile("cp.async.wait_group 0;" ::: "memory");
        __syncthreads();

        // ---- O += P @ V ----
#pragma unroll
        for (int ks = 0; ks < 4; ks++) {
            uint32_t vbh[4][4], vbl[4][4];
            const int jr = ks * 16 + (lane & 7) + ((lane >> 3) & 1) * 8;
#pragma unroll
            for (int dp = 0; dp < 4; dp++) {
                uint32_t off = sw128(jr * 128 + dp * 32 + (lane >> 4) * 16);
                ldm_x4t(sb + A_VH + off, vbh[dp][0], vbh[dp][1], vbh[dp][2], vbh[dp][3]);
                ldm_x4t(sb + A_VL + off, vbl[dp][0], vbl[dp][1], vbl[dp][2], vbl[dp][3]);
            }
#pragma unroll
            for (int nt = 0; nt < 8; nt++) {
                const int dp = nt >> 1, s_ = (nt & 1) * 2;
                mma16816h(o[nt], pa[ks], vbh[dp][s_], vbh[dp][s_ + 1]);
                mma16816h(o[nt], pa[ks], vbl[dp][s_], vbl[dp][s_ + 1]);
            }
        }
    }

    // ---- epilogue: normalize, split bf16 hi/lo -> g_oh/g_ol ----
    const float inv0 = 1.f / l2[0], inv1 = 1.f / l2[1];
    const int row0 = i0 + wbase + (lane >> 2);
#pragma unroll
    for (int nt = 0; nt < 8; nt++) {
        const int d = nt * 8 + 2 * (lane & 3);
        uint32_t hi, lo;
        size_t base0 = ((size_t)b * N_SEQ + row0) * INNER + h * DH + d;
        split2(o[nt][0] * inv0, o[nt][1] * inv0, hi, lo);
        *(uint32_t*)&g_oh[base0] = hi;
        *(uint32_t*)&g_ol[base0] = lo;
        size_t base1 = ((size_t)b * N_SEQ + row0 + 8) * INNER + h * DH + d;
        split2(o[nt][2] * inv1, o[nt][3] * inv1, hi, lo);
        *(uint32_t*)&g_oh[base1] = hi;
        *(uint32_t*)&g_ol[base1] = lo;
    }
}

// ---------------------------------------------------------------------------
extern "C" void kernel_launch(void* const* d_in, const int* in_sizes, int n_in,
                              void* d_out, int out_size)
{
    (void)in_sizes; (void)n_in; (void)out_size;
    const float* x   = (const float*)d_in[0];
    const float* Wq  = (const float*)d_in[1];
    const float* Wkv = (const float*)d_in[2];
    const float* Wo  = (const float*)d_in[3];
    const float* bo  = (const float*)d_in[4];
    const float* rel = (const float*)d_in[5];
    float* out = (float*)d_out;

    const int GEMM_SMEM = 2 * STAGE_B;
    cudaFuncSetAttribute(gemm_mma, cudaFuncAttributeMaxDynamicSharedMemorySize, GEMM_SMEM);
    cudaFuncSetAttribute(attn_mma, cudaFuncAttributeMaxDynamicSharedMemorySize, ATT_SMEM);

    split_xrel<<<(NX4 + NR4 + 255) / 256, 256>>>(x, rel);
    tsplit_all<<<4096, 256>>>(Wq, Wkv, Wo);

    // fused q/k/v projection: x @ [Wq|Wkv]
    gemm_mma<<<dim3(3 * INNER / 128, (B_DIM * N_SEQ) / 128), 256, GEMM_SMEM>>>(0, nullptr, nullptr);

    // fused attention (fp16 2-pass, S2 ring)
    attn_mma<<<dim3(16, HEADS, B_DIM), 128, ATT_SMEM>>>();

    // out = o @ Wo + bo
    gemm_mma<<<dim3(DIMX / 128, (B_DIM * N_SEQ) / 128), 256, GEMM_SMEM>>>(2, bo, out);
}

// round 7
// speedup vs baseline: 4.2495x; 1.3609x over previous
#include <cuda_runtime.h>
#include <cuda_bf16.h>
#include <cuda_fp16.h>
#include <cstdint>

#define B_DIM  2
#define N_SEQ  1024
#define DIMX   1024
#define HEADS  16
#define DH     64
#define INNER  1024
#define MAXPOS 512

// ------------------------- device scratch (no allocs) -----------------------
__device__ __align__(16) __half g_xf[(size_t)B_DIM*N_SEQ*DIMX];          // x single fp16
__device__ __align__(16) __half g_wph[(size_t)3*DIMX*INNER];             // [Wq|Wkv]^T hi
__device__ __align__(16) __half g_wpl[(size_t)3*DIMX*INNER];             // lo
__device__ __align__(16) __half g_woh[(size_t)INNER*DIMX];
__device__ __align__(16) __half g_wol[(size_t)INNER*DIMX];
__device__ __align__(16) __half g_of[(size_t)B_DIM*N_SEQ*INNER];         // attn out single fp16
// attention: q hi/lo (scaled), k/v single, rel single
__device__ __align__(16) __half g_qh[(size_t)B_DIM*HEADS*N_SEQ*DH];
__device__ __align__(16) __half g_ql[(size_t)B_DIM*HEADS*N_SEQ*DH];
__device__ __align__(16) __half g_kf[(size_t)B_DIM*HEADS*N_SEQ*DH];
__device__ __align__(16) __half g_vf[(size_t)B_DIM*HEADS*N_SEQ*DH];
__device__ __align__(16) __half g_relf[(size_t)(2*MAXPOS+1)*DH];

// ------------------------------- helpers ------------------------------------
__device__ __forceinline__ uint32_t smem_u32(const void* p) {
    uint32_t a;
    asm("{ .reg .u64 t; cvta.to.shared.u64 t, %1; cvt.u32.u64 %0, t; }"
        : "=r"(a) : "l"(p));
    return a;
}
__device__ __forceinline__ void cp16(uint32_t saddr, const void* gaddr) {
    asm volatile("cp.async.cg.shared.global [%0], [%1], 16;"
                 :: "r"(saddr), "l"(gaddr) : "memory");
}
__device__ __forceinline__ void ldm_x4(uint32_t a, uint32_t& r0, uint32_t& r1,
                                       uint32_t& r2, uint32_t& r3) {
    asm volatile("ldmatrix.sync.aligned.m8n8.x4.shared.b16 {%0,%1,%2,%3}, [%4];"
                 : "=r"(r0), "=r"(r1), "=r"(r2), "=r"(r3) : "r"(a));
}
__device__ __forceinline__ void ldm_x4t(uint32_t a, uint32_t& r0, uint32_t& r1,
                                        uint32_t& r2, uint32_t& r3) {
    asm volatile("ldmatrix.sync.aligned.m8n8.x4.trans.shared.b16 {%0,%1,%2,%3}, [%4];"
                 : "=r"(r0), "=r"(r1), "=r"(r2), "=r"(r3) : "r"(a));
}
__device__ __forceinline__ void mma16816h(float* c, const uint32_t* a,
                                          uint32_t b0, uint32_t b1) {
    asm volatile(
        "mma.sync.aligned.m16n8k16.row.col.f32.f16.f16.f32 "
        "{%0,%1,%2,%3}, {%4,%5,%6,%7}, {%8,%9}, {%0,%1,%2,%3};"
        : "+f"(c[0]), "+f"(c[1]), "+f"(c[2]), "+f"(c[3])
        : "r"(a[0]), "r"(a[1]), "r"(a[2]), "r"(a[3]), "r"(b0), "r"(b1));
}
__device__ __forceinline__ uint32_t sw128(uint32_t off) {
    return off ^ ((off >> 3) & 0x70);
}
__device__ __forceinline__ uint32_t pack_h2(float a, float b) {
    __half2 h = __floats2half2_rn(a, b);
    return *(uint32_t*)&h;
}
__device__ __forceinline__ void split2h(float a, float b, uint32_t& hi, uint32_t& lo) {
    __half2 h = __floats2half2_rn(a, b);
    float ra = a - __half2float(__low2half(h));
    float rb = b - __half2float(__high2half(h));
    __half2 l = __floats2half2_rn(ra, rb);
    hi = *(uint32_t*)&h; lo = *(uint32_t*)&l;
}

// ------------------------- conversion kernels -------------------------------
#define NX4 (B_DIM * N_SEQ * DIMX / 4)          // 524288
#define NR4 ((2 * MAXPOS + 1) * DH / 4)         // 16400

__global__ __launch_bounds__(256) void split_xrel(const float* __restrict__ x,
                                                  const float* __restrict__ rel)
{
    int i = blockIdx.x * blockDim.x + threadIdx.x;
    if (i >= NX4 + NR4) return;
    if (i < NX4) {
        float4 v = ((const float4*)x)[i];
        ((uint32_t*)g_xf)[2*i]   = pack_h2(v.x, v.y);
        ((uint32_t*)g_xf)[2*i+1] = pack_h2(v.z, v.w);
    } else {
        int j = i - NX4;
        float4 v = ((const float4*)rel)[j];
        ((uint32_t*)g_relf)[2*j]   = pack_h2(v.x, v.y);
        ((uint32_t*)g_relf)[2*j+1] = pack_h2(v.z, v.w);
    }
}

// transpose + split all weights (fp16 hi/lo) in one launch.
__global__ __launch_bounds__(256) void tsplit_all(const float* __restrict__ Wq,
                                                  const float* __restrict__ Wkv,
                                                  const float* __restrict__ Wo)
{
    __shared__ float t[32][33];
    const int bid = blockIdx.x;
    const float* W; __half *th, *tl;
    int N, kt, ntile, rowoff;
    if (bid < 1024)      { W = Wq;  N = 1024; kt = bid >> 5; ntile = bid & 31;
                           th = g_wph; tl = g_wpl; rowoff = 0; }
    else if (bid < 3072) { int l = bid - 1024; W = Wkv; N = 2048;
                           kt = l >> 6; ntile = l & 63;
                           th = g_wph; tl = g_wpl; rowoff = 1024; }
    else                 { int l = bid - 3072; W = Wo; N = 1024;
                           kt = l >> 5; ntile = l & 31;
                           th = g_woh; tl = g_wol; rowoff = 0; }
    const int n0 = ntile * 32, k0 = kt * 32;
    const int tx = threadIdx.x & 31, ty = threadIdx.x >> 5;
#pragma unroll
    for (int r = 0; r < 4; r++)
        t[ty + 8*r][tx] = W[(size_t)(k0 + ty + 8*r) * N + n0 + tx];
    __syncthreads();
#pragma unroll
    for (int r = 0; r < 4; r++) {
        float v = t[tx][ty + 8*r];
        __half h = __float2half_rn(v);
        __half l = __float2half_rn(v - __half2float(h));
        size_t o = (size_t)(rowoff + n0 + ty + 8*r) * 1024 + k0 + tx;
        th[o] = h; tl[o] = l;
    }
}

// ------------------------- fp16 2-pass GEMM (mma.sync) ----------------------
// C = A @ (Bh+Bl)^T : A single fp16, B hi/lo fp16, fp32 accum, 3-stage pipe.
// mode 0: x @ [Wq|Wkv] -> q(hi/lo, scaled) / k / v ; mode 2: o @ Wo + bias.
#define BK 32
#define RS 40
#define TILE_B (128 * RS * 2)     // 10240 B
#define STAGE_B (3 * TILE_B)      // A, Bh, Bl
#define NSTAGE 3

__global__ __launch_bounds__(256, 1) void gemm_mma(int mode,
                                                   const float* __restrict__ bias,
                                                   float* __restrict__ outp)
{
    extern __shared__ __align__(128) char smem[];
    const uint32_t sb = smem_u32(smem);
    const int tid = threadIdx.x;
    const int wid = tid >> 5, lane = tid & 31;
    const int warp_m = wid & 1, warp_n = wid >> 1;
    const int m0 = blockIdx.y * 128, n0 = blockIdx.x * 128;

    const __half *A, *Bh, *Bl;
    if (mode == 0) { A = g_xf; Bh = g_wph; Bl = g_wpl; }
    else           { A = g_of; Bh = g_woh; Bl = g_wol; }

    float acc[4][4][4];
#pragma unroll
    for (int i = 0; i < 4; i++)
#pragma unroll
        for (int j = 0; j < 4; j++)
#pragma unroll
            for (int t = 0; t < 4; t++) acc[i][j][t] = 0.f;

    const int nkt = DIMX / BK;

    auto issue_stage = [&](int kt) {
        const int k0 = kt * BK;
        const uint32_t st = sb + (kt % NSTAGE) * STAGE_B;
#pragma unroll
        for (int i = 0; i < 6; i++) {
            int id = tid + i * 256;
            int tile = id >> 9, rem = id & 511;
            int r = rem >> 2, cc = rem & 3;
            uint32_t sa = st + tile * TILE_B + r * (RS * 2) + cc * 16;
            const __half* src;
            size_t goff;
            if (tile == 0)      { src = A;  goff = (size_t)(m0 + r) * DIMX; }
            else if (tile == 1) { src = Bh; goff = (size_t)(n0 + r) * DIMX; }
            else                { src = Bl; goff = (size_t)(n0 + r) * DIMX; }
            cp16(sa, src + goff + k0 + cc * 8);
        }
        asm volatile("cp.async.commit_group;" ::: "memory");
    };

    issue_stage(0);
    issue_stage(1);

    const int lr = lane & 15;
    const int lc = (lane >> 4) * 8;

    for (int kt = 0; kt < nkt; kt++) {
        if (kt + 2 < nkt) {
            issue_stage(kt + 2);
            asm volatile("cp.async.wait_group 2;" ::: "memory");
        } else if (kt + 1 < nkt) {
            asm volatile("cp.async.wait_group 1;" ::: "memory");
        } else {
            asm volatile("cp.async.wait_group 0;" ::: "memory");
        }
        __syncthreads();

        const uint32_t st = sb + (kt % NSTAGE) * STAGE_B;
        const uint32_t aBase  = st + 0 * TILE_B + (warp_m * 64 + lr) * (RS * 2);
        const uint32_t bBaseH = st + 1 * TILE_B + (warp_n * 32 + lr) * (RS * 2);
        const uint32_t bBaseL = st + 2 * TILE_B + (warp_n * 32 + lr) * (RS * 2);

#pragma unroll
        for (int ks = 0; ks < BK; ks += 16) {
            uint32_t ah[4][4], bh[2][4], bl[2][4];
            const uint32_t koff = (ks + lc) * 2;
#pragma unroll
            for (int mt = 0; mt < 4; mt++)
                ldm_x4(aBase + mt * 16 * (RS * 2) + koff,
                       ah[mt][0], ah[mt][1], ah[mt][2], ah[mt][3]);
#pragma unroll
            for (int p = 0; p < 2; p++) {
                ldm_x4(bBaseH + p * 16 * (RS * 2) + koff,
                       bh[p][0], bh[p][1], bh[p][2], bh[p][3]);
                ldm_x4(bBaseL + p * 16 * (RS * 2) + koff,
                       bl[p][0], bl[p][1], bl[p][2], bl[p][3]);
            }
#pragma unroll
            for (int mt = 0; mt < 4; mt++)
#pragma unroll
                for (int nt = 0; nt < 4; nt++) {
                    const int p = nt >> 1, s = nt & 1;
                    mma16816h(acc[mt][nt], ah[mt], bh[p][s], bh[p][s + 2]);
                    mma16816h(acc[mt][nt], ah[mt], bl[p][s], bl[p][s + 2]);
                }
        }
        __syncthreads();
    }

    const float qscale = 0.125f;
#pragma unroll
    for (int mt = 0; mt < 4; mt++) {
#pragma unroll
        for (int half = 0; half < 2; half++) {
            const int m = m0 + warp_m * 64 + mt * 16 + (lane >> 2) + half * 8;
#pragma unroll
            for (int nt = 0; nt < 4; nt++) {
                const int c = n0 + warp_n * 32 + nt * 8 + 2 * (lane & 3);
                float v0 = acc[mt][nt][half * 2 + 0];
                float v1 = acc[mt][nt][half * 2 + 1];
                if (mode != 0) {
                    float2 o = {v0 + bias[c], v1 + bias[c + 1]};
                    *(float2*)&outp[(size_t)m * DIMX + c] = o;
                } else {
                    const int bb = m >> 10, ii = m & 1023;
                    if (c < INNER) {               // q: fp16 hi/lo, scaled
                        const int hh = c >> 6, dd = c & 63;
                        size_t o = (((size_t)bb * HEADS + hh) * N_SEQ + ii) * DH + dd;
                        uint32_t hi, lo;
                        split2h(v0 * qscale, v1 * qscale, hi, lo);
                        *(uint32_t*)&g_qh[o] = hi;
                        *(uint32_t*)&g_ql[o] = lo;
                    } else {                       // k/v: single fp16
                        int col0 = c - INNER;
                        __half* dst = (col0 < INNER) ? g_kf : g_vf;
                        if (col0 >= INNER) col0 -= INNER;
                        const int hh = col0 >> 6, dd = col0 & 63;
                        size_t o = (((size_t)bb * HEADS + hh) * N_SEQ + ii) * DH + dd;
                        *(uint32_t*)&dst[o] = pack_h2(v0, v1);
                    }
                }
            }
        }
    }
}

// ---------------------------------------------------------------------------
// Tensor-core flash attention: Q/P hi-lo in regs, K/V/rel single fp16, S2 ring.
// ---------------------------------------------------------------------------
#define A_QH 0
#define A_QL 8192
#define A_K  16384
#define A_V  24576
#define A_R  32768
#define A_S2 40960
#define S2S  132
#define ATT_SMEM (A_S2 + 64 * S2S * 4)   // 74752

__global__ __launch_bounds__(128, 2) void attn_mma(void)
{
    extern __shared__ __align__(128) char smem[];
    const uint32_t sb = smem_u32(smem);
    float* s2p = (float*)(smem + A_S2);

    const int tid  = threadIdx.x;
    const int lane = tid & 31, warp = tid >> 5;
    const int wbase = warp * 16;
    const int i0 = blockIdx.x * 64;
    const int h  = blockIdx.y;
    const int b  = blockIdx.z;
    const size_t hb = ((size_t)b * HEADS + h) * N_SEQ * DH;

    // ---- load Q hi/lo planes ----
#pragma unroll
    for (int i = 0; i < 4; i++) {
        int id = tid + i * 128;
        int r = id >> 3, c = id & 7;
        uint32_t d = sw128(r * 128 + c * 16);
        cp16(sb + A_QH + d, g_qh + hb + (size_t)(i0 + r) * DH + c * 8);
        cp16(sb + A_QL + d, g_ql + hb + (size_t)(i0 + r) * DH + c * 8);
    }
    asm volatile("cp.async.commit_group;" ::: "memory");
    asm volatile("cp.async.wait_group 0;" ::: "memory");
    __syncthreads();

    uint32_t qa[2][4][4];
#pragma unroll
    for (int ks = 0; ks < 4; ks++) {
        uint32_t off = sw128((wbase + (lane & 15)) * 128 + ks * 32 + (lane >> 4) * 16);
        ldm_x4(sb + A_QH + off, qa[0][ks][0], qa[0][ks][1], qa[0][ks][2], qa[0][ks][3]);
        ldm_x4(sb + A_QL + off, qa[1][ks][0], qa[1][ks][1], qa[1][ks][2], qa[1][ks][3]);
    }

    auto stage_rel = [&](int Dbase) {
#pragma unroll
        for (int i = 0; i < 4; i++) {
            int id = tid + i * 128;
            int r = id >> 3, c = id & 7;
            int dist = min(max(Dbase + r, -MAXPOS), MAXPOS) + MAXPOS;
            uint32_t d = sw128(r * 128 + c * 16);
            cp16(sb + A_R + d, g_relf + (size_t)dist * DH + c * 8);
        }
    };

    auto s2_group = [&](int baseSlot) {
        float s2[8][4];
#pragma unroll
        for (int nt = 0; nt < 8; nt++)
#pragma unroll
            for (int e = 0; e < 4; e++) s2[nt][e] = 0.f;
#pragma unroll
        for (int ks = 0; ks < 4; ks++) {
            uint32_t rb[4][4];
#pragma unroll
            for (int g = 0; g < 4; g++) {
                uint32_t off = sw128((g * 16 + (lane & 15)) * 128
                                     + ks * 32 + (lane >> 4) * 16);
                ldm_x4(sb + A_R + off, rb[g][0], rb[g][1], rb[g][2], rb[g][3]);
            }
#pragma unroll
            for (int nt = 0; nt < 8; nt++) {
                const int p = nt >> 1, s_ = nt & 1;
                mma16816h(s2[nt], qa[0][ks], rb[p][s_], rb[p][s_ + 2]);
                mma16816h(s2[nt], qa[1][ks], rb[p][s_], rb[p][s_ + 2]);
            }
        }
        const int rl0 = wbase + (lane >> 2);
#pragma unroll
        for (int nt = 0; nt < 8; nt++) {
            const int col = baseSlot + nt * 8 + 2 * (lane & 3);
            *(float2*)&s2p[rl0 * S2S + col]       = {s2[nt][0], s2[nt][1]};
            *(float2*)&s2p[(rl0 + 8) * S2S + col] = {s2[nt][2], s2[nt][3]};
        }
    };

    // pre-group: slots 64..127 = dists [i0+1, i0+64]
    stage_rel(i0 + 1);
    asm volatile("cp.async.commit_group;" ::: "memory");
    asm volatile("cp.async.wait_group 0;" ::: "memory");
    __syncthreads();
    s2_group(64);

    float o[8][4];
#pragma unroll
    for (int nt = 0; nt < 8; nt++)
#pragma unroll
        for (int e = 0; e < 4; e++) o[nt][e] = 0.f;
    float m2[2] = {-1e30f, -1e30f}, l2[2] = {0.f, 0.f};
    bool clipgrp[2] = {false, false};

    for (int jt = 0; jt < 16; jt++) {
        const int j0 = jt * 64;
        __syncthreads();

        // group A: K + (maybe) new rel rows
#pragma unroll
        for (int i = 0; i < 4; i++) {
            int id = tid + i * 128;
            int r = id >> 3, c = id & 7;
            uint32_t d = sw128(r * 128 + c * 16);
            cp16(sb + A_K + d, g_kf + hb + (size_t)(j0 + r) * DH + c * 8);
        }
        const int Dbase = i0 - j0 - 63;
        const bool fullclip = (Dbase + 63 <= -MAXPOS);
        const bool skip = fullclip && clipgrp[jt & 1];
        if (!skip) stage_rel(Dbase);
        asm volatile("cp.async.commit_group;" ::: "memory");
        // group B: V
#pragma unroll
        for (int i = 0; i < 4; i++) {
            int id = tid + i * 128;
            int r = id >> 3, c = id & 7;
            uint32_t d = sw128(r * 128 + c * 16);
            cp16(sb + A_V + d, g_vf + hb + (size_t)(j0 + r) * DH + c * 8);
        }
        asm volatile("cp.async.commit_group;" ::: "memory");

        asm volatile("cp.async.wait_group 1;" ::: "memory");
        __syncthreads();

        // ---- new S2 columns (64) ----
        if (!skip) s2_group((jt & 1) ? 64 : 0);
        clipgrp[jt & 1] = fullclip;
        __syncwarp();

        // ---- S1 = Q @ K^T (64x64) ----
        float s[8][4];
#pragma unroll
        for (int nt = 0; nt < 8; nt++)
#pragma unroll
            for (int e = 0; e < 4; e++) s[nt][e] = 0.f;
#pragma unroll
        for (int ks = 0; ks < 4; ks++) {
            uint32_t kb[4][4];
#pragma unroll
            for (int g = 0; g < 4; g++) {
                uint32_t off = sw128((g * 16 + (lane & 15)) * 128
                                     + ks * 32 + (lane >> 4) * 16);
                ldm_x4(sb + A_K + off, kb[g][0], kb[g][1], kb[g][2], kb[g][3]);
            }
#pragma unroll
            for (int nt = 0; nt < 8; nt++) {
                const int p = nt >> 1, s_ = nt & 1;
                mma16816h(s[nt], qa[0][ks], kb[p][s_], kb[p][s_ + 2]);
                mma16816h(s[nt], qa[1][ks], kb[p][s_], kb[p][s_ + 2]);
            }
        }

        // ---- gather rel bias from ring, online softmax ----
        const int rl0 = wbase + (lane >> 2);
#pragma unroll
        for (int nt = 0; nt < 8; nt++)
#pragma unroll
            for (int e = 0; e < 4; e++) {
                const int rr = rl0 + 8 * (e >> 1);
                const int jj = nt * 8 + 2 * (lane & 3) + (e & 1);
                const int slot = (rr - jj + 63 - j0) & 127;
                s[nt][e] += s2p[rr * S2S + slot];
            }

        float mx[2] = {-1e30f, -1e30f};
#pragma unroll
        for (int nt = 0; nt < 8; nt++)
#pragma unroll
            for (int e = 0; e < 4; e++)
                mx[e >> 1] = fmaxf(mx[e >> 1], s[nt][e]);
#pragma unroll
        for (int h2 = 0; h2 < 2; h2++) {
            mx[h2] = fmaxf(mx[h2], __shfl_xor_sync(0xffffffffu, mx[h2], 1));
            mx[h2] = fmaxf(mx[h2], __shfl_xor_sync(0xffffffffu, mx[h2], 2));
        }
        float al2[2];
#pragma unroll
        for (int h2 = 0; h2 < 2; h2++) {
            float mnew = fmaxf(m2[h2], mx[h2]);
            al2[h2] = __expf(m2[h2] - mnew);
            m2[h2] = mnew;
        }
        float sum[2] = {0.f, 0.f};
#pragma unroll
        for (int nt = 0; nt < 8; nt++)
#pragma unroll
            for (int e = 0; e < 4; e++) {
                float p = __expf(s[nt][e] - m2[e >> 1]);
                s[nt][e] = p;
                sum[e >> 1] += p;
            }
#pragma unroll
        for (int h2 = 0; h2 < 2; h2++) {
            sum[h2] += __shfl_xor_sync(0xffffffffu, sum[h2], 1);
            sum[h2] += __shfl_xor_sync(0xffffffffu, sum[h2], 2);
            l2[h2] = l2[h2] * al2[h2] + sum[h2];
        }
#pragma unroll
        for (int nt = 0; nt < 8; nt++) {
            o[nt][0] *= al2[0]; o[nt][1] *= al2[0];
            o[nt][2] *= al2[1]; o[nt][3] *= al2[1];
        }

        // ---- P c-frag -> a-frag (fp16 hi/lo) ----
        uint32_t pah[4][4], pal[4][4];
#pragma unroll
        for (int ks = 0; ks < 4; ks++) {
            split2h(s[2*ks][0],   s[2*ks][1],   pah[ks][0], pal[ks][0]);
            split2h(s[2*ks][2],   s[2*ks][3],   pah[ks][1], pal[ks][1]);
            split2h(s[2*ks+1][0], s[2*ks+1][1], pah[ks][2], pal[ks][2]);
            split2h(s[2*ks+1][2], s[2*ks+1][3], pah[ks][3], pal[ks][3]);
        }

        asm volatile("cp.async.wait_group 0;" ::: "memory");
        __syncthreads();

        // ---- O += P @ V ----
#pragma unroll
        for (int ks = 0; ks < 4; ks++) {
            uint32_t vb[4][4];
            const int jr = ks * 16 + (lane & 7) + ((lane >> 3) & 1) * 8;
#pragma unroll
            for (int dp = 0; dp < 4; dp++) {
                uint32_t off = sw128(jr * 128 + dp * 32 + (lane >> 4) * 16);
                ldm_x4t(sb + A_V + off, vb[dp][0], vb[dp][1], vb[dp][2], vb[dp][3]);
            }
#pragma unroll
            for (int nt = 0; nt < 8; nt++) {
                const int dp = nt >> 1, s_ = (nt & 1) * 2;
                mma16816h(o[nt], pah[ks], vb[dp][s_], vb[dp][s_ + 1]);
                mma16816h(o[nt], pal[ks], vb[dp][s_], vb[dp][s_ + 1]);
            }
        }
    }

    // ---- epilogue: normalize -> single fp16 g_of ----
    const float inv0 = 1.f / l2[0], inv1 = 1.f / l2[1];
    const int row0 = i0 + wbase + (lane >> 2);
#pragma unroll
    for (int nt = 0; nt < 8; nt++) {
        const int d = nt * 8 + 2 * (lane & 3);
        size_t base0 = ((size_t)b * N_SEQ + row0) * INNER + h * DH + d;
        *(uint32_t*)&g_of[base0] = pack_h2(o[nt][0] * inv0, o[nt][1] * inv0);
        size_t base1 = ((size_t)b * N_SEQ + row0 + 8) * INNER + h * DH + d;
        *(uint32_t*)&g_of[base1] = pack_h2(o[nt][2] * inv1, o[nt][3] * inv1);
    }
}

// ---------------------------------------------------------------------------
extern "C" void kernel_launch(void* const* d_in, const int* in_sizes, int n_in,
                              void* d_out, int out_size)
{
    (void)in_sizes; (void)n_in; (void)out_size;
    const float* x   = (const float*)d_in[0];
    const float* Wq  = (const float*)d_in[1];
    const float* Wkv = (const float*)d_in[2];
    const float* Wo  = (const float*)d_in[3];
    const float* bo  = (const float*)d_in[4];
    const float* rel = (const float*)d_in[5];
    float* out = (float*)d_out;

    const int GEMM_SMEM = NSTAGE * STAGE_B;      // 92160
    cudaFuncSetAttribute(gemm_mma, cudaFuncAttributeMaxDynamicSharedMemorySize, GEMM_SMEM);
    cudaFuncSetAttribute(attn_mma, cudaFuncAttributeMaxDynamicSharedMemorySize, ATT_SMEM);

    split_xrel<<<(NX4 + NR4 + 255) / 256, 256>>>(x, rel);
    tsplit_all<<<4096, 256>>>(Wq, Wkv, Wo);

    // fused q/k/v projection: x @ [Wq|Wkv]
    gemm_mma<<<dim3(3 * INNER / 128, (B_DIM * N_SEQ) / 128), 256, GEMM_SMEM>>>(0, nullptr, nullptr);

    // fused attention (fp16, Q/P hi-lo, S2 ring)
    attn_mma<<<dim3(16, HEADS, B_DIM), 128, ATT_SMEM>>>();

    // out = o @ Wo + bo
    gemm_mma<<<dim3(DIMX / 128, (B_DIM * N_SEQ) / 128), 256, GEMM_SMEM>>>(2, bo, out);
}

// round 8
// speedup vs baseline: 4.5539x; 1.0716x over previous
#include <cuda_runtime.h>
#include <cuda_bf16.h>
#include <cuda_fp16.h>
#include <cstdint>

#define B_DIM  2
#define N_SEQ  1024
#define DIMX   1024
#define HEADS  16
#define DH     64
#define INNER  1024
#define MAXPOS 512

// ------------------------- device scratch (no allocs) -----------------------
__device__ __align__(16) __half g_xf[(size_t)B_DIM*N_SEQ*DIMX];
__device__ __align__(16) __half g_wph[(size_t)3*DIMX*INNER];
__device__ __align__(16) __half g_wpl[(size_t)3*DIMX*INNER];
__device__ __align__(16) __half g_woh[(size_t)INNER*DIMX];
__device__ __align__(16) __half g_wol[(size_t)INNER*DIMX];
__device__ __align__(16) __half g_of[(size_t)B_DIM*N_SEQ*INNER];
// attention: q hi/lo (scaled by 0.125*log2e), k/v/rel single fp16
__device__ __align__(16) __half g_qh[(size_t)B_DIM*HEADS*N_SEQ*DH];
__device__ __align__(16) __half g_ql[(size_t)B_DIM*HEADS*N_SEQ*DH];
__device__ __align__(16) __half g_kf[(size_t)B_DIM*HEADS*N_SEQ*DH];
__device__ __align__(16) __half g_vf[(size_t)B_DIM*HEADS*N_SEQ*DH];
__device__ __align__(16) __half g_relf[(size_t)(2*MAXPOS+1)*DH];

// ------------------------------- helpers ------------------------------------
__device__ __forceinline__ uint32_t smem_u32(const void* p) {
    uint32_t a;
    asm("{ .reg .u64 t; cvta.to.shared.u64 t, %1; cvt.u32.u64 %0, t; }"
        : "=r"(a) : "l"(p));
    return a;
}
__device__ __forceinline__ void cp16(uint32_t saddr, const void* gaddr) {
    asm volatile("cp.async.cg.shared.global [%0], [%1], 16;"
                 :: "r"(saddr), "l"(gaddr) : "memory");
}
__device__ __forceinline__ void ldm_x4(uint32_t a, uint32_t& r0, uint32_t& r1,
                                       uint32_t& r2, uint32_t& r3) {
    asm volatile("ldmatrix.sync.aligned.m8n8.x4.shared.b16 {%0,%1,%2,%3}, [%4];"
                 : "=r"(r0), "=r"(r1), "=r"(r2), "=r"(r3) : "r"(a));
}
__device__ __forceinline__ void ldm_x4t(uint32_t a, uint32_t& r0, uint32_t& r1,
                                        uint32_t& r2, uint32_t& r3) {
    asm volatile("ldmatrix.sync.aligned.m8n8.x4.trans.shared.b16 {%0,%1,%2,%3}, [%4];"
                 : "=r"(r0), "=r"(r1), "=r"(r2), "=r"(r3) : "r"(a));
}
__device__ __forceinline__ void mma16816h(float* c, const uint32_t* a,
                                          uint32_t b0, uint32_t b1) {
    asm volatile(
        "mma.sync.aligned.m16n8k16.row.col.f32.f16.f16.f32 "
        "{%0,%1,%2,%3}, {%4,%5,%6,%7}, {%8,%9}, {%0,%1,%2,%3};"
        : "+f"(c[0]), "+f"(c[1]), "+f"(c[2]), "+f"(c[3])
        : "r"(a[0]), "r"(a[1]), "r"(a[2]), "r"(a[3]), "r"(b0), "r"(b1));
}
__device__ __forceinline__ uint32_t sw128(uint32_t off) {
    return off ^ ((off >> 3) & 0x70);
}
__device__ __forceinline__ uint32_t pack_h2(float a, float b) {
    __half2 h = __floats2half2_rn(a, b);
    return *(uint32_t*)&h;
}
__device__ __forceinline__ void split2h(float a, float b, uint32_t& hi, uint32_t& lo) {
    __half2 h = __floats2half2_rn(a, b);
    float ra = a - __half2float(__low2half(h));
    float rb = b - __half2float(__high2half(h));
    __half2 l = __floats2half2_rn(ra, rb);
    hi = *(uint32_t*)&h; lo = *(uint32_t*)&l;
}

// ------------------- fused conversion kernel (one launch) -------------------
// blocks [0, 4096): weight transpose+split ; blocks [4096, ...): x / rel pack
#define NX4 (B_DIM * N_SEQ * DIMX / 4)          // 524288
#define NR4 ((2 * MAXPOS + 1) * DH / 4)         // 16400
#define NCONV_BLK ((NX4 + NR4 + 255) / 256)     // 2113

__global__ __launch_bounds__(256) void convert_all(const float* __restrict__ x,
                                                   const float* __restrict__ rel,
                                                   const float* __restrict__ Wq,
                                                   const float* __restrict__ Wkv,
                                                   const float* __restrict__ Wo)
{
    const int bid = blockIdx.x;
    if (bid >= 4096) {
        int i = (bid - 4096) * 256 + threadIdx.x;
        if (i >= NX4 + NR4) return;
        if (i < NX4) {
            float4 v = ((const float4*)x)[i];
            ((uint32_t*)g_xf)[2*i]   = pack_h2(v.x, v.y);
            ((uint32_t*)g_xf)[2*i+1] = pack_h2(v.z, v.w);
        } else {
            int j = i - NX4;
            float4 v = ((const float4*)rel)[j];
            ((uint32_t*)g_relf)[2*j]   = pack_h2(v.x, v.y);
            ((uint32_t*)g_relf)[2*j+1] = pack_h2(v.z, v.w);
        }
        return;
    }
    __shared__ float t[32][33];
    const float* W; __half *th, *tl;
    int N, kt, ntile, rowoff;
    if (bid < 1024)      { W = Wq;  N = 1024; kt = bid >> 5; ntile = bid & 31;
                           th = g_wph; tl = g_wpl; rowoff = 0; }
    else if (bid < 3072) { int l = bid - 1024; W = Wkv; N = 2048;
                           kt = l >> 6; ntile = l & 63;
                           th = g_wph; tl = g_wpl; rowoff = 1024; }
    else                 { int l = bid - 3072; W = Wo; N = 1024;
                           kt = l >> 5; ntile = l & 31;
                           th = g_woh; tl = g_wol; rowoff = 0; }
    const int n0 = ntile * 32, k0 = kt * 32;
    const int tx = threadIdx.x & 31, ty = threadIdx.x >> 5;
#pragma unroll
    for (int r = 0; r < 4; r++)
        t[ty + 8*r][tx] = W[(size_t)(k0 + ty + 8*r) * N + n0 + tx];
    __syncthreads();
#pragma unroll
    for (int r = 0; r < 4; r++) {
        float v = t[tx][ty + 8*r];
        __half h = __float2half_rn(v);
        __half l = __float2half_rn(v - __half2float(h));
        size_t o = (size_t)(rowoff + n0 + ty + 8*r) * 1024 + k0 + tx;
        th[o] = h; tl[o] = l;
    }
}

// ------------------------- fp16 2-pass GEMM (mma.sync) ----------------------
#define BK 32
#define RS 40
#define TILE_B (128 * RS * 2)     // 10240 B
#define STAGE_B (3 * TILE_B)      // A, Bh, Bl
#define NSTAGE 3

__global__ __launch_bounds__(256, 1) void gemm_mma(int mode,
                                                   const float* __restrict__ bias,
                                                   float* __restrict__ outp)
{
    extern __shared__ __align__(128) char smem[];
    const uint32_t sb = smem_u32(smem);
    const int tid = threadIdx.x;
    const int wid = tid >> 5, lane = tid & 31;
    const int warp_m = wid & 1, warp_n = wid >> 1;
    const int m0 = blockIdx.y * 128, n0 = blockIdx.x * 128;

    const __half *A, *Bh, *Bl;
    if (mode == 0) { A = g_xf; Bh = g_wph; Bl = g_wpl; }
    else           { A = g_of; Bh = g_woh; Bl = g_wol; }

    float acc[4][4][4];
#pragma unroll
    for (int i = 0; i < 4; i++)
#pragma unroll
        for (int j = 0; j < 4; j++)
#pragma unroll
            for (int t = 0; t < 4; t++) acc[i][j][t] = 0.f;

    const int nkt = DIMX / BK;

    auto issue_stage = [&](int kt) {
        const int k0 = kt * BK;
        const uint32_t st = sb + (kt % NSTAGE) * STAGE_B;
#pragma unroll
        for (int i = 0; i < 6; i++) {
            int id = tid + i * 256;
            int tile = id >> 9, rem = id & 511;
            int r = rem >> 2, cc = rem & 3;
            uint32_t sa = st + tile * TILE_B + r * (RS * 2) + cc * 16;
            const __half* src;
            size_t goff;
            if (tile == 0)      { src = A;  goff = (size_t)(m0 + r) * DIMX; }
            else if (tile == 1) { src = Bh; goff = (size_t)(n0 + r) * DIMX; }
            else                { src = Bl; goff = (size_t)(n0 + r) * DIMX; }
            cp16(sa, src + goff + k0 + cc * 8);
        }
        asm volatile("cp.async.commit_group;" ::: "memory");
    };

    issue_stage(0);
    issue_stage(1);

    const int lr = lane & 15;
    const int lc = (lane >> 4) * 8;

    for (int kt = 0; kt < nkt; kt++) {
        if (kt + 2 < nkt) {
            issue_stage(kt + 2);
            asm volatile("cp.async.wait_group 2;" ::: "memory");
        } else if (kt + 1 < nkt) {
            asm volatile("cp.async.wait_group 1;" ::: "memory");
        } else {
            asm volatile("cp.async.wait_group 0;" ::: "memory");
        }
        __syncthreads();

        const uint32_t st = sb + (kt % NSTAGE) * STAGE_B;
        const uint32_t aBase  = st + 0 * TILE_B + (warp_m * 64 + lr) * (RS * 2);
        const uint32_t bBaseH = st + 1 * TILE_B + (warp_n * 32 + lr) * (RS * 2);
        const uint32_t bBaseL = st + 2 * TILE_B + (warp_n * 32 + lr) * (RS * 2);

#pragma unroll
        for (int ks = 0; ks < BK; ks += 16) {
            uint32_t ah[4][4], bh[2][4], bl[2][4];
            const uint32_t koff = (ks + lc) * 2;
#pragma unroll
            for (int mt = 0; mt < 4; mt++)
                ldm_x4(aBase + mt * 16 * (RS * 2) + koff,
                       ah[mt][0], ah[mt][1], ah[mt][2], ah[mt][3]);
#pragma unroll
            for (int p = 0; p < 2; p++) {
                ldm_x4(bBaseH + p * 16 * (RS * 2) + koff,
                       bh[p][0], bh[p][1], bh[p][2], bh[p][3]);
                ldm_x4(bBaseL + p * 16 * (RS * 2) + koff,
                       bl[p][0], bl[p][1], bl[p][2], bl[p][3]);
            }
#pragma unroll
            for (int mt = 0; mt < 4; mt++)
#pragma unroll
                for (int nt = 0; nt < 4; nt++) {
                    const int p = nt >> 1, s = nt & 1;
                    mma16816h(acc[mt][nt], ah[mt], bh[p][s], bh[p][s + 2]);
                    mma16816h(acc[mt][nt], ah[mt], bl[p][s], bl[p][s + 2]);
                }
        }
        __syncthreads();
    }

    // q scale folds softmax scale AND log2(e) for exp2-softmax
    const float qscale = 0.125f * 1.4426950408889634f;
#pragma unroll
    for (int mt = 0; mt < 4; mt++) {
#pragma unroll
        for (int half = 0; half < 2; half++) {
            const int m = m0 + warp_m * 64 + mt * 16 + (lane >> 2) + half * 8;
#pragma unroll
            for (int nt = 0; nt < 4; nt++) {
                const int c = n0 + warp_n * 32 + nt * 8 + 2 * (lane & 3);
                float v0 = acc[mt][nt][half * 2 + 0];
                float v1 = acc[mt][nt][half * 2 + 1];
                if (mode != 0) {
                    float2 o = {v0 + bias[c], v1 + bias[c + 1]};
                    *(float2*)&outp[(size_t)m * DIMX + c] = o;
                } else {
                    const int bb = m >> 10, ii = m & 1023;
                    if (c < INNER) {               // q: fp16 hi/lo, scaled
                        const int hh = c >> 6, dd = c & 63;
                        size_t o = (((size_t)bb * HEADS + hh) * N_SEQ + ii) * DH + dd;
                        uint32_t hi, lo;
                        split2h(v0 * qscale, v1 * qscale, hi, lo);
                        *(uint32_t*)&g_qh[o] = hi;
                        *(uint32_t*)&g_ql[o] = lo;
                    } else {                       // k/v: single fp16
                        int col0 = c - INNER;
                        __half* dst = (col0 < INNER) ? g_kf : g_vf;
                        if (col0 >= INNER) col0 -= INNER;
                        const int hh = col0 >> 6, dd = col0 & 63;
                        size_t o = (((size_t)bb * HEADS + hh) * N_SEQ + ii) * DH + dd;
                        *(uint32_t*)&dst[o] = pack_h2(v0, v1);
                    }
                }
            }
        }
    }
}

// ---------------------------------------------------------------------------
// Tensor-core flash attention: Q hi/lo, K/V/rel single fp16, P single,
// fp16 S2 ring, exp2 softmax, occupancy 3.
// ---------------------------------------------------------------------------
#define A_QH 0
#define A_QL 8192
#define A_K  16384
#define A_V  24576
#define A_R  32768
#define A_S2 40960
#define S2S  132
#define ATT_SMEM (A_S2 + 64 * S2S * 2)   // 57856

__global__ __launch_bounds__(128, 3) void attn_mma(void)
{
    extern __shared__ __align__(128) char smem[];
    const uint32_t sb = smem_u32(smem);
    __half* s2h = (__half*)(smem + A_S2);

    const int tid  = threadIdx.x;
    const int lane = tid & 31, warp = tid >> 5;
    const int wbase = warp * 16;
    const int i0 = blockIdx.x * 64;
    const int h  = blockIdx.y;
    const int b  = blockIdx.z;
    const size_t hb = ((size_t)b * HEADS + h) * N_SEQ * DH;

    // ---- load Q hi/lo planes ----
#pragma unroll
    for (int i = 0; i < 4; i++) {
        int id = tid + i * 128;
        int r = id >> 3, c = id & 7;
        uint32_t d = sw128(r * 128 + c * 16);
        cp16(sb + A_QH + d, g_qh + hb + (size_t)(i0 + r) * DH + c * 8);
        cp16(sb + A_QL + d, g_ql + hb + (size_t)(i0 + r) * DH + c * 8);
    }
    asm volatile("cp.async.commit_group;" ::: "memory");
    asm volatile("cp.async.wait_group 0;" ::: "memory");
    __syncthreads();

    uint32_t qa[2][4][4];
#pragma unroll
    for (int ks = 0; ks < 4; ks++) {
        uint32_t off = sw128((wbase + (lane & 15)) * 128 + ks * 32 + (lane >> 4) * 16);
        ldm_x4(sb + A_QH + off, qa[0][ks][0], qa[0][ks][1], qa[0][ks][2], qa[0][ks][3]);
        ldm_x4(sb + A_QL + off, qa[1][ks][0], qa[1][ks][1], qa[1][ks][2], qa[1][ks][3]);
    }

    auto stage_rel = [&](int Dbase) {
#pragma unroll
        for (int i = 0; i < 4; i++) {
            int id = tid + i * 128;
            int r = id >> 3, c = id & 7;
            int dist = min(max(Dbase + r, -MAXPOS), MAXPOS) + MAXPOS;
            uint32_t d = sw128(r * 128 + c * 16);
            cp16(sb + A_R + d, g_relf + (size_t)dist * DH + c * 8);
        }
    };

    auto s2_group = [&](int baseSlot) {
        float s2[8][4];
#pragma unroll
        for (int nt = 0; nt < 8; nt++)
#pragma unroll
            for (int e = 0; e < 4; e++) s2[nt][e] = 0.f;
#pragma unroll
        for (int ks = 0; ks < 4; ks++) {
            uint32_t rb[4][4];
#pragma unroll
            for (int g = 0; g < 4; g++) {
                uint32_t off = sw128((g * 16 + (lane & 15)) * 128
                                     + ks * 32 + (lane >> 4) * 16);
                ldm_x4(sb + A_R + off, rb[g][0], rb[g][1], rb[g][2], rb[g][3]);
            }
#pragma unroll
            for (int nt = 0; nt < 8; nt++) {
                const int p = nt >> 1, s_ = nt & 1;
                mma16816h(s2[nt], qa[0][ks], rb[p][s_], rb[p][s_ + 2]);
                mma16816h(s2[nt], qa[1][ks], rb[p][s_], rb[p][s_ + 2]);
            }
        }
        const int rl0 = wbase + (lane >> 2);
#pragma unroll
        for (int nt = 0; nt < 8; nt++) {
            const int col = baseSlot + nt * 8 + 2 * (lane & 3);
            *(uint32_t*)&s2h[rl0 * S2S + col]       = pack_h2(s2[nt][0], s2[nt][1]);
            *(uint32_t*)&s2h[(rl0 + 8) * S2S + col] = pack_h2(s2[nt][2], s2[nt][3]);
        }
    };

    // pre-group: slots 64..127 = dists [i0+1, i0+64]
    stage_rel(i0 + 1);
    asm volatile("cp.async.commit_group;" ::: "memory");
    asm volatile("cp.async.wait_group 0;" ::: "memory");
    __syncthreads();
    s2_group(64);

    float o[8][4];
#pragma unroll
    for (int nt = 0; nt < 8; nt++)
#pragma unroll
        for (int e = 0; e < 4; e++) o[nt][e] = 0.f;
    float m2[2] = {-1e30f, -1e30f}, l2[2] = {0.f, 0.f};
    bool clipgrp[2] = {false, false};

    for (int jt = 0; jt < 16; jt++) {
        const int j0 = jt * 64;
        __syncthreads();

        // group A: K + (maybe) new rel rows
#pragma unroll
        for (int i = 0; i < 4; i++) {
            int id = tid + i * 128;
            int r = id >> 3, c = id & 7;
            uint32_t d = sw128(r * 128 + c * 16);
            cp16(sb + A_K + d, g_kf + hb + (size_t)(j0 + r) * DH + c * 8);
        }
        const int Dbase = i0 - j0 - 63;
        const bool fullclip = (Dbase + 63 <= -MAXPOS);
        const bool skip = fullclip && clipgrp[jt & 1];
        if (!skip) stage_rel(Dbase);
        asm volatile("cp.async.commit_group;" ::: "memory");
        // group B: V
#pragma unroll
        for (int i = 0; i < 4; i++) {
            int id = tid + i * 128;
            int r = id >> 3, c = id & 7;
            uint32_t d = sw128(r * 128 + c * 16);
            cp16(sb + A_V + d, g_vf + hb + (size_t)(j0 + r) * DH + c * 8);
        }
        asm volatile("cp.async.commit_group;" ::: "memory");

        asm volatile("cp.async.wait_group 1;" ::: "memory");
        __syncthreads();

        // ---- new S2 columns (64) ----
        if (!skip) s2_group((jt & 1) ? 64 : 0);
        clipgrp[jt & 1] = fullclip;
        __syncwarp();

        // ---- S1 = Q @ K^T (64x64) ----
        float s[8][4];
#pragma unroll
        for (int nt = 0; nt < 8; nt++)
#pragma unroll
            for (int e = 0; e < 4; e++) s[nt][e] = 0.f;
#pragma unroll
        for (int ks = 0; ks < 4; ks++) {
            uint32_t kb[4][4];
#pragma unroll
            for (int g = 0; g < 4; g++) {
                uint32_t off = sw128((g * 16 + (lane & 15)) * 128
                                     + ks * 32 + (lane >> 4) * 16);
                ldm_x4(sb + A_K + off, kb[g][0], kb[g][1], kb[g][2], kb[g][3]);
            }
#pragma unroll
            for (int nt = 0; nt < 8; nt++) {
                const int p = nt >> 1, s_ = nt & 1;
                mma16816h(s[nt], qa[0][ks], kb[p][s_], kb[p][s_ + 2]);
                mma16816h(s[nt], qa[1][ks], kb[p][s_], kb[p][s_ + 2]);
            }
        }

        // ---- gather rel bias from ring, online softmax (base-2 domain) ----
        const int rl0 = wbase + (lane >> 2);
#pragma unroll
        for (int nt = 0; nt < 8; nt++)
#pragma unroll
            for (int e = 0; e < 4; e++) {
                const int rr = rl0 + 8 * (e >> 1);
                const int jj = nt * 8 + 2 * (lane & 3) + (e & 1);
                const int slot = (rr - jj + 63 - j0) & 127;
                s[nt][e] += __half2float(s2h[rr * S2S + slot]);
            }

        float mx[2] = {-1e30f, -1e30f};
#pragma unroll
        for (int nt = 0; nt < 8; nt++)
#pragma unroll
            for (int e = 0; e < 4; e++)
                mx[e >> 1] = fmaxf(mx[e >> 1], s[nt][e]);
#pragma unroll
        for (int h2 = 0; h2 < 2; h2++) {
            mx[h2] = fmaxf(mx[h2], __shfl_xor_sync(0xffffffffu, mx[h2], 1));
            mx[h2] = fmaxf(mx[h2], __shfl_xor_sync(0xffffffffu, mx[h2], 2));
        }
        float al2[2];
#pragma unroll
        for (int h2 = 0; h2 < 2; h2++) {
            float mnew = fmaxf(m2[h2], mx[h2]);
            al2[h2] = exp2f(m2[h2] - mnew);
            m2[h2] = mnew;
        }
        float sum[2] = {0.f, 0.f};
#pragma unroll
        for (int nt = 0; nt < 8; nt++)
#pragma unroll
            for (int e = 0; e < 4; e++) {
                float p = exp2f(s[nt][e] - m2[e >> 1]);
                s[nt][e] = p;
                sum[e >> 1] += p;
            }
#pragma unroll
        for (int h2 = 0; h2 < 2; h2++) {
            sum[h2] += __shfl_xor_sync(0xffffffffu, sum[h2], 1);
            sum[h2] += __shfl_xor_sync(0xffffffffu, sum[h2], 2);
            l2[h2] = l2[h2] * al2[h2] + sum[h2];
        }
#pragma unroll
        for (int nt = 0; nt < 8; nt++) {
            o[nt][0] *= al2[0]; o[nt][1] *= al2[0];
            o[nt][2] *= al2[1]; o[nt][3] *= al2[1];
        }

        // ---- P c-frag -> a-frag (single fp16) ----
        uint32_t pa[4][4];
#pragma unroll
        for (int ks = 0; ks < 4; ks++) {
            pa[ks][0] = pack_h2(s[2*ks][0],   s[2*ks][1]);
            pa[ks][1] = pack_h2(s[2*ks][2],   s[2*ks][3]);
            pa[ks][2] = pack_h2(s[2*ks+1][0], s[2*ks+1][1]);
            pa[ks][3] = pack_h2(s[2*ks+1][2], s[2*ks+1][3]);
        }

        asm volatile("cp.async.wait_group 0;" ::: "memory");
        __syncthreads();

        // ---- O += P @ V (single pass) ----
#pragma unroll
        for (int ks = 0; ks < 4; ks++) {
            uint32_t vb[4][4];
            const int jr = ks * 16 + (lane & 7) + ((lane >> 3) & 1) * 8;
#pragma unroll
            for (int dp = 0; dp < 4; dp++) {
                uint32_t off = sw128(jr * 128 + dp * 32 + (lane >> 4) * 16);
                ldm_x4t(sb + A_V + off, vb[dp][0], vb[dp][1], vb[dp][2], vb[dp][3]);
            }
#pragma unroll
            for (int nt = 0; nt < 8; nt++) {
                const int dp = nt >> 1, s_ = (nt & 1) * 2;
                mma16816h(o[nt], pa[ks], vb[dp][s_], vb[dp][s_ + 1]);
            }
        }
    }

    // ---- epilogue: normalize -> single fp16 g_of ----
    const float inv0 = 1.f / l2[0], inv1 = 1.f / l2[1];
    const int row0 = i0 + wbase + (lane >> 2);
#pragma unroll
    for (int nt = 0; nt < 8; nt++) {
        const int d = nt * 8 + 2 * (lane & 3);
        size_t base0 = ((size_t)b * N_SEQ + row0) * INNER + h * DH + d;
        *(uint32_t*)&g_of[base0] = pack_h2(o[nt][0] * inv0, o[nt][1] * inv0);
        size_t base1 = ((size_t)b * N_SEQ + row0 + 8) * INNER + h * DH + d;
        *(uint32_t*)&g_of[base1] = pack_h2(o[nt][2] * inv1, o[nt][3] * inv1);
    }
}

// ---------------------------------------------------------------------------
extern "C" void kernel_launch(void* const* d_in, const int* in_sizes, int n_in,
                              void* d_out, int out_size)
{
    (void)in_sizes; (void)n_in; (void)out_size;
    const float* x   = (const float*)d_in[0];
    const float* Wq  = (const float*)d_in[1];
    const float* Wkv = (const float*)d_in[2];
    const float* Wo  = (const float*)d_in[3];
    const float* bo  = (const float*)d_in[4];
    const float* rel = (const float*)d_in[5];
    float* out = (float*)d_out;

    const int GEMM_SMEM = NSTAGE * STAGE_B;      // 92160
    cudaFuncSetAttribute(gemm_mma, cudaFuncAttributeMaxDynamicSharedMemorySize, GEMM_SMEM);
    cudaFuncSetAttribute(attn_mma, cudaFuncAttributeMaxDynamicSharedMemorySize, ATT_SMEM);

    // all fp32 -> fp16 conversions in one launch
    convert_all<<<4096 + NCONV_BLK, 256>>>(x, rel, Wq, Wkv, Wo);

    // fused q/k/v projection: x @ [Wq|Wkv]
    gemm_mma<<<dim3(3 * INNER / 128, (B_DIM * N_SEQ) / 128), 256, GEMM_SMEM>>>(0, nullptr, nullptr);

    // fused attention
    attn_mma<<<dim3(16, HEADS, B_DIM), 128, ATT_SMEM>>>();

    // out = o @ Wo + bo
    gemm_mma<<<dim3(DIMX / 128, (B_DIM * N_SEQ) / 128), 256, GEMM_SMEM>>>(2, bo, out);
}

// round 9
// speedup vs baseline: 5.0884x; 1.1174x over previous
#include <cuda_runtime.h>
#include <cuda_fp16.h>
#include <cstdint>

#define B_DIM  2
#define N_SEQ  1024
#define DIMX   1024
#define HEADS  16
#define DH     64
#define INNER  1024
#define MAXPOS 512

// ------------------------- device scratch (no allocs) -----------------------
__device__ __align__(16) __half g_xf[(size_t)B_DIM*N_SEQ*DIMX];
__device__ __align__(16) __half g_wph[(size_t)3*DIMX*INNER];
__device__ __align__(16) __half g_wpl[(size_t)3*DIMX*INNER];
__device__ __align__(16) __half g_woh[(size_t)INNER*DIMX];
__device__ __align__(16) __half g_wol[(size_t)INNER*DIMX];
__device__ __align__(16) __half g_of[(size_t)B_DIM*N_SEQ*INNER];
// attention: q hi/lo (scaled by 0.125*log2e), k/v/rel single fp16
__device__ __align__(16) __half g_qh[(size_t)B_DIM*HEADS*N_SEQ*DH];
__device__ __align__(16) __half g_ql[(size_t)B_DIM*HEADS*N_SEQ*DH];
__device__ __align__(16) __half g_kf[(size_t)B_DIM*HEADS*N_SEQ*DH];
__device__ __align__(16) __half g_vf[(size_t)B_DIM*HEADS*N_SEQ*DH];
__device__ __align__(16) __half g_relf[(size_t)(2*MAXPOS+1)*DH];

// ------------------------------- helpers ------------------------------------
__device__ __forceinline__ uint32_t smem_u32(const void* p) {
    uint32_t a;
    asm("{ .reg .u64 t; cvta.to.shared.u64 t, %1; cvt.u32.u64 %0, t; }"
        : "=r"(a) : "l"(p));
    return a;
}
__device__ __forceinline__ void cp16(uint32_t saddr, const void* gaddr) {
    asm volatile("cp.async.cg.shared.global [%0], [%1], 16;"
                 :: "r"(saddr), "l"(gaddr) : "memory");
}
__device__ __forceinline__ void ldm_x4(uint32_t a, uint32_t& r0, uint32_t& r1,
                                       uint32_t& r2, uint32_t& r3) {
    asm volatile("ldmatrix.sync.aligned.m8n8.x4.shared.b16 {%0,%1,%2,%3}, [%4];"
                 : "=r"(r0), "=r"(r1), "=r"(r2), "=r"(r3) : "r"(a));
}
__device__ __forceinline__ void ldm_x4t(uint32_t a, uint32_t& r0, uint32_t& r1,
                                        uint32_t& r2, uint32_t& r3) {
    asm volatile("ldmatrix.sync.aligned.m8n8.x4.trans.shared.b16 {%0,%1,%2,%3}, [%4];"
                 : "=r"(r0), "=r"(r1), "=r"(r2), "=r"(r3) : "r"(a));
}
__device__ __forceinline__ void mma16816h(float* c, const uint32_t* a,
                                          uint32_t b0, uint32_t b1) {
    asm volatile(
        "mma.sync.aligned.m16n8k16.row.col.f32.f16.f16.f32 "
        "{%0,%1,%2,%3}, {%4,%5,%6,%7}, {%8,%9}, {%0,%1,%2,%3};"
        : "+f"(c[0]), "+f"(c[1]), "+f"(c[2]), "+f"(c[3])
        : "r"(a[0]), "r"(a[1]), "r"(a[2]), "r"(a[3]), "r"(b0), "r"(b1));
}
__device__ __forceinline__ uint32_t sw128(uint32_t off) {
    return off ^ ((off >> 3) & 0x70);
}
__device__ __forceinline__ uint32_t pack_h2(float a, float b) {
    __half2 h = __floats2half2_rn(a, b);
    return *(uint32_t*)&h;
}
__device__ __forceinline__ void split2h(float a, float b, uint32_t& hi, uint32_t& lo) {
    __half2 h = __floats2half2_rn(a, b);
    float ra = a - __half2float(__low2half(h));
    float rb = b - __half2float(__high2half(h));
    __half2 l = __floats2half2_rn(ra, rb);
    hi = *(uint32_t*)&h; lo = *(uint32_t*)&l;
}

// ------------------- fused conversion kernel (one launch) -------------------
#define NX4 (B_DIM * N_SEQ * DIMX / 4)          // 524288
#define NR4 ((2 * MAXPOS + 1) * DH / 4)         // 16400
#define NCONV_BLK ((NX4 + NR4 + 255) / 256)     // 2113

__global__ __launch_bounds__(256) void convert_all(const float* __restrict__ x,
                                                   const float* __restrict__ rel,
                                                   const float* __restrict__ Wq,
                                                   const float* __restrict__ Wkv,
                                                   const float* __restrict__ Wo)
{
    const int bid = blockIdx.x;
    if (bid >= 4096) {
        int i = (bid - 4096) * 256 + threadIdx.x;
        if (i >= NX4 + NR4) return;
        if (i < NX4) {
            float4 v = ((const float4*)x)[i];
            ((uint32_t*)g_xf)[2*i]   = pack_h2(v.x, v.y);
            ((uint32_t*)g_xf)[2*i+1] = pack_h2(v.z, v.w);
        } else {
            int j = i - NX4;
            float4 v = ((const float4*)rel)[j];
            ((uint32_t*)g_relf)[2*j]   = pack_h2(v.x, v.y);
            ((uint32_t*)g_relf)[2*j+1] = pack_h2(v.z, v.w);
        }
        return;
    }
    __shared__ float t[32][33];
    const float* W; __half *th, *tl;
    int N, kt, ntile, rowoff;
    if (bid < 1024)      { W = Wq;  N = 1024; kt = bid >> 5; ntile = bid & 31;
                           th = g_wph; tl = g_wpl; rowoff = 0; }
    else if (bid < 3072) { int l = bid - 1024; W = Wkv; N = 2048;
                           kt = l >> 6; ntile = l & 63;
                           th = g_wph; tl = g_wpl; rowoff = 1024; }
    else                 { int l = bid - 3072; W = Wo; N = 1024;
                           kt = l >> 5; ntile = l & 31;
                           th = g_woh; tl = g_wol; rowoff = 0; }
    const int n0 = ntile * 32, k0 = kt * 32;
    const int tx = threadIdx.x & 31, ty = threadIdx.x >> 5;
#pragma unroll
    for (int r = 0; r < 4; r++)
        t[ty + 8*r][tx] = W[(size_t)(k0 + ty + 8*r) * N + n0 + tx];
    __syncthreads();
#pragma unroll
    for (int r = 0; r < 4; r++) {
        float v = t[tx][ty + 8*r];
        __half h = __float2half_rn(v);
        __half l = __float2half_rn(v - __half2float(h));
        size_t o = (size_t)(rowoff + n0 + ty + 8*r) * 1024 + k0 + tx;
        th[o] = h; tl[o] = l;
    }
}

// ------------------------- fp16 2-pass GEMM (mma.sync) ----------------------
// BK=64, SW128 swizzle (128B rows), 2-stage cp.async pipeline, 2 CTAs/SM.
#define BK 64
#define TILE_B 16384              // 128 rows * 128 B
#define STAGE_B (3 * TILE_B)      // A, Bh, Bl = 49152
#define NSTAGE 2

__global__ __launch_bounds__(256, 2) void gemm_mma(int mode,
                                                   const float* __restrict__ bias,
                                                   float* __restrict__ outp)
{
    extern __shared__ __align__(128) char smem[];
    const uint32_t sb = smem_u32(smem);
    const int tid = threadIdx.x;
    const int wid = tid >> 5, lane = tid & 31;
    const int warp_m = wid & 1, warp_n = wid >> 1;
    const int m0 = blockIdx.y * 128, n0 = blockIdx.x * 128;

    const __half *A, *Bh, *Bl;
    if (mode == 0) { A = g_xf; Bh = g_wph; Bl = g_wpl; }
    else           { A = g_of; Bh = g_woh; Bl = g_wol; }

    float acc[4][4][4];
#pragma unroll
    for (int i = 0; i < 4; i++)
#pragma unroll
        for (int j = 0; j < 4; j++)
#pragma unroll
            for (int t = 0; t < 4; t++) acc[i][j][t] = 0.f;

    const int nkt = DIMX / BK;     // 16

    auto issue_stage = [&](int kt) {
        const int k0 = kt * BK;
        const uint32_t st = sb + (kt & 1) * STAGE_B;
#pragma unroll
        for (int i = 0; i < 12; i++) {
            int id = tid + i * 256;
            int tile = id >> 10, rem = id & 1023;
            int r = rem >> 3, cc = rem & 7;
            uint32_t sa = st + tile * TILE_B + sw128(r * 128 + cc * 16);
            const __half* src;
            size_t goff;
            if (tile == 0)      { src = A;  goff = (size_t)(m0 + r) * DIMX; }
            else if (tile == 1) { src = Bh; goff = (size_t)(n0 + r) * DIMX; }
            else                { src = Bl; goff = (size_t)(n0 + r) * DIMX; }
            cp16(sa, src + goff + k0 + cc * 8);
        }
        asm volatile("cp.async.commit_group;" ::: "memory");
    };

    issue_stage(0);

    const int lr = lane & 15;
    const int lcb = (lane >> 4) * 16;    // byte offset within 32B k-group

    for (int kt = 0; kt < nkt; kt++) {
        if (kt + 1 < nkt) {
            issue_stage(kt + 1);
            asm volatile("cp.async.wait_group 1;" ::: "memory");
        } else {
            asm volatile("cp.async.wait_group 0;" ::: "memory");
        }
        __syncthreads();

        const uint32_t st = sb + (kt & 1) * STAGE_B;

#pragma unroll
        for (int ks = 0; ks < 4; ks++) {
            const uint32_t koffb = ks * 32 + lcb;
            uint32_t ah[4][4], bh[2][4], bl[2][4];
#pragma unroll
            for (int mt = 0; mt < 4; mt++) {
                uint32_t off = sw128((warp_m * 64 + mt * 16 + lr) * 128 + koffb);
                ldm_x4(st + 0 * TILE_B + off,
                       ah[mt][0], ah[mt][1], ah[mt][2], ah[mt][3]);
            }
#pragma unroll
            for (int p = 0; p < 2; p++) {
                uint32_t off = sw128((warp_n * 32 + p * 16 + lr) * 128 + koffb);
                ldm_x4(st + 1 * TILE_B + off,
                       bh[p][0], bh[p][1], bh[p][2], bh[p][3]);
                ldm_x4(st + 2 * TILE_B + off,
                       bl[p][0], bl[p][1], bl[p][2], bl[p][3]);
            }
#pragma unroll
            for (int mt = 0; mt < 4; mt++)
#pragma unroll
                for (int nt = 0; nt < 4; nt++) {
                    const int p = nt >> 1, s = nt & 1;
                    mma16816h(acc[mt][nt], ah[mt], bh[p][s], bh[p][s + 2]);
                    mma16816h(acc[mt][nt], ah[mt], bl[p][s], bl[p][s + 2]);
                }
        }
        __syncthreads();
    }

    // q scale folds softmax scale AND log2(e) for exp2-softmax
    const float qscale = 0.125f * 1.4426950408889634f;
#pragma unroll
    for (int mt = 0; mt < 4; mt++) {
#pragma unroll
        for (int half = 0; half < 2; half++) {
            const int m = m0 + warp_m * 64 + mt * 16 + (lane >> 2) + half * 8;
#pragma unroll
            for (int nt = 0; nt < 4; nt++) {
                const int c = n0 + warp_n * 32 + nt * 8 + 2 * (lane & 3);
                float v0 = acc[mt][nt][half * 2 + 0];
                float v1 = acc[mt][nt][half * 2 + 1];
                if (mode != 0) {
                    float2 o = {v0 + bias[c], v1 + bias[c + 1]};
                    *(float2*)&outp[(size_t)m * DIMX + c] = o;
                } else {
                    const int bb = m >> 10, ii = m & 1023;
                    if (c < INNER) {               // q: fp16 hi/lo, scaled
                        const int hh = c >> 6, dd = c & 63;
                        size_t o = (((size_t)bb * HEADS + hh) * N_SEQ + ii) * DH + dd;
                        uint32_t hi, lo;
                        split2h(v0 * qscale, v1 * qscale, hi, lo);
                        *(uint32_t*)&g_qh[o] = hi;
                        *(uint32_t*)&g_ql[o] = lo;
                    } else {                       // k/v: single fp16
                        int col0 = c - INNER;
                        __half* dst = (col0 < INNER) ? g_kf : g_vf;
                        if (col0 >= INNER) col0 -= INNER;
                        const int hh = col0 >> 6, dd = col0 & 63;
                        size_t o = (((size_t)bb * HEADS + hh) * N_SEQ + ii) * DH + dd;
                        *(uint32_t*)&dst[o] = pack_h2(v0, v1);
                    }
                }
            }
        }
    }
}

// ---------------------------------------------------------------------------
// Tensor-core flash attention: Q hi/lo, K/V/rel single fp16, P single,
// fp16 S2 ring, exp2 softmax, occupancy 3.  (unchanged from round 8)
// ---------------------------------------------------------------------------
#define A_QH 0
#define A_QL 8192
#define A_K  16384
#define A_V  24576
#define A_R  32768
#define A_S2 40960
#define S2S  132
#define ATT_SMEM (A_S2 + 64 * S2S * 2)   // 57856

__global__ __launch_bounds__(128, 3) void attn_mma(void)
{
    extern __shared__ __align__(128) char smem[];
    const uint32_t sb = smem_u32(smem);
    __half* s2h = (__half*)(smem + A_S2);

    const int tid  = threadIdx.x;
    const int lane = tid & 31, warp = tid >> 5;
    const int wbase = warp * 16;
    const int i0 = blockIdx.x * 64;
    const int h  = blockIdx.y;
    const int b  = blockIdx.z;
    const size_t hb = ((size_t)b * HEADS + h) * N_SEQ * DH;

    // ---- load Q hi/lo planes ----
#pragma unroll
    for (int i = 0; i < 4; i++) {
        int id = tid + i * 128;
        int r = id >> 3, c = id & 7;
        uint32_t d = sw128(r * 128 + c * 16);
        cp16(sb + A_QH + d, g_qh + hb + (size_t)(i0 + r) * DH + c * 8);
        cp16(sb + A_QL + d, g_ql + hb + (size_t)(i0 + r) * DH + c * 8);
    }
    asm volatile("cp.async.commit_group;" ::: "memory");
    asm volatile("cp.async.wait_group 0;" ::: "memory");
    __syncthreads();

    uint32_t qa[2][4][4];
#pragma unroll
    for (int ks = 0; ks < 4; ks++) {
        uint32_t off = sw128((wbase + (lane & 15)) * 128 + ks * 32 + (lane >> 4) * 16);
        ldm_x4(sb + A_QH + off, qa[0][ks][0], qa[0][ks][1], qa[0][ks][2], qa[0][ks][3]);
        ldm_x4(sb + A_QL + off, qa[1][ks][0], qa[1][ks][1], qa[1][ks][2], qa[1][ks][3]);
    }

    auto stage_rel = [&](int Dbase) {
#pragma unroll
        for (int i = 0; i < 4; i++) {
            int id = tid + i * 128;
            int r = id >> 3, c = id & 7;
            int dist = min(max(Dbase + r, -MAXPOS), MAXPOS) + MAXPOS;
            uint32_t d = sw128(r * 128 + c * 16);
            cp16(sb + A_R + d, g_relf + (size_t)dist * DH + c * 8);
        }
    };

    auto s2_group = [&](int baseSlot) {
        float s2[8][4];
#pragma unroll
        for (int nt = 0; nt < 8; nt++)
#pragma unroll
            for (int e = 0; e < 4; e++) s2[nt][e] = 0.f;
#pragma unroll
        for (int ks = 0; ks < 4; ks++) {
            uint32_t rb[4][4];
#pragma unroll
            for (int g = 0; g < 4; g++) {
                uint32_t off = sw128((g * 16 + (lane & 15)) * 128
                                     + ks * 32 + (lane >> 4) * 16);
                ldm_x4(sb + A_R + off, rb[g][0], rb[g][1], rb[g][2], rb[g][3]);
            }
#pragma unroll
            for (int nt = 0; nt < 8; nt++) {
                const int p = nt >> 1, s_ = nt & 1;
                mma16816h(s2[nt], qa[0][ks], rb[p][s_], rb[p][s_ + 2]);
                mma16816h(s2[nt], qa[1][ks], rb[p][s_], rb[p][s_ + 2]);
            }
        }
        const int rl0 = wbase + (lane >> 2);
#pragma unroll
        for (int nt = 0; nt < 8; nt++) {
            const int col = baseSlot + nt * 8 + 2 * (lane & 3);
            *(uint32_t*)&s2h[rl0 * S2S + col]       = pack_h2(s2[nt][0], s2[nt][1]);
            *(uint32_t*)&s2h[(rl0 + 8) * S2S + col] = pack_h2(s2[nt][2], s2[nt][3]);
        }
    };

    // pre-group: slots 64..127 = dists [i0+1, i0+64]
    stage_rel(i0 + 1);
    asm volatile("cp.async.commit_group;" ::: "memory");
    asm volatile("cp.async.wait_group 0;" ::: "memory");
    __syncthreads();
    s2_group(64);

    float o[8][4];
#pragma unroll
    for (int nt = 0; nt < 8; nt++)
#pragma unroll
        for (int e = 0; e < 4; e++) o[nt][e] = 0.f;
    float m2[2] = {-1e30f, -1e30f}, l2[2] = {0.f, 0.f};
    bool clipgrp[2] = {false, false};

    for (int jt = 0; jt < 16; jt++) {
        const int j0 = jt * 64;
        __syncthreads();

        // group A: K + (maybe) new rel rows
#pragma unroll
        for (int i = 0; i < 4; i++) {
            int id = tid + i * 128;
            int r = id >> 3, c = id & 7;
            uint32_t d = sw128(r * 128 + c * 16);
            cp16(sb + A_K + d, g_kf + hb + (size_t)(j0 + r) * DH + c * 8);
        }
        const int Dbase = i0 - j0 - 63;
        const bool fullclip = (Dbase + 63 <= -MAXPOS);
        const bool skip = fullclip && clipgrp[jt & 1];
        if (!skip) stage_rel(Dbase);
        asm volatile("cp.async.commit_group;" ::: "memory");
        // group B: V
#pragma unroll
        for (int i = 0; i < 4; i++) {
            int id = tid + i * 128;
            int r = id >> 3, c = id & 7;
            uint32_t d = sw128(r * 128 + c * 16);
            cp16(sb + A_V + d, g_vf + hb + (size_t)(j0 + r) * DH + c * 8);
        }
        asm volatile("cp.async.commit_group;" ::: "memory");

        asm volatile("cp.async.wait_group 1;" ::: "memory");
        __syncthreads();

        // ---- new S2 columns (64) ----
        if (!skip) s2_group((jt & 1) ? 64 : 0);
        clipgrp[jt & 1] = fullclip;
        __syncwarp();

        // ---- S1 = Q @ K^T (64x64) ----
        float s[8][4];
#pragma unroll
        for (int nt = 0; nt < 8; nt++)
#pragma unroll
            for (int e = 0; e < 4; e++) s[nt][e] = 0.f;
#pragma unroll
        for (int ks = 0; ks < 4; ks++) {
            uint32_t kb[4][4];
#pragma unroll
            for (int g = 0; g < 4; g++) {
                uint32_t off = sw128((g * 16 + (lane & 15)) * 128
                                     + ks * 32 + (lane >> 4) * 16);
                ldm_x4(sb + A_K + off, kb[g][0], kb[g][1], kb[g][2], kb[g][3]);
            }
#pragma unroll
            for (int nt = 0; nt < 8; nt++) {
                const int p = nt >> 1, s_ = nt & 1;
                mma16816h(s[nt], qa[0][ks], kb[p][s_], kb[p][s_ + 2]);
                mma16816h(s[nt], qa[1][ks], kb[p][s_], kb[p][s_ + 2]);
            }
        }

        // ---- gather rel bias from ring, online softmax (base-2 domain) ----
        const int rl0 = wbase + (lane >> 2);
#pragma unroll
        for (int nt = 0; nt < 8; nt++)
#pragma unroll
            for (int e = 0; e < 4; e++) {
                const int rr = rl0 + 8 * (e >> 1);
                const int jj = nt * 8 + 2 * (lane & 3) + (e & 1);
                const int slot = (rr - jj + 63 - j0) & 127;
                s[nt][e] += __half2float(s2h[rr * S2S + slot]);
            }

        float mx[2] = {-1e30f, -1e30f};
#pragma unroll
        for (int nt = 0; nt < 8; nt++)
#pragma unroll
            for (int e = 0; e < 4; e++)
                mx[e >> 1] = fmaxf(mx[e >> 1], s[nt][e]);
#pragma unroll
        for (int h2 = 0; h2 < 2; h2++) {
            mx[h2] = fmaxf(mx[h2], __shfl_xor_sync(0xffffffffu, mx[h2], 1));
            mx[h2] = fmaxf(mx[h2], __shfl_xor_sync(0xffffffffu, mx[h2], 2));
        }
        float al2[2];
#pragma unroll
        for (int h2 = 0; h2 < 2; h2++) {
            float mnew = fmaxf(m2[h2], mx[h2]);
            al2[h2] = exp2f(m2[h2] - mnew);
            m2[h2] = mnew;
        }
        float sum[2] = {0.f, 0.f};
#pragma unroll
        for (int nt = 0; nt < 8; nt++)
#pragma unroll
            for (int e = 0; e < 4; e++) {
                float p = exp2f(s[nt][e] - m2[e >> 1]);
                s[nt][e] = p;
                sum[e >> 1] += p;
            }
#pragma unroll
        for (int h2 = 0; h2 < 2; h2++) {
            sum[h2] += __shfl_xor_sync(0xffffffffu, sum[h2], 1);
            sum[h2] += __shfl_xor_sync(0xffffffffu, sum[h2], 2);
            l2[h2] = l2[h2] * al2[h2] + sum[h2];
        }
#pragma unroll
        for (int nt = 0; nt < 8; nt++) {
            o[nt][0] *= al2[0]; o[nt][1] *= al2[0];
            o[nt][2] *= al2[1]; o[nt][3] *= al2[1];
        }

        // ---- P c-frag -> a-frag (single fp16) ----
        uint32_t pa[4][4];
#pragma unroll
        for (int ks = 0; ks < 4; ks++) {
            pa[ks][0] = pack_h2(s[2*ks][0],   s[2*ks][1]);
            pa[ks][1] = pack_h2(s[2*ks][2],   s[2*ks][3]);
            pa[ks][2] = pack_h2(s[2*ks+1][0], s[2*ks+1][1]);
            pa[ks][3] = pack_h2(s[2*ks+1][2], s[2*ks+1][3]);
        }

        asm volatile("cp.async.wait_group 0;" ::: "memory");
        __syncthreads();

        // ---- O += P @ V (single pass) ----
#pragma unroll
        for (int ks = 0; ks < 4; ks++) {
            uint32_t vb[4][4];
            const int jr = ks * 16 + (lane & 7) + ((lane >> 3) & 1) * 8;
#pragma unroll
            for (int dp = 0; dp < 4; dp++) {
                uint32_t off = sw128(jr * 128 + dp * 32 + (lane >> 4) * 16);
                ldm_x4t(sb + A_V + off, vb[dp][0], vb[dp][1], vb[dp][2], vb[dp][3]);
            }
#pragma unroll
            for (int nt = 0; nt < 8; nt++) {
                const int dp = nt >> 1, s_ = (nt & 1) * 2;
                mma16816h(o[nt], pa[ks], vb[dp][s_], vb[dp][s_ + 1]);
            }
        }
    }

    // ---- epilogue: normalize -> single fp16 g_of ----
    const float inv0 = 1.f / l2[0], inv1 = 1.f / l2[1];
    const int row0 = i0 + wbase + (lane >> 2);
#pragma unroll
    for (int nt = 0; nt < 8; nt++) {
        const int d = nt * 8 + 2 * (lane & 3);
        size_t base0 = ((size_t)b * N_SEQ + row0) * INNER + h * DH + d;
        *(uint32_t*)&g_of[base0] = pack_h2(o[nt][0] * inv0, o[nt][1] * inv0);
        size_t base1 = ((size_t)b * N_SEQ + row0 + 8) * INNER + h * DH + d;
        *(uint32_t*)&g_of[base1] = pack_h2(o[nt][2] * inv1, o[nt][3] * inv1);
    }
}

// ---------------------------------------------------------------------------
extern "C" void kernel_launch(void* const* d_in, const int* in_sizes, int n_in,
                              void* d_out, int out_size)
{
    (void)in_sizes; (void)n_in; (void)out_size;
    const float* x   = (const float*)d_in[0];
    const float* Wq  = (const float*)d_in[1];
    const float* Wkv = (const float*)d_in[2];
    const float* Wo  = (const float*)d_in[3];
    const float* bo  = (const float*)d_in[4];
    const float* rel = (const float*)d_in[5];
    float* out = (float*)d_out;

    const int GEMM_SMEM = NSTAGE * STAGE_B;      // 98304
    cudaFuncSetAttribute(gemm_mma, cudaFuncAttributeMaxDynamicSharedMemorySize, GEMM_SMEM);
    cudaFuncSetAttribute(attn_mma, cudaFuncAttributeMaxDynamicSharedMemorySize, ATT_SMEM);

    // all fp32 -> fp16 conversions in one launch
    convert_all<<<4096 + NCONV_BLK, 256>>>(x, rel, Wq, Wkv, Wo);

    // fused q/k/v projection: x @ [Wq|Wkv]
    gemm_mma<<<dim3(3 * INNER / 128, (B_DIM * N_SEQ) / 128), 256, GEMM_SMEM>>>(0, nullptr, nullptr);

    // fused attention
    attn_mma<<<dim3(16, HEADS, B_DIM), 128, ATT_SMEM>>>();

    // out = o @ Wo + bo
    gemm_mma<<<dim3(DIMX / 128, (B_DIM * N_SEQ) / 128), 256, GEMM_SMEM>>>(2, bo, out);
}

// round 10
// speedup vs baseline: 5.3128x; 1.0441x over previous
#include <cuda_runtime.h>
#include <cuda_fp16.h>
#include <cstdint>

#define B_DIM  2
#define N_SEQ  1024
#define DIMX   1024
#define HEADS  16
#define DH     64
#define INNER  1024
#define MAXPOS 512

// ------------------------- device scratch (no allocs) -----------------------
__device__ __align__(16) __half g_xf[(size_t)B_DIM*N_SEQ*DIMX];
__device__ __align__(16) __half g_wph[(size_t)3*DIMX*INNER];
__device__ __align__(16) __half g_wpl[(size_t)3*DIMX*INNER];
__device__ __align__(16) __half g_woh[(size_t)INNER*DIMX];
__device__ __align__(16) __half g_wol[(size_t)INNER*DIMX];
__device__ __align__(16) __half g_of[(size_t)B_DIM*N_SEQ*INNER];
// attention: q hi/lo (scaled by 0.125*log2e), k/v/rel single fp16
__device__ __align__(16) __half g_qh[(size_t)B_DIM*HEADS*N_SEQ*DH];
__device__ __align__(16) __half g_ql[(size_t)B_DIM*HEADS*N_SEQ*DH];
__device__ __align__(16) __half g_kf[(size_t)B_DIM*HEADS*N_SEQ*DH];
__device__ __align__(16) __half g_vf[(size_t)B_DIM*HEADS*N_SEQ*DH];
__device__ __align__(16) __half g_relf[(size_t)(2*MAXPOS+1)*DH];

// ------------------------------- helpers ------------------------------------
__device__ __forceinline__ uint32_t smem_u32(const void* p) {
    uint32_t a;
    asm("{ .reg .u64 t; cvta.to.shared.u64 t, %1; cvt.u32.u64 %0, t; }"
        : "=r"(a) : "l"(p));
    return a;
}
__device__ __forceinline__ void cp16(uint32_t saddr, const void* gaddr) {
    asm volatile("cp.async.cg.shared.global [%0], [%1], 16;"
                 :: "r"(saddr), "l"(gaddr) : "memory");
}
__device__ __forceinline__ void ldm_x4(uint32_t a, uint32_t& r0, uint32_t& r1,
                                       uint32_t& r2, uint32_t& r3) {
    asm volatile("ldmatrix.sync.aligned.m8n8.x4.shared.b16 {%0,%1,%2,%3}, [%4];"
                 : "=r"(r0), "=r"(r1), "=r"(r2), "=r"(r3) : "r"(a));
}
__device__ __forceinline__ void ldm_x4t(uint32_t a, uint32_t& r0, uint32_t& r1,
                                        uint32_t& r2, uint32_t& r3) {
    asm volatile("ldmatrix.sync.aligned.m8n8.x4.trans.shared.b16 {%0,%1,%2,%3}, [%4];"
                 : "=r"(r0), "=r"(r1), "=r"(r2), "=r"(r3) : "r"(a));
}
__device__ __forceinline__ void mma16816h(float* c, const uint32_t* a,
                                          uint32_t b0, uint32_t b1) {
    asm volatile(
        "mma.sync.aligned.m16n8k16.row.col.f32.f16.f16.f32 "
        "{%0,%1,%2,%3}, {%4,%5,%6,%7}, {%8,%9}, {%0,%1,%2,%3};"
        : "+f"(c[0]), "+f"(c[1]), "+f"(c[2]), "+f"(c[3])
        : "r"(a[0]), "r"(a[1]), "r"(a[2]), "r"(a[3]), "r"(b0), "r"(b1));
}
__device__ __forceinline__ uint32_t sw128(uint32_t off) {
    return off ^ ((off >> 3) & 0x70);
}
__device__ __forceinline__ uint32_t pack_h2(float a, float b) {
    __half2 h = __floats2half2_rn(a, b);
    return *(uint32_t*)&h;
}
__device__ __forceinline__ void split2h(float a, float b, uint32_t& hi, uint32_t& lo) {
    __half2 h = __floats2half2_rn(a, b);
    float ra = a - __half2float(__low2half(h));
    float rb = b - __half2float(__high2half(h));
    __half2 l = __floats2half2_rn(ra, rb);
    hi = *(uint32_t*)&h; lo = *(uint32_t*)&l;
}

// ------------------- fused conversion kernel (one launch) -------------------
#define NX4 (B_DIM * N_SEQ * DIMX / 4)          // 524288
#define NR4 ((2 * MAXPOS + 1) * DH / 4)         // 16400
#define NCONV_BLK ((NX4 + NR4 + 255) / 256)     // 2113

__global__ __launch_bounds__(256) void convert_all(const float* __restrict__ x,
                                                   const float* __restrict__ rel,
                                                   const float* __restrict__ Wq,
                                                   const float* __restrict__ Wkv,
                                                   const float* __restrict__ Wo)
{
    const int bid = blockIdx.x;
    if (bid >= 4096) {
        int i = (bid - 4096) * 256 + threadIdx.x;
        if (i >= NX4 + NR4) return;
        if (i < NX4) {
            float4 v = ((const float4*)x)[i];
            ((uint32_t*)g_xf)[2*i]   = pack_h2(v.x, v.y);
            ((uint32_t*)g_xf)[2*i+1] = pack_h2(v.z, v.w);
        } else {
            int j = i - NX4;
            float4 v = ((const float4*)rel)[j];
            ((uint32_t*)g_relf)[2*j]   = pack_h2(v.x, v.y);
            ((uint32_t*)g_relf)[2*j+1] = pack_h2(v.z, v.w);
        }
        return;
    }
    __shared__ float t[32][33];
    const float* W; __half *th, *tl;
    int N, kt, ntile, rowoff;
    if (bid < 1024)      { W = Wq;  N = 1024; kt = bid >> 5; ntile = bid & 31;
                           th = g_wph; tl = g_wpl; rowoff = 0; }
    else if (bid < 3072) { int l = bid - 1024; W = Wkv; N = 2048;
                           kt = l >> 6; ntile = l & 63;
                           th = g_wph; tl = g_wpl; rowoff = 1024; }
    else                 { int l = bid - 3072; W = Wo; N = 1024;
                           kt = l >> 5; ntile = l & 31;
                           th = g_woh; tl = g_wol; rowoff = 0; }
    const int n0 = ntile * 32, k0 = kt * 32;
    const int tx = threadIdx.x & 31, ty = threadIdx.x >> 5;
#pragma unroll
    for (int r = 0; r < 4; r++)
        t[ty + 8*r][tx] = W[(size_t)(k0 + ty + 8*r) * N + n0 + tx];
    __syncthreads();
#pragma unroll
    for (int r = 0; r < 4; r++) {
        float v = t[tx][ty + 8*r];
        __half h = __float2half_rn(v);
        __half l = __float2half_rn(v - __half2float(h));
        size_t o = (size_t)(rowoff + n0 + ty + 8*r) * 1024 + k0 + tx;
        th[o] = h; tl[o] = l;
    }
}

// ------------------------- fp16 2-pass GEMM (mma.sync) ----------------------
// Tile 128x64 (BM=128, BN=64), 128 threads = 4 warps (2x2), warp tile 64x32.
// BK=64, SW128 swizzle, 2-stage cp.async pipeline, 3 CTAs/SM.
#define BK 64
#define A_TILE_B 16384            // 128 rows * 128 B
#define B_TILE_B 8192             // 64 rows * 128 B
#define STAGE_B (A_TILE_B + 2 * B_TILE_B)   // 32768
#define NSTAGE 2

__global__ __launch_bounds__(128, 3) void gemm_mma(int mode,
                                                   const float* __restrict__ bias,
                                                   float* __restrict__ outp)
{
    extern __shared__ __align__(128) char smem[];
    const uint32_t sb = smem_u32(smem);
    const int tid = threadIdx.x;
    const int wid = tid >> 5, lane = tid & 31;
    const int warp_m = wid & 1, warp_n = wid >> 1;   // 2 x 2
    const int m0 = blockIdx.y * 128, n0 = blockIdx.x * 64;

    const __half *A, *Bh, *Bl;
    if (mode == 0) { A = g_xf; Bh = g_wph; Bl = g_wpl; }
    else           { A = g_of; Bh = g_woh; Bl = g_wol; }

    float acc[4][4][4];
#pragma unroll
    for (int i = 0; i < 4; i++)
#pragma unroll
        for (int j = 0; j < 4; j++)
#pragma unroll
            for (int t = 0; t < 4; t++) acc[i][j][t] = 0.f;

    const int nkt = DIMX / BK;     // 16

    auto issue_stage = [&](int kt) {
        const int k0 = kt * BK;
        const uint32_t st = sb + (kt & 1) * STAGE_B;
        // A: 128 rows x 128 B = 1024 chunks, 8 per thread
#pragma unroll
        for (int i = 0; i < 8; i++) {
            int id = tid + i * 128;
            int r = id >> 3, cc = id & 7;
            cp16(st + sw128(r * 128 + cc * 16),
                 A + (size_t)(m0 + r) * DIMX + k0 + cc * 8);
        }
        // Bh/Bl: 64 rows x 128 B = 512 chunks each, 4 per thread
#pragma unroll
        for (int i = 0; i < 4; i++) {
            int id = tid + i * 128;
            int r = id >> 3, cc = id & 7;
            uint32_t sw = sw128(r * 128 + cc * 16);
            size_t g = (size_t)(n0 + r) * DIMX + k0 + cc * 8;
            cp16(st + A_TILE_B + sw, Bh + g);
            cp16(st + A_TILE_B + B_TILE_B + sw, Bl + g);
        }
        asm volatile("cp.async.commit_group;" ::: "memory");
    };

    issue_stage(0);

    const int lr = lane & 15;
    const int lcb = (lane >> 4) * 16;    // byte offset within 32B k-group

    for (int kt = 0; kt < nkt; kt++) {
        if (kt + 1 < nkt) {
            issue_stage(kt + 1);
            asm volatile("cp.async.wait_group 1;" ::: "memory");
        } else {
            asm volatile("cp.async.wait_group 0;" ::: "memory");
        }
        __syncthreads();

        const uint32_t st = sb + (kt & 1) * STAGE_B;

#pragma unroll
        for (int ks = 0; ks < 4; ks++) {
            const uint32_t koffb = ks * 32 + lcb;
            uint32_t ah[4][4], bh[2][4], bl[2][4];
#pragma unroll
            for (int mt = 0; mt < 4; mt++) {
                uint32_t off = sw128((warp_m * 64 + mt * 16 + lr) * 128 + koffb);
                ldm_x4(st + off, ah[mt][0], ah[mt][1], ah[mt][2], ah[mt][3]);
            }
#pragma unroll
            for (int p = 0; p < 2; p++) {
                uint32_t off = sw128((warp_n * 32 + p * 16 + lr) * 128 + koffb);
                ldm_x4(st + A_TILE_B + off,
                       bh[p][0], bh[p][1], bh[p][2], bh[p][3]);
                ldm_x4(st + A_TILE_B + B_TILE_B + off,
                       bl[p][0], bl[p][1], bl[p][2], bl[p][3]);
            }
#pragma unroll
            for (int mt = 0; mt < 4; mt++)
#pragma unroll
                for (int nt = 0; nt < 4; nt++) {
                    const int p = nt >> 1, s = nt & 1;
                    mma16816h(acc[mt][nt], ah[mt], bh[p][s], bh[p][s + 2]);
                    mma16816h(acc[mt][nt], ah[mt], bl[p][s], bl[p][s + 2]);
                }
        }
        __syncthreads();
    }

    // q scale folds softmax scale AND log2(e) for exp2-softmax
    const float qscale = 0.125f * 1.4426950408889634f;
#pragma unroll
    for (int mt = 0; mt < 4; mt++) {
#pragma unroll
        for (int half = 0; half < 2; half++) {
            const int m = m0 + warp_m * 64 + mt * 16 + (lane >> 2) + half * 8;
#pragma unroll
            for (int nt = 0; nt < 4; nt++) {
                const int c = n0 + warp_n * 32 + nt * 8 + 2 * (lane & 3);
                float v0 = acc[mt][nt][half * 2 + 0];
                float v1 = acc[mt][nt][half * 2 + 1];
                if (mode != 0) {
                    float2 o = {v0 + bias[c], v1 + bias[c + 1]};
                    *(float2*)&outp[(size_t)m * DIMX + c] = o;
                } else {
                    const int bb = m >> 10, ii = m & 1023;
                    if (c < INNER) {               // q: fp16 hi/lo, scaled
                        const int hh = c >> 6, dd = c & 63;
                        size_t o = (((size_t)bb * HEADS + hh) * N_SEQ + ii) * DH + dd;
                        uint32_t hi, lo;
                        split2h(v0 * qscale, v1 * qscale, hi, lo);
                        *(uint32_t*)&g_qh[o] = hi;
                        *(uint32_t*)&g_ql[o] = lo;
                    } else {                       // k/v: single fp16
                        int col0 = c - INNER;
                        __half* dst = (col0 < INNER) ? g_kf : g_vf;
                        if (col0 >= INNER) col0 -= INNER;
                        const int hh = col0 >> 6, dd = col0 & 63;
                        size_t o = (((size_t)bb * HEADS + hh) * N_SEQ + ii) * DH + dd;
                        *(uint32_t*)&dst[o] = pack_h2(v0, v1);
                    }
                }
            }
        }
    }
}

// ---------------------------------------------------------------------------
// Tensor-core flash attention: Q hi/lo, K/V/rel single fp16, P single,
// fp16 S2 ring, exp2 softmax, occupancy 3.  (unchanged)
// ---------------------------------------------------------------------------
#define A_QH 0
#define A_QL 8192
#define A_K  16384
#define A_V  24576
#define A_R  32768
#define A_S2 40960
#define S2S  132
#define ATT_SMEM (A_S2 + 64 * S2S * 2)   // 57856

__global__ __launch_bounds__(128, 3) void attn_mma(void)
{
    extern __shared__ __align__(128) char smem[];
    const uint32_t sb = smem_u32(smem);
    __half* s2h = (__half*)(smem + A_S2);

    const int tid  = threadIdx.x;
    const int lane = tid & 31, warp = tid >> 5;
    const int wbase = warp * 16;
    const int i0 = blockIdx.x * 64;
    const int h  = blockIdx.y;
    const int b  = blockIdx.z;
    const size_t hb = ((size_t)b * HEADS + h) * N_SEQ * DH;

    // ---- load Q hi/lo planes ----
#pragma unroll
    for (int i = 0; i < 4; i++) {
        int id = tid + i * 128;
        int r = id >> 3, c = id & 7;
        uint32_t d = sw128(r * 128 + c * 16);
        cp16(sb + A_QH + d, g_qh + hb + (size_t)(i0 + r) * DH + c * 8);
        cp16(sb + A_QL + d, g_ql + hb + (size_t)(i0 + r) * DH + c * 8);
    }
    asm volatile("cp.async.commit_group;" ::: "memory");
    asm volatile("cp.async.wait_group 0;" ::: "memory");
    __syncthreads();

    uint32_t qa[2][4][4];
#pragma unroll
    for (int ks = 0; ks < 4; ks++) {
        uint32_t off = sw128((wbase + (lane & 15)) * 128 + ks * 32 + (lane >> 4) * 16);
        ldm_x4(sb + A_QH + off, qa[0][ks][0], qa[0][ks][1], qa[0][ks][2], qa[0][ks][3]);
        ldm_x4(sb + A_QL + off, qa[1][ks][0], qa[1][ks][1], qa[1][ks][2], qa[1][ks][3]);
    }

    auto stage_rel = [&](int Dbase) {
#pragma unroll
        for (int i = 0; i < 4; i++) {
            int id = tid + i * 128;
            int r = id >> 3, c = id & 7;
            int dist = min(max(Dbase + r, -MAXPOS), MAXPOS) + MAXPOS;
            uint32_t d = sw128(r * 128 + c * 16);
            cp16(sb + A_R + d, g_relf + (size_t)dist * DH + c * 8);
        }
    };

    auto s2_group = [&](int baseSlot) {
        float s2[8][4];
#pragma unroll
        for (int nt = 0; nt < 8; nt++)
#pragma unroll
            for (int e = 0; e < 4; e++) s2[nt][e] = 0.f;
#pragma unroll
        for (int ks = 0; ks < 4; ks++) {
            uint32_t rb[4][4];
#pragma unroll
            for (int g = 0; g < 4; g++) {
                uint32_t off = sw128((g * 16 + (lane & 15)) * 128
                                     + ks * 32 + (lane >> 4) * 16);
                ldm_x4(sb + A_R + off, rb[g][0], rb[g][1], rb[g][2], rb[g][3]);
            }
#pragma unroll
            for (int nt = 0; nt < 8; nt++) {
                const int p = nt >> 1, s_ = nt & 1;
                mma16816h(s2[nt], qa[0][ks], rb[p][s_], rb[p][s_ + 2]);
                mma16816h(s2[nt], qa[1][ks], rb[p][s_], rb[p][s_ + 2]);
            }
        }
        const int rl0 = wbase + (lane >> 2);
#pragma unroll
        for (int nt = 0; nt < 8; nt++) {
            const int col = baseSlot + nt * 8 + 2 * (lane & 3);
            *(uint32_t*)&s2h[rl0 * S2S + col]       = pack_h2(s2[nt][0], s2[nt][1]);
            *(uint32_t*)&s2h[(rl0 + 8) * S2S + col] = pack_h2(s2[nt][2], s2[nt][3]);
        }
    };

    // pre-group: slots 64..127 = dists [i0+1, i0+64]
    stage_rel(i0 + 1);
    asm volatile("cp.async.commit_group;" ::: "memory");
    asm volatile("cp.async.wait_group 0;" ::: "memory");
    __syncthreads();
    s2_group(64);

    float o[8][4];
#pragma unroll
    for (int nt = 0; nt < 8; nt++)
#pragma unroll
        for (int e = 0; e < 4; e++) o[nt][e] = 0.f;
    float m2[2] = {-1e30f, -1e30f}, l2[2] = {0.f, 0.f};
    bool clipgrp[2] = {false, false};

    for (int jt = 0; jt < 16; jt++) {
        const int j0 = jt * 64;
        __syncthreads();

        // group A: K + (maybe) new rel rows
#pragma unroll
        for (int i = 0; i < 4; i++) {
            int id = tid + i * 128;
            int r = id >> 3, c = id & 7;
            uint32_t d = sw128(r * 128 + c * 16);
            cp16(sb + A_K + d, g_kf + hb + (size_t)(j0 + r) * DH + c * 8);
        }
        const int Dbase = i0 - j0 - 63;
        const bool fullclip = (Dbase + 63 <= -MAXPOS);
        const bool skip = fullclip && clipgrp[jt & 1];
        if (!skip) stage_rel(Dbase);
        asm volatile("cp.async.commit_group;" ::: "memory");
        // group B: V
#pragma unroll
        for (int i = 0; i < 4; i++) {
            int id = tid + i * 128;
            int r = id >> 3, c = id & 7;
            uint32_t d = sw128(r * 128 + c * 16);
            cp16(sb + A_V + d, g_vf + hb + (size_t)(j0 + r) * DH + c * 8);
        }
        asm volatile("cp.async.commit_group;" ::: "memory");

        asm volatile("cp.async.wait_group 1;" ::: "memory");
        __syncthreads();

        // ---- new S2 columns (64) ----
        if (!skip) s2_group((jt & 1) ? 64 : 0);
        clipgrp[jt & 1] = fullclip;
        __syncwarp();

        // ---- S1 = Q @ K^T (64x64) ----
        float s[8][4];
#pragma unroll
        for (int nt = 0; nt < 8; nt++)
#pragma unroll
            for (int e = 0; e < 4; e++) s[nt][e] = 0.f;
#pragma unroll
        for (int ks = 0; ks < 4; ks++) {
            uint32_t kb[4][4];
#pragma unroll
            for (int g = 0; g < 4; g++) {
                uint32_t off = sw128((g * 16 + (lane & 15)) * 128
                                     + ks * 32 + (lane >> 4) * 16);
                ldm_x4(sb + A_K + off, kb[g][0], kb[g][1], kb[g][2], kb[g][3]);
            }
#pragma unroll
            for (int nt = 0; nt < 8; nt++) {
                const int p = nt >> 1, s_ = nt & 1;
                mma16816h(s[nt], qa[0][ks], kb[p][s_], kb[p][s_ + 2]);
                mma16816h(s[nt], qa[1][ks], kb[p][s_], kb[p][s_ + 2]);
            }
        }

        // ---- gather rel bias from ring, online softmax (base-2 domain) ----
        const int rl0 = wbase + (lane >> 2);
#pragma unroll
        for (int nt = 0; nt < 8; nt++)
#pragma unroll
            for (int e = 0; e < 4; e++) {
                const int rr = rl0 + 8 * (e >> 1);
                const int jj = nt * 8 + 2 * (lane & 3) + (e & 1);
                const int slot = (rr - jj + 63 - j0) & 127;
                s[nt][e] += __half2float(s2h[rr * S2S + slot]);
            }

        float mx[2] = {-1e30f, -1e30f};
#pragma unroll
        for (int nt = 0; nt < 8; nt++)
#pragma unroll
            for (int e = 0; e < 4; e++)
                mx[e >> 1] = fmaxf(mx[e >> 1], s[nt][e]);
#pragma unroll
        for (int h2 = 0; h2 < 2; h2++) {
            mx[h2] = fmaxf(mx[h2], __shfl_xor_sync(0xffffffffu, mx[h2], 1));
            mx[h2] = fmaxf(mx[h2], __shfl_xor_sync(0xffffffffu, mx[h2], 2));
        }
        float al2[2];
#pragma unroll
        for (int h2 = 0; h2 < 2; h2++) {
            float mnew = fmaxf(m2[h2], mx[h2]);
            al2[h2] = exp2f(m2[h2] - mnew);
            m2[h2] = mnew;
        }
        float sum[2] = {0.f, 0.f};
#pragma unroll
        for (int nt = 0; nt < 8; nt++)
#pragma unroll
            for (int e = 0; e < 4; e++) {
                float p = exp2f(s[nt][e] - m2[e >> 1]);
                s[nt][e] = p;
                sum[e >> 1] += p;
            }
#pragma unroll
        for (int h2 = 0; h2 < 2; h2++) {
            sum[h2] += __shfl_xor_sync(0xffffffffu, sum[h2], 1);
            sum[h2] += __shfl_xor_sync(0xffffffffu, sum[h2], 2);
            l2[h2] = l2[h2] * al2[h2] + sum[h2];
        }
#pragma unroll
        for (int nt = 0; nt < 8; nt++) {
            o[nt][0] *= al2[0]; o[nt][1] *= al2[0];
            o[nt][2] *= al2[1]; o[nt][3] *= al2[1];
        }

        // ---- P c-frag -> a-frag (single fp16) ----
        uint32_t pa[4][4];
#pragma unroll
        for (int ks = 0; ks < 4; ks++) {
            pa[ks][0] = pack_h2(s[2*ks][0],   s[2*ks][1]);
            pa[ks][1] = pack_h2(s[2*ks][2],   s[2*ks][3]);
            pa[ks][2] = pack_h2(s[2*ks+1][0], s[2*ks+1][1]);
            pa[ks][3] = pack_h2(s[2*ks+1][2], s[2*ks+1][3]);
        }

        asm volatile("cp.async.wait_group 0;" ::: "memory");
        __syncthreads();

        // ---- O += P @ V (single pass) ----
#pragma unroll
        for (int ks = 0; ks < 4; ks++) {
            uint32_t vb[4][4];
            const int jr = ks * 16 + (lane & 7) + ((lane >> 3) & 1) * 8;
#pragma unroll
            for (int dp = 0; dp < 4; dp++) {
                uint32_t off = sw128(jr * 128 + dp * 32 + (lane >> 4) * 16);
                ldm_x4t(sb + A_V + off, vb[dp][0], vb[dp][1], vb[dp][2], vb[dp][3]);
            }
#pragma unroll
            for (int nt = 0; nt < 8; nt++) {
                const int dp = nt >> 1, s_ = (nt & 1) * 2;
                mma16816h(o[nt], pa[ks], vb[dp][s_], vb[dp][s_ + 1]);
            }
        }
    }

    // ---- epilogue: normalize -> single fp16 g_of ----
    const float inv0 = 1.f / l2[0], inv1 = 1.f / l2[1];
    const int row0 = i0 + wbase + (lane >> 2);
#pragma unroll
    for (int nt = 0; nt < 8; nt++) {
        const int d = nt * 8 + 2 * (lane & 3);
        size_t base0 = ((size_t)b * N_SEQ + row0) * INNER + h * DH + d;
        *(uint32_t*)&g_of[base0] = pack_h2(o[nt][0] * inv0, o[nt][1] * inv0);
        size_t base1 = ((size_t)b * N_SEQ + row0 + 8) * INNER + h * DH + d;
        *(uint32_t*)&g_of[base1] = pack_h2(o[nt][2] * inv1, o[nt][3] * inv1);
    }
}

// ---------------------------------------------------------------------------
extern "C" void kernel_launch(void* const* d_in, const int* in_sizes, int n_in,
                              void* d_out, int out_size)
{
    (void)in_sizes; (void)n_in; (void)out_size;
    const float* x   = (const float*)d_in[0];
    const float* Wq  = (const float*)d_in[1];
    const float* Wkv = (const float*)d_in[2];
    const float* Wo  = (const float*)d_in[3];
    const float* bo  = (const float*)d_in[4];
    const float* rel = (const float*)d_in[5];
    float* out = (float*)d_out;

    const int GEMM_SMEM = NSTAGE * STAGE_B;      // 65536
    cudaFuncSetAttribute(gemm_mma, cudaFuncAttributeMaxDynamicSharedMemorySize, GEMM_SMEM);
    cudaFuncSetAttribute(attn_mma, cudaFuncAttributeMaxDynamicSharedMemorySize, ATT_SMEM);

    // all fp32 -> fp16 conversions in one launch
    convert_all<<<4096 + NCONV_BLK, 256>>>(x, rel, Wq, Wkv, Wo);

    // fused q/k/v projection: x @ [Wq|Wkv]  (grid 48 x 16 = 768 CTAs)
    gemm_mma<<<dim3(3 * INNER / 64, (B_DIM * N_SEQ) / 128), 128, GEMM_SMEM>>>(0, nullptr, nullptr);

    // fused attention
    attn_mma<<<dim3(16, HEADS, B_DIM), 128, ATT_SMEM>>>();

    // out = o @ Wo + bo  (grid 16 x 16 = 256 CTAs)
    gemm_mma<<<dim3(DIMX / 64, (B_DIM * N_SEQ) / 128), 128, GEMM_SMEM>>>(2, bo, out);
}